// round 2
// baseline (speedup 1.0000x reference)
#include <cuda_runtime.h>
#include <cuda_bf16.h>
#include <cstdint>
#include <cstddef>

#define DIM      512
#define N_NODES  8192
#define N_EDGES  131072   // 2048 paths * 64

// ---------------- scratch (device globals; no runtime allocation) ----------
__device__ float    g_q[N_NODES * DIM];     // projected queries, fp32
__device__ float    g_scores[N_EDGES];      // per-edge scores
__device__ unsigned g_smax[N_NODES];        // ordered-uint-encoded segment max
__device__ float    g_denom[N_NODES];       // softmax denominators

// input-layout config, filled by detect_kernel each launch
struct Cfg { int idx_is_1; int mask_byte; };
__device__ Cfg g_cfg;

// monotone float <-> uint mapping for atomicMax over signed floats
__device__ __forceinline__ unsigned fflip(float f) {
    unsigned u = __float_as_uint(f);
    return u ^ ((u >> 31) ? 0xFFFFFFFFu : 0x80000000u);
}
__device__ __forceinline__ float funflip(unsigned u) {
    u ^= ((u >> 31) ? 0x80000000u : 0xFFFFFFFFu);
    return __uint_as_float(u);
}

// ---------------- K-1: detect which 131072-array is idx vs mask, and the
// mask's storage width. Reads only the first 131072 BYTES of each buffer,
// which is in-bounds for bool(1B), int32 and float32 encodings.
__global__ __launch_bounds__(256) void detect_kernel(
    const unsigned* __restrict__ c0, const unsigned* __restrict__ c1)
{
    __shared__ unsigned sm[2], so[2];
    if (threadIdx.x < 2) { sm[threadIdx.x] = 0u; so[threadIdx.x] = 0u; }
    __syncthreads();
    unsigned m0 = 0, m1 = 0, o0 = 0, o1 = 0;
    for (int i = threadIdx.x; i < 32768; i += 256) {
        unsigned a = c0[i], b = c1[i];
        m0 = max(m0, a); m1 = max(m1, b);
        o0 |= a & 0xFEFEFEFEu; o1 |= b & 0xFEFEFEFEu;
    }
    atomicMax(&sm[0], m0); atomicMax(&sm[1], m1);
    atomicOr (&so[0], o0); atomicOr (&so[1], o1);
    __syncthreads();
    if (threadIdx.x == 0) {
        unsigned M0 = sm[0], M1 = sm[1];
        int idx_is_1;
        if      (M0 <= 1u)                   idx_is_1 = 1;   // c0 is int mask
        else if (M1 <= 1u)                   idx_is_1 = 0;
        else if (M0 < 8192u && M1 >= 8192u)  idx_is_1 = 0;   // c0 looks like node ids
        else if (M1 < 8192u && M0 >= 8192u)  idx_is_1 = 1;
        else                                 idx_is_1 = 1;   // fallback: decl order (mask, idx)
        unsigned Mm = idx_is_1 ? M0 : M1;
        unsigned Om = idx_is_1 ? so[0] : so[1];
        // packed bool bytes: every byte in {0,1} but word values exceed 1
        g_cfg.idx_is_1  = idx_is_1;
        g_cfg.mask_byte = (Mm > 1u && Om == 0u) ? 1 : 0;
    }
}

__device__ __forceinline__ bool edge_live(const void* mask, int e, int mask_byte) {
    return mask_byte ? (((const unsigned char*)mask)[e] != 0)
                     : (((const unsigned*)mask)[e] != 0u);
}

// ---------------- K0: init output + per-node state ------------------------
__global__ __launch_bounds__(256) void init_kernel(float4* __restrict__ out) {
    int i = blockIdx.x * 256 + threadIdx.x;            // 1,048,576 threads
    if (i < N_NODES) { g_smax[i] = fflip(-1e30f); g_denom[i] = 0.f; }
    out[i] = make_float4(0.f, 0.f, 0.f, 0.f);
}

// ---------------- K1: q = prev @ Wq + bq  (fp32, fma.rn.f32x2) -------------
__global__ __launch_bounds__(256, 2) void gemm_q_kernel(
    const float* __restrict__ A,      // [8192, 512] prev
    const float* __restrict__ B,      // [512, 512]  Wq
    const float* __restrict__ bias,   // [512]       bq
    float* __restrict__ C)            // [8192, 512] q
{
    __shared__ float As[16][132];     // transposed A tile, padded
    __shared__ float Bs[16][128];

    const int tid = threadIdx.x;
    const int tx = tid & 15, ty = tid >> 4;
    const int bm = blockIdx.y, bn = blockIdx.x;

    unsigned long long acc[2][4][2][2];
    #pragma unroll
    for (int a1 = 0; a1 < 2; a1++)
        #pragma unroll
        for (int a2 = 0; a2 < 4; a2++)
            #pragma unroll
            for (int a3 = 0; a3 < 2; a3++) {
                acc[a1][a2][a3][0] = 0ull; acc[a1][a2][a3][1] = 0ull;
            }

    const float* Ab = A + (size_t)bm * 128 * DIM;
    const float* Bb = B + bn * 128;

    for (int k0 = 0; k0 < DIM; k0 += 16) {
        #pragma unroll
        for (int i = 0; i < 2; i++) {
            int l = tid + i * 256;
            int r = l >> 2, c4 = (l & 3) * 4;
            float4 v = *(const float4*)(Ab + (size_t)r * DIM + k0 + c4);
            As[c4 + 0][r] = v.x; As[c4 + 1][r] = v.y;
            As[c4 + 2][r] = v.z; As[c4 + 3][r] = v.w;
        }
        #pragma unroll
        for (int i = 0; i < 2; i++) {
            int l = tid + i * 256;
            int r = l >> 5, c4 = (l & 31) * 4;
            *(float4*)&Bs[r][c4] = *(const float4*)(Bb + (size_t)(k0 + r) * DIM + c4);
        }
        __syncthreads();

        #pragma unroll
        for (int k = 0; k < 16; k++) {
            float4 av0 = *(const float4*)&As[k][ty * 4];
            float4 av1 = *(const float4*)&As[k][64 + ty * 4];
            float4 bv0 = *(const float4*)&Bs[k][tx * 4];
            float4 bv1 = *(const float4*)&Bs[k][64 + tx * 4];

            unsigned long long b2[2][2];
            asm("mov.b64 %0,{%1,%2};" : "=l"(b2[0][0]) : "f"(bv0.x), "f"(bv0.y));
            asm("mov.b64 %0,{%1,%2};" : "=l"(b2[0][1]) : "f"(bv0.z), "f"(bv0.w));
            asm("mov.b64 %0,{%1,%2};" : "=l"(b2[1][0]) : "f"(bv1.x), "f"(bv1.y));
            asm("mov.b64 %0,{%1,%2};" : "=l"(b2[1][1]) : "f"(bv1.z), "f"(bv1.w));

            float a_s[2][4];
            a_s[0][0] = av0.x; a_s[0][1] = av0.y; a_s[0][2] = av0.z; a_s[0][3] = av0.w;
            a_s[1][0] = av1.x; a_s[1][1] = av1.y; a_s[1][2] = av1.z; a_s[1][3] = av1.w;

            #pragma unroll
            for (int rh = 0; rh < 2; rh++) {
                #pragma unroll
                for (int i = 0; i < 4; i++) {
                    unsigned long long ap;
                    asm("mov.b64 %0,{%1,%1};" : "=l"(ap) : "f"(a_s[rh][i]));
                    #pragma unroll
                    for (int ch = 0; ch < 2; ch++) {
                        asm("fma.rn.f32x2 %0,%1,%2,%0;"
                            : "+l"(acc[rh][i][ch][0]) : "l"(ap), "l"(b2[ch][0]));
                        asm("fma.rn.f32x2 %0,%1,%2,%0;"
                            : "+l"(acc[rh][i][ch][1]) : "l"(ap), "l"(b2[ch][1]));
                    }
                }
            }
        }
        __syncthreads();
    }

    #pragma unroll
    for (int ch = 0; ch < 2; ch++) {
        int col = bn * 128 + ch * 64 + tx * 4;
        float4 bb = *(const float4*)(bias + col);
        #pragma unroll
        for (int rh = 0; rh < 2; rh++) {
            #pragma unroll
            for (int i = 0; i < 4; i++) {
                int row = bm * 128 + rh * 64 + ty * 4 + i;
                float p0x, p0y, p1x, p1y;
                asm("mov.b64 {%0,%1},%2;" : "=f"(p0x), "=f"(p0y) : "l"(acc[rh][i][ch][0]));
                asm("mov.b64 {%0,%1},%2;" : "=f"(p1x), "=f"(p1y) : "l"(acc[rh][i][ch][1]));
                float4 o = make_float4(p0x + bb.x, p0y + bb.y, p1x + bb.z, p1y + bb.w);
                *(float4*)(C + (size_t)row * DIM + col) = o;
            }
        }
    }
}

// ---------------- K2: per-edge score + segment max -------------------------
// one warp per edge; lane loads 16 floats (4x float4, stride 128)
__global__ __launch_bounds__(256) void score_kernel(
    const float* __restrict__ vals,
    const void* __restrict__ c0,
    const void* __restrict__ c1)
{
    const Cfg cfg = g_cfg;
    const int*  idx  = cfg.idx_is_1 ? (const int*)c1 : (const int*)c0;
    const void* mask = cfg.idx_is_1 ? c0 : c1;

    int e    = (blockIdx.x * 256 + threadIdx.x) >> 5;
    int lane = threadIdx.x & 31;
    if (!edge_live(mask, e, cfg.mask_byte)) return;
    int node = idx[e];

    const float* v  = vals + (size_t)e * DIM;
    const float* qp = g_q  + (size_t)node * DIM;
    float s = 0.f;
    #pragma unroll
    for (int j = 0; j < 4; j++) {
        float4 a = *(const float4*)(v  + lane * 4 + j * 128);
        float4 b = *(const float4*)(qp + lane * 4 + j * 128);
        s += a.x * b.x + a.y * b.y + a.z * b.z + a.w * b.w;
    }
    #pragma unroll
    for (int o = 16; o; o >>= 1) s += __shfl_xor_sync(0xFFFFFFFFu, s, o);

    if (lane == 0) {
        g_scores[e] = s;
        atomicMax(&g_smax[node], fflip(s));
    }
}

// ---------------- K3: w = exp(score - smax); scatter-add num/denom ---------
__global__ __launch_bounds__(256) void accum_kernel(
    const float* __restrict__ vals,
    const void* __restrict__ c0,
    const void* __restrict__ c1,
    float* __restrict__ out)
{
    const Cfg cfg = g_cfg;
    const int*  idx  = cfg.idx_is_1 ? (const int*)c1 : (const int*)c0;
    const void* mask = cfg.idx_is_1 ? c0 : c1;

    int e    = (blockIdx.x * 256 + threadIdx.x) >> 5;
    int lane = threadIdx.x & 31;
    if (!edge_live(mask, e, cfg.mask_byte)) return;
    int node = idx[e];

    float smax = funflip(g_smax[node]);
    float w = expf(g_scores[e] - smax);         // arg <= 0, no overflow
    if (lane == 0) atomicAdd(&g_denom[node], w);

    const float* v  = vals + (size_t)e * DIM;
    float* op       = out  + (size_t)node * DIM;
    #pragma unroll
    for (int j = 0; j < 4; j++) {
        float4 a = *(const float4*)(v + lane * 4 + j * 128);
        float x = w * a.x, y = w * a.y, z = w * a.z, ww = w * a.w;
        asm volatile("red.global.add.v4.f32 [%0], {%1,%2,%3,%4};"
                     :: "l"(op + lane * 4 + j * 128),
                        "f"(x), "f"(y), "f"(z), "f"(ww)
                     : "memory");
    }
}

// ---------------- K4: out /= max(denom, 1e-12) -----------------------------
__global__ __launch_bounds__(256) void finalize_kernel(float4* __restrict__ out) {
    int i = blockIdx.x * 256 + threadIdx.x;     // 1,048,576 threads
    int node = i >> 7;                          // 128 float4 per node row
    float inv = 1.0f / fmaxf(g_denom[node], 1e-12f);
    float4 v = out[i];
    v.x *= inv; v.y *= inv; v.z *= inv; v.w *= inv;
    out[i] = v;
}

// ---------------- launch ---------------------------------------------------
extern "C" void kernel_launch(void* const* d_in, const int* in_sizes, int n_in,
                              void* d_out, int out_size)
{
    const float* enc  = nullptr;   // [2048,64,512]
    const void*  c0   = nullptr;   // first 131072-element input (mask or idx)
    const void*  c1   = nullptr;   // second 131072-element input
    const float* prev = nullptr;   // [8192,512]
    const float* Wq   = nullptr;   // [512,512]
    const float* bq   = nullptr;   // [512]
    int n131072 = 0;

    for (int i = 0; i < n_in; i++) {
        switch (in_sizes[i]) {
            case 67108864: enc  = (const float*)d_in[i]; break;
            case 4194304:  prev = (const float*)d_in[i]; break;
            case 262144:   Wq   = (const float*)d_in[i]; break;
            case 512:      bq   = (const float*)d_in[i]; break;
            case 131072:
                if (n131072++ == 0) c0 = d_in[i];
                else                c1 = d_in[i];
                break;
            default: break;  // nr_cfg_nodes scalar (if materialized)
        }
    }

    float* out = (float*)d_out;
    float* q;
    cudaGetSymbolAddress((void**)&q, g_q);   // address lookup only, no alloc

    // K-1: classify the two 131072-element inputs (order + mask dtype)
    detect_kernel<<<1, 256>>>((const unsigned*)c0, (const unsigned*)c1);

    // K0: zero output, reset per-node state
    init_kernel<<<(N_NODES * DIM / 4) / 256, 256>>>((float4*)out);

    // K1: q = prev @ Wq + bq
    dim3 ggrid(DIM / 128, N_NODES / 128);    // (4, 64)
    gemm_q_kernel<<<ggrid, 256>>>(prev, Wq, bq, q);

    // K2: scores + segment max   (131072 warps)
    score_kernel<<<N_EDGES / 8, 256>>>(enc, c0, c1);

    // K3: softmax weights + scatter-add numerator/denominator
    accum_kernel<<<N_EDGES / 8, 256>>>(enc, c0, c1, out);

    // K4: divide
    finalize_kernel<<<(N_NODES * DIM / 4) / 256, 256>>>((float4*)out);
}

// round 4
// speedup vs baseline: 1.2565x; 1.2565x over previous
#include <cuda_runtime.h>
#include <cuda_bf16.h>
#include <cstdint>
#include <cstddef>

#define DIM      512
#define N_NODES  8192
#define N_EDGES  131072   // 2048 paths * 64

// ---------------- scratch (device globals; no runtime allocation) ----------
__device__ float         g_q[N_NODES * DIM];      // projected queries, fp32
__device__ float         g_scores[N_EDGES];
__device__ unsigned      g_smax[N_NODES];
__device__ float         g_denom[N_NODES];
__device__ __nv_bfloat16 g_Ahi[N_NODES * DIM];    // prev split hi  [8192][512]
__device__ __nv_bfloat16 g_Alo[N_NODES * DIM];    // prev split lo
__device__ __nv_bfloat16 g_BhiT[DIM * DIM];       // Wq^T split hi  [n][k]
__device__ __nv_bfloat16 g_BloT[DIM * DIM];       // Wq^T split lo

struct Cfg { int idx_is_1; int mask_byte; };
__device__ Cfg g_cfg;

// ---------------- helpers ---------------------------------------------------
__device__ __forceinline__ unsigned fflip(float f) {
    unsigned u = __float_as_uint(f);
    return u ^ ((u >> 31) ? 0xFFFFFFFFu : 0x80000000u);
}
__device__ __forceinline__ float funflip(unsigned u) {
    u ^= ((u >> 31) ? 0x80000000u : 0xFFFFFFFFu);
    return __uint_as_float(u);
}
__device__ __forceinline__ uint32_t smem_u32(const void* p) {
    uint32_t a;
    asm("{ .reg .u64 t; cvta.to.shared.u64 t, %1; cvt.u32.u64 %0, t; }" : "=r"(a) : "l"(p));
    return a;
}
__device__ __forceinline__ void ldm_x4(uint32_t& r0, uint32_t& r1, uint32_t& r2,
                                       uint32_t& r3, uint32_t addr) {
    asm volatile("ldmatrix.sync.aligned.m8n8.x4.shared.b16 {%0,%1,%2,%3}, [%4];"
                 : "=r"(r0), "=r"(r1), "=r"(r2), "=r"(r3) : "r"(addr));
}
__device__ __forceinline__ void mma_16816(float* c, const uint32_t* a, const uint32_t* b) {
    asm volatile(
        "mma.sync.aligned.m16n8k16.row.col.f32.bf16.bf16.f32 "
        "{%0,%1,%2,%3}, {%4,%5,%6,%7}, {%8,%9}, {%0,%1,%2,%3};"
        : "+f"(c[0]), "+f"(c[1]), "+f"(c[2]), "+f"(c[3])
        : "r"(a[0]), "r"(a[1]), "r"(a[2]), "r"(a[3]), "r"(b[0]), "r"(b[1]));
}

// ---------------- K-1: detect idx/mask binding -----------------------------
__global__ __launch_bounds__(256) void detect_kernel(
    const unsigned* __restrict__ c0, const unsigned* __restrict__ c1)
{
    __shared__ unsigned sm[2], so[2];
    if (threadIdx.x < 2) { sm[threadIdx.x] = 0u; so[threadIdx.x] = 0u; }
    __syncthreads();
    unsigned m0 = 0, m1 = 0, o0 = 0, o1 = 0;
    for (int i = threadIdx.x; i < 32768; i += 256) {
        unsigned a = c0[i], b = c1[i];
        m0 = max(m0, a); m1 = max(m1, b);
        o0 |= a & 0xFEFEFEFEu; o1 |= b & 0xFEFEFEFEu;
    }
    atomicMax(&sm[0], m0); atomicMax(&sm[1], m1);
    atomicOr (&so[0], o0); atomicOr (&so[1], o1);
    __syncthreads();
    if (threadIdx.x == 0) {
        unsigned M0 = sm[0], M1 = sm[1];
        int idx_is_1;
        if      (M0 <= 1u)                   idx_is_1 = 1;
        else if (M1 <= 1u)                   idx_is_1 = 0;
        else if (M0 < 8192u && M1 >= 8192u)  idx_is_1 = 0;
        else if (M1 < 8192u && M0 >= 8192u)  idx_is_1 = 1;
        else                                 idx_is_1 = 1;
        unsigned Mm = idx_is_1 ? M0 : M1;
        unsigned Om = idx_is_1 ? so[0] : so[1];
        g_cfg.idx_is_1  = idx_is_1;
        g_cfg.mask_byte = (Mm > 1u && Om == 0u) ? 1 : 0;
    }
}
__device__ __forceinline__ bool edge_live(const void* mask, int e, int mask_byte) {
    return mask_byte ? (((const unsigned char*)mask)[e] != 0)
                     : (((const unsigned*)mask)[e] != 0u);
}

// ---------------- K0: init output + per-node state -------------------------
__global__ __launch_bounds__(256) void init_kernel(float4* __restrict__ out) {
    int i = blockIdx.x * 256 + threadIdx.x;
    if (i < N_NODES) { g_smax[i] = fflip(-1e30f); g_denom[i] = 0.f; }
    out[i] = make_float4(0.f, 0.f, 0.f, 0.f);
}

// ---------------- C1: split prev into bf16 hi/lo ---------------------------
__global__ __launch_bounds__(256) void conv_prev_kernel(const float4* __restrict__ A) {
    int i = blockIdx.x * 256 + threadIdx.x;     // 1,048,576 float4
    float4 v = A[i];
    __nv_bfloat16 h0 = __float2bfloat16(v.x), h1 = __float2bfloat16(v.y);
    __nv_bfloat16 h2 = __float2bfloat16(v.z), h3 = __float2bfloat16(v.w);
    __nv_bfloat16 l0 = __float2bfloat16(v.x - __bfloat162float(h0));
    __nv_bfloat16 l1 = __float2bfloat16(v.y - __bfloat162float(h1));
    __nv_bfloat16 l2 = __float2bfloat16(v.z - __bfloat162float(h2));
    __nv_bfloat16 l3 = __float2bfloat16(v.w - __bfloat162float(h3));
    ((__nv_bfloat162*)g_Ahi)[i * 2 + 0] = __nv_bfloat162(h0, h1);
    ((__nv_bfloat162*)g_Ahi)[i * 2 + 1] = __nv_bfloat162(h2, h3);
    ((__nv_bfloat162*)g_Alo)[i * 2 + 0] = __nv_bfloat162(l0, l1);
    ((__nv_bfloat162*)g_Alo)[i * 2 + 1] = __nv_bfloat162(l2, l3);
}

// ---------------- C2: transpose+split Wq -> [n][k] bf16 hi/lo --------------
__global__ __launch_bounds__(256) void conv_wq_kernel(const float* __restrict__ Wq) {
    __shared__ float t[64][65];
    int n0 = blockIdx.x * 64, k0 = blockIdx.y * 64;
    #pragma unroll
    for (int i = 0; i < 16; i++) {
        int lin = threadIdx.x + i * 256;
        int r = lin >> 6, c = lin & 63;          // r = k offset, c = n offset
        t[r][c] = Wq[(size_t)(k0 + r) * DIM + n0 + c];
    }
    __syncthreads();
    #pragma unroll
    for (int i = 0; i < 16; i++) {
        int lin = threadIdx.x + i * 256;
        int r = lin >> 6, c = lin & 63;          // r = n offset, c = k offset
        float v = t[c][r];
        __nv_bfloat16 h = __float2bfloat16(v);
        __nv_bfloat16 l = __float2bfloat16(v - __bfloat162float(h));
        size_t o = (size_t)(n0 + r) * DIM + k0 + c;
        g_BhiT[o] = h; g_BloT[o] = l;
    }
}

// ---------------- K1: q = prev @ Wq + bq via mma.sync bf16-split -----------
// CTA 128x128, BK=32, 8 warps (2 in M x 4 in N), warp tile 64x32.
// acc += Ah*Bh + Ah*Bl + Al*Bh  (fp32 accumulators)
#define SSTRIDE 40   // padded bf16 row stride: 80 B -> conflict-free ldmatrix
__global__ __launch_bounds__(256) void gemm_mma_kernel(
    const float* __restrict__ bias, float* __restrict__ C)
{
    __shared__ __nv_bfloat16 sT[4][128][SSTRIDE];   // Ah, Al, Bh, Bl

    const int tid = threadIdx.x, wid = tid >> 5, lane = tid & 31;
    const int wm = wid & 1, wn = wid >> 1;          // warp grid 2(M) x 4(N)
    const int bm = blockIdx.y, bn = blockIdx.x;

    const __nv_bfloat16* srcs[4];
    srcs[0] = g_Ahi  + (size_t)bm * 128 * DIM;
    srcs[1] = g_Alo  + (size_t)bm * 128 * DIM;
    srcs[2] = g_BhiT + (size_t)bn * 128 * DIM;
    srcs[3] = g_BloT + (size_t)bn * 128 * DIM;

    float acc[4][4][4];
    #pragma unroll
    for (int i = 0; i < 4; i++)
        #pragma unroll
        for (int j = 0; j < 4; j++)
            #pragma unroll
            for (int k = 0; k < 4; k++) acc[i][j][k] = 0.f;

    // ldmatrix source addresses (per-lane)
    const uint32_t a_row = lane & 15, a_c8 = (lane >> 4) << 3;
    const uint32_t b_n   = (lane & 7) + ((lane >> 4) << 3);
    const uint32_t b_k8  = ((lane >> 3) & 1) << 3;
    uint32_t sA[2], sB[2];
    sA[0] = smem_u32(&sT[0][wm * 64 + a_row][a_c8]);
    sA[1] = smem_u32(&sT[1][wm * 64 + a_row][a_c8]);
    sB[0] = smem_u32(&sT[2][wn * 32 + b_n][b_k8]);
    sB[1] = smem_u32(&sT[3][wn * 32 + b_n][b_k8]);

    // per-thread global->smem mapping: 2 x 16B units per tile
    const int u0 = tid, u1 = tid + 256;             // of 512 units (128 rows x 4)
    const int r0 = u0 >> 2, c0 = (u0 & 3) * 8;
    const int r1 = u1 >> 2, c1 = (u1 & 3) * 8;

    uint4 pf[8];
    #pragma unroll
    for (int t = 0; t < 4; t++) {
        pf[t * 2 + 0] = *(const uint4*)(srcs[t] + (size_t)r0 * DIM + c0);
        pf[t * 2 + 1] = *(const uint4*)(srcs[t] + (size_t)r1 * DIM + c1);
    }

    for (int ch = 0; ch < 16; ch++) {
        #pragma unroll
        for (int t = 0; t < 4; t++) {
            *(uint4*)&sT[t][r0][c0] = pf[t * 2 + 0];
            *(uint4*)&sT[t][r1][c1] = pf[t * 2 + 1];
        }
        __syncthreads();

        if (ch < 15) {
            const int kb = (ch + 1) * 32;
            #pragma unroll
            for (int t = 0; t < 4; t++) {
                pf[t * 2 + 0] = *(const uint4*)(srcs[t] + (size_t)r0 * DIM + kb + c0);
                pf[t * 2 + 1] = *(const uint4*)(srcs[t] + (size_t)r1 * DIM + kb + c1);
            }
        }

        #pragma unroll
        for (int ks = 0; ks < 2; ks++) {
            const uint32_t ko = ks * 16 * 2;        // byte offset along k
            uint32_t ah[4][4], al[4][4], bh[4][2], bl[4][2];
            #pragma unroll
            for (int mi = 0; mi < 4; mi++) {
                uint32_t off = mi * 16 * SSTRIDE * 2 + ko;
                ldm_x4(ah[mi][0], ah[mi][1], ah[mi][2], ah[mi][3], sA[0] + off);
                ldm_x4(al[mi][0], al[mi][1], al[mi][2], al[mi][3], sA[1] + off);
            }
            #pragma unroll
            for (int nh = 0; nh < 2; nh++) {
                uint32_t off = nh * 16 * SSTRIDE * 2 + ko;
                ldm_x4(bh[nh*2][0], bh[nh*2][1], bh[nh*2+1][0], bh[nh*2+1][1], sB[0] + off);
                ldm_x4(bl[nh*2][0], bl[nh*2][1], bl[nh*2+1][0], bl[nh*2+1][1], sB[1] + off);
            }
            #pragma unroll
            for (int mi = 0; mi < 4; mi++)
                #pragma unroll
                for (int ni = 0; ni < 4; ni++) {
                    mma_16816(acc[mi][ni], ah[mi], bh[ni]);
                    mma_16816(acc[mi][ni], ah[mi], bl[ni]);
                    mma_16816(acc[mi][ni], al[mi], bh[ni]);
                }
        }
        __syncthreads();
    }

    // epilogue: direct global stores with bias
    const int qr = lane >> 2, qc = (lane & 3) * 2;
    #pragma unroll
    for (int ni = 0; ni < 4; ni++) {
        int col = bn * 128 + wn * 32 + ni * 8 + qc;
        float2 b = *(const float2*)(bias + col);
        #pragma unroll
        for (int mi = 0; mi < 4; mi++) {
            int row = bm * 128 + wm * 64 + mi * 16 + qr;
            float2 v0 = make_float2(acc[mi][ni][0] + b.x, acc[mi][ni][1] + b.y);
            float2 v1 = make_float2(acc[mi][ni][2] + b.x, acc[mi][ni][3] + b.y);
            *(float2*)(C + (size_t)row * DIM + col)       = v0;
            *(float2*)(C + (size_t)(row + 8) * DIM + col) = v1;
        }
    }
}

// ---------------- K2: per-edge score + segment max -------------------------
__global__ __launch_bounds__(256) void score_kernel(
    const float* __restrict__ vals,
    const void* __restrict__ c0,
    const void* __restrict__ c1)
{
    const Cfg cfg = g_cfg;
    const int*  idx  = cfg.idx_is_1 ? (const int*)c1 : (const int*)c0;
    const void* mask = cfg.idx_is_1 ? c0 : c1;

    int e    = (blockIdx.x * 256 + threadIdx.x) >> 5;
    int lane = threadIdx.x & 31;
    if (!edge_live(mask, e, cfg.mask_byte)) return;
    int node = idx[e];

    const float* v  = vals + (size_t)e * DIM;
    const float* qp = g_q  + (size_t)node * DIM;
    float s = 0.f;
    #pragma unroll
    for (int j = 0; j < 4; j++) {
        float4 a = *(const float4*)(v  + lane * 4 + j * 128);
        float4 b = *(const float4*)(qp + lane * 4 + j * 128);
        s += a.x * b.x + a.y * b.y + a.z * b.z + a.w * b.w;
    }
    #pragma unroll
    for (int o = 16; o; o >>= 1) s += __shfl_xor_sync(0xFFFFFFFFu, s, o);

    if (lane == 0) {
        g_scores[e] = s;
        atomicMax(&g_smax[node], fflip(s));
    }
}

// ---------------- K3: w = exp(score - smax); scatter-add -------------------
__global__ __launch_bounds__(256) void accum_kernel(
    const float* __restrict__ vals,
    const void* __restrict__ c0,
    const void* __restrict__ c1,
    float* __restrict__ out)
{
    const Cfg cfg = g_cfg;
    const int*  idx  = cfg.idx_is_1 ? (const int*)c1 : (const int*)c0;
    const void* mask = cfg.idx_is_1 ? c0 : c1;

    int e    = (blockIdx.x * 256 + threadIdx.x) >> 5;
    int lane = threadIdx.x & 31;
    if (!edge_live(mask, e, cfg.mask_byte)) return;
    int node = idx[e];

    float smax = funflip(g_smax[node]);
    float w = expf(g_scores[e] - smax);
    if (lane == 0) atomicAdd(&g_denom[node], w);

    const float* v  = vals + (size_t)e * DIM;
    float* op       = out  + (size_t)node * DIM;
    #pragma unroll
    for (int j = 0; j < 4; j++) {
        float4 a = *(const float4*)(v + lane * 4 + j * 128);
        float x = w * a.x, y = w * a.y, z = w * a.z, ww = w * a.w;
        asm volatile("red.global.add.v4.f32 [%0], {%1,%2,%3,%4};"
                     :: "l"(op + lane * 4 + j * 128),
                        "f"(x), "f"(y), "f"(z), "f"(ww)
                     : "memory");
    }
}

// ---------------- K4: out /= max(denom, 1e-12) -----------------------------
__global__ __launch_bounds__(256) void finalize_kernel(float4* __restrict__ out) {
    int i = blockIdx.x * 256 + threadIdx.x;
    int node = i >> 7;
    float inv = 1.0f / fmaxf(g_denom[node], 1e-12f);
    float4 v = out[i];
    v.x *= inv; v.y *= inv; v.z *= inv; v.w *= inv;
    out[i] = v;
}

// ---------------- launch ---------------------------------------------------
extern "C" void kernel_launch(void* const* d_in, const int* in_sizes, int n_in,
                              void* d_out, int out_size)
{
    const float* enc  = nullptr;
    const void*  c0   = nullptr;
    const void*  c1   = nullptr;
    const float* prev = nullptr;
    const float* Wq   = nullptr;
    const float* bq   = nullptr;
    int n131072 = 0;

    for (int i = 0; i < n_in; i++) {
        switch (in_sizes[i]) {
            case 67108864: enc  = (const float*)d_in[i]; break;
            case 4194304:  prev = (const float*)d_in[i]; break;
            case 262144:   Wq   = (const float*)d_in[i]; break;
            case 512:      bq   = (const float*)d_in[i]; break;
            case 131072:
                if (n131072++ == 0) c0 = d_in[i];
                else                c1 = d_in[i];
                break;
            default: break;
        }
    }

    float* out = (float*)d_out;
    float* q;
    cudaGetSymbolAddress((void**)&q, g_q);

    detect_kernel<<<1, 256>>>((const unsigned*)c0, (const unsigned*)c1);
    init_kernel<<<(N_NODES * DIM / 4) / 256, 256>>>((float4*)out);

    conv_prev_kernel<<<(N_NODES * DIM / 4) / 256, 256>>>((const float4*)prev);
    conv_wq_kernel<<<dim3(8, 8), 256>>>(Wq);

    dim3 ggrid(DIM / 128, N_NODES / 128);   // (4, 64)
    gemm_mma_kernel<<<ggrid, 256>>>(bq, q);

    score_kernel<<<N_EDGES / 8, 256>>>(enc, c0, c1);
    accum_kernel<<<N_EDGES / 8, 256>>>(enc, c0, c1, out);
    finalize_kernel<<<(N_NODES * DIM / 4) / 256, 256>>>((float4*)out);
}

// round 5
// speedup vs baseline: 1.3101x; 1.0427x over previous
#include <cuda_runtime.h>
#include <cuda_bf16.h>
#include <cstdint>
#include <cstddef>

#define DIM      512
#define N_NODES  8192
#define N_EDGES  131072   // 2048 paths * 64

// ---------------- scratch (device globals; no runtime allocation) ----------
__device__ float         g_q[N_NODES * DIM];      // projected queries, fp32
__device__ float         g_scores[N_EDGES];
__device__ unsigned      g_smax[N_NODES];
__device__ float         g_denom[N_NODES];
__device__ __nv_bfloat16 g_Ahi[N_NODES * DIM];    // prev split hi  [8192][512]
__device__ __nv_bfloat16 g_Alo[N_NODES * DIM];    // prev split lo
__device__ __nv_bfloat16 g_BhiT[DIM * DIM];       // Wq^T split hi  [n][k]
__device__ __nv_bfloat16 g_BloT[DIM * DIM];       // Wq^T split lo
__device__ int           g_live[N_EDGES];         // compacted live edge ids
__device__ int           g_livecount;

struct Cfg { int idx_is_1; int mask_byte; };
__device__ Cfg g_cfg;

// ---------------- helpers ---------------------------------------------------
__device__ __forceinline__ unsigned fflip(float f) {
    unsigned u = __float_as_uint(f);
    return u ^ ((u >> 31) ? 0xFFFFFFFFu : 0x80000000u);
}
__device__ __forceinline__ float funflip(unsigned u) {
    u ^= ((u >> 31) ? 0x80000000u : 0xFFFFFFFFu);
    return __uint_as_float(u);
}
__device__ __forceinline__ uint32_t smem_u32(const void* p) {
    uint32_t a;
    asm("{ .reg .u64 t; cvta.to.shared.u64 t, %1; cvt.u32.u64 %0, t; }" : "=r"(a) : "l"(p));
    return a;
}
__device__ __forceinline__ void ldm_x4(uint32_t& r0, uint32_t& r1, uint32_t& r2,
                                       uint32_t& r3, uint32_t addr) {
    asm volatile("ldmatrix.sync.aligned.m8n8.x4.shared.b16 {%0,%1,%2,%3}, [%4];"
                 : "=r"(r0), "=r"(r1), "=r"(r2), "=r"(r3) : "r"(addr));
}
__device__ __forceinline__ void mma_16816(float* c, const uint32_t* a, const uint32_t* b) {
    asm volatile(
        "mma.sync.aligned.m16n8k16.row.col.f32.bf16.bf16.f32 "
        "{%0,%1,%2,%3}, {%4,%5,%6,%7}, {%8,%9}, {%0,%1,%2,%3};"
        : "+f"(c[0]), "+f"(c[1]), "+f"(c[2]), "+f"(c[3])
        : "r"(a[0]), "r"(a[1]), "r"(a[2]), "r"(a[3]), "r"(b[0]), "r"(b[1]));
}
__device__ __forceinline__ float4 ldcs4(const float* p) {
    float4 v;
    asm volatile("ld.global.cs.v4.f32 {%0,%1,%2,%3}, [%4];"
                 : "=f"(v.x), "=f"(v.y), "=f"(v.z), "=f"(v.w) : "l"(p));
    return v;
}

// ---------------- K-1: detect idx/mask binding -----------------------------
__global__ __launch_bounds__(256) void detect_kernel(
    const unsigned* __restrict__ c0, const unsigned* __restrict__ c1)
{
    __shared__ unsigned sm[2], so[2];
    if (threadIdx.x < 2) { sm[threadIdx.x] = 0u; so[threadIdx.x] = 0u; }
    __syncthreads();
    unsigned m0 = 0, m1 = 0, o0 = 0, o1 = 0;
    for (int i = threadIdx.x; i < 32768; i += 256) {
        unsigned a = c0[i], b = c1[i];
        m0 = max(m0, a); m1 = max(m1, b);
        o0 |= a & 0xFEFEFEFEu; o1 |= b & 0xFEFEFEFEu;
    }
    atomicMax(&sm[0], m0); atomicMax(&sm[1], m1);
    atomicOr (&so[0], o0); atomicOr (&so[1], o1);
    __syncthreads();
    if (threadIdx.x == 0) {
        unsigned M0 = sm[0], M1 = sm[1];
        int idx_is_1;
        if      (M0 <= 1u)                   idx_is_1 = 1;
        else if (M1 <= 1u)                   idx_is_1 = 0;
        else if (M0 < 8192u && M1 >= 8192u)  idx_is_1 = 0;
        else if (M1 < 8192u && M0 >= 8192u)  idx_is_1 = 1;
        else                                 idx_is_1 = 1;
        unsigned Mm = idx_is_1 ? M0 : M1;
        unsigned Om = idx_is_1 ? so[0] : so[1];
        g_cfg.idx_is_1  = idx_is_1;
        g_cfg.mask_byte = (Mm > 1u && Om == 0u) ? 1 : 0;
        g_livecount = 0;
    }
}
__device__ __forceinline__ bool edge_live(const void* mask, int e, int mask_byte) {
    return mask_byte ? (((const unsigned char*)mask)[e] != 0)
                     : (((const unsigned*)mask)[e] != 0u);
}

// ---------------- K-0.5: compact live edges --------------------------------
__global__ __launch_bounds__(256) void compact_kernel(
    const void* __restrict__ c0, const void* __restrict__ c1)
{
    const Cfg cfg = g_cfg;
    const void* mask = cfg.idx_is_1 ? c0 : c1;
    int e = blockIdx.x * 256 + threadIdx.x;
    bool live = edge_live(mask, e, cfg.mask_byte);
    unsigned ball = __ballot_sync(0xFFFFFFFFu, live);
    int lane = threadIdx.x & 31;
    int base = 0;
    if (lane == 0) base = atomicAdd(&g_livecount, __popc(ball));
    base = __shfl_sync(0xFFFFFFFFu, base, 0);
    if (live) g_live[base + __popc(ball & ((1u << lane) - 1u))] = e;
}

// ---------------- K0: init output + per-node state -------------------------
__global__ __launch_bounds__(256) void init_kernel(float4* __restrict__ out) {
    int i = blockIdx.x * 256 + threadIdx.x;
    if (i < N_NODES) { g_smax[i] = fflip(-1e30f); g_denom[i] = 0.f; }
    out[i] = make_float4(0.f, 0.f, 0.f, 0.f);
}

// ---------------- C1: split prev into bf16 hi/lo ---------------------------
__global__ __launch_bounds__(256) void conv_prev_kernel(const float4* __restrict__ A) {
    int i = blockIdx.x * 256 + threadIdx.x;     // 1,048,576 float4
    float4 v = A[i];
    __nv_bfloat16 h0 = __float2bfloat16(v.x), h1 = __float2bfloat16(v.y);
    __nv_bfloat16 h2 = __float2bfloat16(v.z), h3 = __float2bfloat16(v.w);
    __nv_bfloat16 l0 = __float2bfloat16(v.x - __bfloat162float(h0));
    __nv_bfloat16 l1 = __float2bfloat16(v.y - __bfloat162float(h1));
    __nv_bfloat16 l2 = __float2bfloat16(v.z - __bfloat162float(h2));
    __nv_bfloat16 l3 = __float2bfloat16(v.w - __bfloat162float(h3));
    ((__nv_bfloat162*)g_Ahi)[i * 2 + 0] = __nv_bfloat162(h0, h1);
    ((__nv_bfloat162*)g_Ahi)[i * 2 + 1] = __nv_bfloat162(h2, h3);
    ((__nv_bfloat162*)g_Alo)[i * 2 + 0] = __nv_bfloat162(l0, l1);
    ((__nv_bfloat162*)g_Alo)[i * 2 + 1] = __nv_bfloat162(l2, l3);
}

// ---------------- C2: transpose+split Wq -> [n][k] bf16 hi/lo --------------
// 32x32 tiles, 256 CTAs -> latency-bound no more
__global__ __launch_bounds__(256) void conv_wq_kernel(const float* __restrict__ Wq) {
    __shared__ float t[32][33];
    int n0 = blockIdx.x * 32, k0 = blockIdx.y * 32;
    #pragma unroll
    for (int i = 0; i < 4; i++) {
        int lin = threadIdx.x + i * 256;
        int r = lin >> 5, c = lin & 31;          // r = k offset, c = n offset
        t[r][c] = Wq[(size_t)(k0 + r) * DIM + n0 + c];
    }
    __syncthreads();
    #pragma unroll
    for (int i = 0; i < 4; i++) {
        int lin = threadIdx.x + i * 256;
        int r = lin >> 5, c = lin & 31;          // r = n offset, c = k offset
        float v = t[c][r];
        __nv_bfloat16 h = __float2bfloat16(v);
        __nv_bfloat16 l = __float2bfloat16(v - __bfloat162float(h));
        size_t o = (size_t)(n0 + r) * DIM + k0 + c;
        g_BhiT[o] = h; g_BloT[o] = l;
    }
}

// ---------------- K1: q = prev @ Wq + bq via mma.sync bf16-split -----------
#define SSTRIDE 40   // padded bf16 row stride: 80 B -> conflict-free ldmatrix
__global__ __launch_bounds__(256) void gemm_mma_kernel(
    const float* __restrict__ bias, float* __restrict__ C)
{
    __shared__ __nv_bfloat16 sT[4][128][SSTRIDE];   // Ah, Al, Bh, Bl

    const int tid = threadIdx.x, wid = tid >> 5, lane = tid & 31;
    const int wm = wid & 1, wn = wid >> 1;          // warp grid 2(M) x 4(N)
    const int bm = blockIdx.y, bn = blockIdx.x;

    const __nv_bfloat16* srcs[4];
    srcs[0] = g_Ahi  + (size_t)bm * 128 * DIM;
    srcs[1] = g_Alo  + (size_t)bm * 128 * DIM;
    srcs[2] = g_BhiT + (size_t)bn * 128 * DIM;
    srcs[3] = g_BloT + (size_t)bn * 128 * DIM;

    float acc[4][4][4];
    #pragma unroll
    for (int i = 0; i < 4; i++)
        #pragma unroll
        for (int j = 0; j < 4; j++)
            #pragma unroll
            for (int k = 0; k < 4; k++) acc[i][j][k] = 0.f;

    const uint32_t a_row = lane & 15, a_c8 = (lane >> 4) << 3;
    const uint32_t b_n   = (lane & 7) + ((lane >> 4) << 3);
    const uint32_t b_k8  = ((lane >> 3) & 1) << 3;
    uint32_t sA[2], sB[2];
    sA[0] = smem_u32(&sT[0][wm * 64 + a_row][a_c8]);
    sA[1] = smem_u32(&sT[1][wm * 64 + a_row][a_c8]);
    sB[0] = smem_u32(&sT[2][wn * 32 + b_n][b_k8]);
    sB[1] = smem_u32(&sT[3][wn * 32 + b_n][b_k8]);

    const int u0 = tid, u1 = tid + 256;
    const int r0 = u0 >> 2, c0 = (u0 & 3) * 8;
    const int r1 = u1 >> 2, c1 = (u1 & 3) * 8;

    uint4 pf[8];
    #pragma unroll
    for (int t = 0; t < 4; t++) {
        pf[t * 2 + 0] = *(const uint4*)(srcs[t] + (size_t)r0 * DIM + c0);
        pf[t * 2 + 1] = *(const uint4*)(srcs[t] + (size_t)r1 * DIM + c1);
    }

    for (int ch = 0; ch < 16; ch++) {
        #pragma unroll
        for (int t = 0; t < 4; t++) {
            *(uint4*)&sT[t][r0][c0] = pf[t * 2 + 0];
            *(uint4*)&sT[t][r1][c1] = pf[t * 2 + 1];
        }
        __syncthreads();

        if (ch < 15) {
            const int kb = (ch + 1) * 32;
            #pragma unroll
            for (int t = 0; t < 4; t++) {
                pf[t * 2 + 0] = *(const uint4*)(srcs[t] + (size_t)r0 * DIM + kb + c0);
                pf[t * 2 + 1] = *(const uint4*)(srcs[t] + (size_t)r1 * DIM + kb + c1);
            }
        }

        #pragma unroll
        for (int ks = 0; ks < 2; ks++) {
            const uint32_t ko = ks * 16 * 2;
            uint32_t ah[4][4], al[4][4], bh[4][2], bl[4][2];
            #pragma unroll
            for (int mi = 0; mi < 4; mi++) {
                uint32_t off = mi * 16 * SSTRIDE * 2 + ko;
                ldm_x4(ah[mi][0], ah[mi][1], ah[mi][2], ah[mi][3], sA[0] + off);
                ldm_x4(al[mi][0], al[mi][1], al[mi][2], al[mi][3], sA[1] + off);
            }
            #pragma unroll
            for (int nh = 0; nh < 2; nh++) {
                uint32_t off = nh * 16 * SSTRIDE * 2 + ko;
                ldm_x4(bh[nh*2][0], bh[nh*2][1], bh[nh*2+1][0], bh[nh*2+1][1], sB[0] + off);
                ldm_x4(bl[nh*2][0], bl[nh*2][1], bl[nh*2+1][0], bl[nh*2+1][1], sB[1] + off);
            }
            #pragma unroll
            for (int mi = 0; mi < 4; mi++)
                #pragma unroll
                for (int ni = 0; ni < 4; ni++) {
                    mma_16816(acc[mi][ni], ah[mi], bh[ni]);
                    mma_16816(acc[mi][ni], ah[mi], bl[ni]);
                    mma_16816(acc[mi][ni], al[mi], bh[ni]);
                }
        }
        __syncthreads();
    }

    const int qr = lane >> 2, qc = (lane & 3) * 2;
    #pragma unroll
    for (int ni = 0; ni < 4; ni++) {
        int col = bn * 128 + wn * 32 + ni * 8 + qc;
        float2 b = *(const float2*)(bias + col);
        #pragma unroll
        for (int mi = 0; mi < 4; mi++) {
            int row = bm * 128 + wm * 64 + mi * 16 + qr;
            float2 v0 = make_float2(acc[mi][ni][0] + b.x, acc[mi][ni][1] + b.y);
            float2 v1 = make_float2(acc[mi][ni][2] + b.x, acc[mi][ni][3] + b.y);
            *(float2*)(C + (size_t)row * DIM + col)       = v0;
            *(float2*)(C + (size_t)(row + 8) * DIM + col) = v1;
        }
    }
}

// ---------------- K2: per-live-edge score + segment max --------------------
__global__ __launch_bounds__(256) void score_kernel(
    const float* __restrict__ vals,
    const void* __restrict__ c0,
    const void* __restrict__ c1)
{
    const Cfg cfg = g_cfg;
    const int* idx = cfg.idx_is_1 ? (const int*)c1 : (const int*)c0;

    int w    = (blockIdx.x * 256 + threadIdx.x) >> 5;
    int lane = threadIdx.x & 31;
    if (w >= g_livecount) return;
    int e    = g_live[w];
    int node = idx[e];

    const float* v  = vals + (size_t)e * DIM;
    const float* qp = g_q  + (size_t)node * DIM;
    float4 a[4], b[4];
    #pragma unroll
    for (int j = 0; j < 4; j++) a[j] = ldcs4(v + lane * 4 + j * 128);
    #pragma unroll
    for (int j = 0; j < 4; j++) b[j] = *(const float4*)(qp + lane * 4 + j * 128);
    float s = 0.f;
    #pragma unroll
    for (int j = 0; j < 4; j++)
        s += a[j].x * b[j].x + a[j].y * b[j].y + a[j].z * b[j].z + a[j].w * b[j].w;
    #pragma unroll
    for (int o = 16; o; o >>= 1) s += __shfl_xor_sync(0xFFFFFFFFu, s, o);

    if (lane == 0) {
        g_scores[e] = s;
        atomicMax(&g_smax[node], fflip(s));
    }
}

// ---------------- K3: w = exp(score - smax); scatter-add -------------------
__global__ __launch_bounds__(256) void accum_kernel(
    const float* __restrict__ vals,
    const void* __restrict__ c0,
    const void* __restrict__ c1,
    float* __restrict__ out)
{
    const Cfg cfg = g_cfg;
    const int* idx = cfg.idx_is_1 ? (const int*)c1 : (const int*)c0;

    int w    = (blockIdx.x * 256 + threadIdx.x) >> 5;
    int lane = threadIdx.x & 31;
    if (w >= g_livecount) return;
    int e    = g_live[w];
    int node = idx[e];

    float smax = funflip(g_smax[node]);
    float wgt  = expf(g_scores[e] - smax);
    if (lane == 0) atomicAdd(&g_denom[node], wgt);

    const float* v = vals + (size_t)e * DIM;
    float* op      = out  + (size_t)node * DIM;
    float4 a[4];
    #pragma unroll
    for (int j = 0; j < 4; j++) a[j] = ldcs4(v + lane * 4 + j * 128);
    #pragma unroll
    for (int j = 0; j < 4; j++) {
        float x = wgt * a[j].x, y = wgt * a[j].y, z = wgt * a[j].z, u = wgt * a[j].w;
        asm volatile("red.global.add.v4.f32 [%0], {%1,%2,%3,%4};"
                     :: "l"(op + lane * 4 + j * 128),
                        "f"(x), "f"(y), "f"(z), "f"(u)
                     : "memory");
    }
}

// ---------------- K4: out /= max(denom, 1e-12) -----------------------------
__global__ __launch_bounds__(256) void finalize_kernel(float4* __restrict__ out) {
    int i = blockIdx.x * 256 + threadIdx.x;
    int node = i >> 7;
    float inv = 1.0f / fmaxf(g_denom[node], 1e-12f);
    float4 v = out[i];
    v.x *= inv; v.y *= inv; v.z *= inv; v.w *= inv;
    out[i] = v;
}

// ---------------- launch ---------------------------------------------------
extern "C" void kernel_launch(void* const* d_in, const int* in_sizes, int n_in,
                              void* d_out, int out_size)
{
    const float* enc  = nullptr;
    const void*  c0   = nullptr;
    const void*  c1   = nullptr;
    const float* prev = nullptr;
    const float* Wq   = nullptr;
    const float* bq   = nullptr;
    int n131072 = 0;

    for (int i = 0; i < n_in; i++) {
        switch (in_sizes[i]) {
            case 67108864: enc  = (const float*)d_in[i]; break;
            case 4194304:  prev = (const float*)d_in[i]; break;
            case 262144:   Wq   = (const float*)d_in[i]; break;
            case 512:      bq   = (const float*)d_in[i]; break;
            case 131072:
                if (n131072++ == 0) c0 = d_in[i];
                else                c1 = d_in[i];
                break;
            default: break;
        }
    }

    float* out = (float*)d_out;
    float* q;
    cudaGetSymbolAddress((void**)&q, g_q);

    detect_kernel<<<1, 256>>>((const unsigned*)c0, (const unsigned*)c1);
    compact_kernel<<<N_EDGES / 256, 256>>>(c0, c1);
    init_kernel<<<(N_NODES * DIM / 4) / 256, 256>>>((float4*)out);

    conv_prev_kernel<<<(N_NODES * DIM / 4) / 256, 256>>>((const float4*)prev);
    conv_wq_kernel<<<dim3(16, 16), 256>>>(Wq);

    dim3 ggrid(DIM / 128, N_NODES / 128);   // (4, 64)
    gemm_mma_kernel<<<ggrid, 256>>>(bq, q);

    score_kernel<<<N_EDGES / 8, 256>>>(enc, c0, c1);
    accum_kernel<<<N_EDGES / 8, 256>>>(enc, c0, c1, out);
    finalize_kernel<<<(N_NODES * DIM / 4) / 256, 256>>>((float4*)out);
}

// round 6
// speedup vs baseline: 1.5583x; 1.1895x over previous
#include <cuda_runtime.h>
#include <cuda_bf16.h>
#include <cstdint>
#include <cstddef>

#define DIM      512
#define N_NODES  8192
#define N_EDGES  131072   // 2048 paths * 64

// ---------------- scratch (device globals; no runtime allocation) ----------
__device__ float         g_q[N_NODES * DIM];      // projected queries, fp32
__device__ __nv_bfloat16 g_Ahi[N_NODES * DIM];    // prev split hi
__device__ __nv_bfloat16 g_Alo[N_NODES * DIM];    // prev split lo
__device__ __nv_bfloat16 g_BhiT[DIM * DIM];       // Wq^T split hi [n][k]
__device__ __nv_bfloat16 g_BloT[DIM * DIM];       // Wq^T split lo
__device__ int           g_cnt[N_NODES];          // per-node live-edge counts
__device__ int           g_start[N_NODES + 1];    // CSR starts
__device__ int           g_cursor[N_NODES];       // scatter cursors
__device__ int           g_elist[N_EDGES];        // node-sorted live edge ids

struct Cfg { int idx_is_1; int mask_byte; };
__device__ Cfg g_cfg;

// ---------------- helpers ---------------------------------------------------
__device__ __forceinline__ uint32_t smem_u32(const void* p) {
    uint32_t a;
    asm("{ .reg .u64 t; cvta.to.shared.u64 t, %1; cvt.u32.u64 %0, t; }" : "=r"(a) : "l"(p));
    return a;
}
__device__ __forceinline__ void ldm_x4(uint32_t& r0, uint32_t& r1, uint32_t& r2,
                                       uint32_t& r3, uint32_t addr) {
    asm volatile("ldmatrix.sync.aligned.m8n8.x4.shared.b16 {%0,%1,%2,%3}, [%4];"
                 : "=r"(r0), "=r"(r1), "=r"(r2), "=r"(r3) : "r"(addr));
}
__device__ __forceinline__ void mma_16816(float* c, const uint32_t* a, const uint32_t* b) {
    asm volatile(
        "mma.sync.aligned.m16n8k16.row.col.f32.bf16.bf16.f32 "
        "{%0,%1,%2,%3}, {%4,%5,%6,%7}, {%8,%9}, {%0,%1,%2,%3};"
        : "+f"(c[0]), "+f"(c[1]), "+f"(c[2]), "+f"(c[3])
        : "r"(a[0]), "r"(a[1]), "r"(a[2]), "r"(a[3]), "r"(b[0]), "r"(b[1]));
}
__device__ __forceinline__ float4 ldcs4(const float* p) {
    float4 v;
    asm volatile("ld.global.cs.v4.f32 {%0,%1,%2,%3}, [%4];"
                 : "=f"(v.x), "=f"(v.y), "=f"(v.z), "=f"(v.w) : "l"(p));
    return v;
}

// ---------------- K-1: detect idx/mask binding -----------------------------
__global__ __launch_bounds__(256) void detect_kernel(
    const unsigned* __restrict__ c0, const unsigned* __restrict__ c1)
{
    __shared__ unsigned sm[2], so[2];
    if (threadIdx.x < 2) { sm[threadIdx.x] = 0u; so[threadIdx.x] = 0u; }
    __syncthreads();
    unsigned m0 = 0, m1 = 0, o0 = 0, o1 = 0;
    for (int i = threadIdx.x; i < 32768; i += 256) {
        unsigned a = c0[i], b = c1[i];
        m0 = max(m0, a); m1 = max(m1, b);
        o0 |= a & 0xFEFEFEFEu; o1 |= b & 0xFEFEFEFEu;
    }
    atomicMax(&sm[0], m0); atomicMax(&sm[1], m1);
    atomicOr (&so[0], o0); atomicOr (&so[1], o1);
    __syncthreads();
    if (threadIdx.x == 0) {
        unsigned M0 = sm[0], M1 = sm[1];
        int idx_is_1;
        if      (M0 <= 1u)                   idx_is_1 = 1;
        else if (M1 <= 1u)                   idx_is_1 = 0;
        else if (M0 < 8192u && M1 >= 8192u)  idx_is_1 = 0;
        else if (M1 < 8192u && M0 >= 8192u)  idx_is_1 = 1;
        else                                 idx_is_1 = 1;
        unsigned Mm = idx_is_1 ? M0 : M1;
        unsigned Om = idx_is_1 ? so[0] : so[1];
        g_cfg.idx_is_1  = idx_is_1;
        g_cfg.mask_byte = (Mm > 1u && Om == 0u) ? 1 : 0;
    }
}
__device__ __forceinline__ bool edge_live(const void* mask, int e, int mask_byte) {
    return mask_byte ? (((const unsigned char*)mask)[e] != 0)
                     : (((const unsigned*)mask)[e] != 0u);
}

// ---------------- S0: zero counts ------------------------------------------
__global__ __launch_bounds__(256) void zero_kernel() {
    g_cnt[blockIdx.x * 256 + threadIdx.x] = 0;
}

// ---------------- S1: histogram of live edges per node ----------------------
__global__ __launch_bounds__(256) void hist_kernel(
    const void* __restrict__ c0, const void* __restrict__ c1)
{
    const Cfg cfg = g_cfg;
    const int*  idx  = cfg.idx_is_1 ? (const int*)c1 : (const int*)c0;
    const void* mask = cfg.idx_is_1 ? c0 : c1;
    int e = blockIdx.x * 256 + threadIdx.x;
    if (edge_live(mask, e, cfg.mask_byte)) atomicAdd(&g_cnt[idx[e]], 1);
}

// ---------------- S2: exclusive scan over 8192 counts (one block) ----------
__global__ __launch_bounds__(1024) void scan_kernel() {
    __shared__ int part[1024];
    int t = threadIdx.x;
    int base = t * 8;
    int loc[8], s = 0;
    #pragma unroll
    for (int i = 0; i < 8; i++) { loc[i] = g_cnt[base + i]; s += loc[i]; }
    part[t] = s;
    __syncthreads();
    #pragma unroll
    for (int ofs = 1; ofs < 1024; ofs <<= 1) {
        int v = (t >= ofs) ? part[t - ofs] : 0;
        __syncthreads();
        part[t] += v;
        __syncthreads();
    }
    int excl = part[t] - s;
    #pragma unroll
    for (int i = 0; i < 8; i++) {
        g_start[base + i]  = excl;
        g_cursor[base + i] = excl;
        excl += loc[i];
    }
    if (t == 1023) g_start[N_NODES] = excl;
}

// ---------------- S3: scatter live edges into node-sorted list -------------
__global__ __launch_bounds__(256) void scatter_kernel(
    const void* __restrict__ c0, const void* __restrict__ c1)
{
    const Cfg cfg = g_cfg;
    const int*  idx  = cfg.idx_is_1 ? (const int*)c1 : (const int*)c0;
    const void* mask = cfg.idx_is_1 ? c0 : c1;
    int e = blockIdx.x * 256 + threadIdx.x;
    if (edge_live(mask, e, cfg.mask_byte)) {
        int p = atomicAdd(&g_cursor[idx[e]], 1);
        g_elist[p] = e;
    }
}

// ---------------- C1: split prev into bf16 hi/lo (4 f4/thread) -------------
__global__ __launch_bounds__(256) void conv_prev_kernel(const float4* __restrict__ A) {
    int base = blockIdx.x * 1024 + threadIdx.x;
    #pragma unroll
    for (int k = 0; k < 4; k++) {
        int i = base + k * 256;
        float4 v = A[i];
        __nv_bfloat16 h0 = __float2bfloat16(v.x), h1 = __float2bfloat16(v.y);
        __nv_bfloat16 h2 = __float2bfloat16(v.z), h3 = __float2bfloat16(v.w);
        __nv_bfloat16 l0 = __float2bfloat16(v.x - __bfloat162float(h0));
        __nv_bfloat16 l1 = __float2bfloat16(v.y - __bfloat162float(h1));
        __nv_bfloat16 l2 = __float2bfloat16(v.z - __bfloat162float(h2));
        __nv_bfloat16 l3 = __float2bfloat16(v.w - __bfloat162float(h3));
        ((__nv_bfloat162*)g_Ahi)[i * 2 + 0] = __nv_bfloat162(h0, h1);
        ((__nv_bfloat162*)g_Ahi)[i * 2 + 1] = __nv_bfloat162(h2, h3);
        ((__nv_bfloat162*)g_Alo)[i * 2 + 0] = __nv_bfloat162(l0, l1);
        ((__nv_bfloat162*)g_Alo)[i * 2 + 1] = __nv_bfloat162(l2, l3);
    }
}

// ---------------- C2: transpose+split Wq -> [n][k] bf16 hi/lo --------------
__global__ __launch_bounds__(256) void conv_wq_kernel(const float* __restrict__ Wq) {
    __shared__ float t[32][33];
    int n0 = blockIdx.x * 32, k0 = blockIdx.y * 32;
    #pragma unroll
    for (int i = 0; i < 4; i++) {
        int lin = threadIdx.x + i * 256;
        int r = lin >> 5, c = lin & 31;
        t[r][c] = Wq[(size_t)(k0 + r) * DIM + n0 + c];
    }
    __syncthreads();
    #pragma unroll
    for (int i = 0; i < 4; i++) {
        int lin = threadIdx.x + i * 256;
        int r = lin >> 5, c = lin & 31;
        float v = t[c][r];
        __nv_bfloat16 h = __float2bfloat16(v);
        __nv_bfloat16 l = __float2bfloat16(v - __bfloat162float(h));
        size_t o = (size_t)(n0 + r) * DIM + k0 + c;
        g_BhiT[o] = h; g_BloT[o] = l;
    }
}

// ---------------- K1: q = prev @ Wq + bq via mma.sync bf16-split -----------
#define SSTRIDE 40   // padded bf16 row stride: 80 B -> conflict-free ldmatrix
__global__ __launch_bounds__(256) void gemm_mma_kernel(
    const float* __restrict__ bias, float* __restrict__ C)
{
    __shared__ __nv_bfloat16 sT[4][128][SSTRIDE];   // Ah, Al, Bh, Bl

    const int tid = threadIdx.x, wid = tid >> 5, lane = tid & 31;
    const int wm = wid & 1, wn = wid >> 1;
    const int bm = blockIdx.y, bn = blockIdx.x;

    const __nv_bfloat16* srcs[4];
    srcs[0] = g_Ahi  + (size_t)bm * 128 * DIM;
    srcs[1] = g_Alo  + (size_t)bm * 128 * DIM;
    srcs[2] = g_BhiT + (size_t)bn * 128 * DIM;
    srcs[3] = g_BloT + (size_t)bn * 128 * DIM;

    float acc[4][4][4];
    #pragma unroll
    for (int i = 0; i < 4; i++)
        #pragma unroll
        for (int j = 0; j < 4; j++)
            #pragma unroll
            for (int k = 0; k < 4; k++) acc[i][j][k] = 0.f;

    const uint32_t a_row = lane & 15, a_c8 = (lane >> 4) << 3;
    const uint32_t b_n   = (lane & 7) + ((lane >> 4) << 3);
    const uint32_t b_k8  = ((lane >> 3) & 1) << 3;
    uint32_t sA[2], sB[2];
    sA[0] = smem_u32(&sT[0][wm * 64 + a_row][a_c8]);
    sA[1] = smem_u32(&sT[1][wm * 64 + a_row][a_c8]);
    sB[0] = smem_u32(&sT[2][wn * 32 + b_n][b_k8]);
    sB[1] = smem_u32(&sT[3][wn * 32 + b_n][b_k8]);

    const int u0 = tid, u1 = tid + 256;
    const int r0 = u0 >> 2, c0 = (u0 & 3) * 8;
    const int r1 = u1 >> 2, c1 = (u1 & 3) * 8;

    uint4 pf[8];
    #pragma unroll
    for (int t = 0; t < 4; t++) {
        pf[t * 2 + 0] = *(const uint4*)(srcs[t] + (size_t)r0 * DIM + c0);
        pf[t * 2 + 1] = *(const uint4*)(srcs[t] + (size_t)r1 * DIM + c1);
    }

    for (int ch = 0; ch < 16; ch++) {
        #pragma unroll
        for (int t = 0; t < 4; t++) {
            *(uint4*)&sT[t][r0][c0] = pf[t * 2 + 0];
            *(uint4*)&sT[t][r1][c1] = pf[t * 2 + 1];
        }
        __syncthreads();

        if (ch < 15) {
            const int kb = (ch + 1) * 32;
            #pragma unroll
            for (int t = 0; t < 4; t++) {
                pf[t * 2 + 0] = *(const uint4*)(srcs[t] + (size_t)r0 * DIM + kb + c0);
                pf[t * 2 + 1] = *(const uint4*)(srcs[t] + (size_t)r1 * DIM + kb + c1);
            }
        }

        #pragma unroll
        for (int ks = 0; ks < 2; ks++) {
            const uint32_t ko = ks * 16 * 2;
            uint32_t ah[4][4], al[4][4], bh[4][2], bl[4][2];
            #pragma unroll
            for (int mi = 0; mi < 4; mi++) {
                uint32_t off = mi * 16 * SSTRIDE * 2 + ko;
                ldm_x4(ah[mi][0], ah[mi][1], ah[mi][2], ah[mi][3], sA[0] + off);
                ldm_x4(al[mi][0], al[mi][1], al[mi][2], al[mi][3], sA[1] + off);
            }
            #pragma unroll
            for (int nh = 0; nh < 2; nh++) {
                uint32_t off = nh * 16 * SSTRIDE * 2 + ko;
                ldm_x4(bh[nh*2][0], bh[nh*2][1], bh[nh*2+1][0], bh[nh*2+1][1], sB[0] + off);
                ldm_x4(bl[nh*2][0], bl[nh*2][1], bl[nh*2+1][0], bl[nh*2+1][1], sB[1] + off);
            }
            #pragma unroll
            for (int mi = 0; mi < 4; mi++)
                #pragma unroll
                for (int ni = 0; ni < 4; ni++) {
                    mma_16816(acc[mi][ni], ah[mi], bh[ni]);
                    mma_16816(acc[mi][ni], ah[mi], bl[ni]);
                    mma_16816(acc[mi][ni], al[mi], bh[ni]);
                }
        }
        __syncthreads();
    }

    const int qr = lane >> 2, qc = (lane & 3) * 2;
    #pragma unroll
    for (int ni = 0; ni < 4; ni++) {
        int col = bn * 128 + wn * 32 + ni * 8 + qc;
        float2 b = *(const float2*)(bias + col);
        #pragma unroll
        for (int mi = 0; mi < 4; mi++) {
            int row = bm * 128 + wm * 64 + mi * 16 + qr;
            float2 v0 = make_float2(acc[mi][ni][0] + b.x, acc[mi][ni][1] + b.y);
            float2 v1 = make_float2(acc[mi][ni][2] + b.x, acc[mi][ni][3] + b.y);
            *(float2*)(C + (size_t)row * DIM + col)       = v0;
            *(float2*)(C + (size_t)(row + 8) * DIM + col) = v1;
        }
    }
}

// ---------------- K2: fused node-major online-softmax attention ------------
// one warp per node: single pass over its live edges, no atomics, no revisit
__global__ __launch_bounds__(256) void attn_kernel(
    const float* __restrict__ vals, float* __restrict__ out)
{
    int node = (blockIdx.x * 256 + threadIdx.x) >> 5;
    int lane = threadIdx.x & 31;

    int s0 = g_start[node], s1 = g_start[node + 1];

    const float* qp = g_q + (size_t)node * DIM;
    float4 q[4];
    #pragma unroll
    for (int j = 0; j < 4; j++) q[j] = *(const float4*)(qp + lane * 4 + j * 128);

    float m = -1e30f, d = 0.f;
    float4 acc[4];
    #pragma unroll
    for (int j = 0; j < 4; j++) acc[j] = make_float4(0.f, 0.f, 0.f, 0.f);

    for (int p = s0; p < s1; p++) {
        int e = g_elist[p];
        const float* v = vals + (size_t)e * DIM;
        float4 a[4];
        #pragma unroll
        for (int j = 0; j < 4; j++) a[j] = ldcs4(v + lane * 4 + j * 128);

        float s = 0.f;
        #pragma unroll
        for (int j = 0; j < 4; j++)
            s += a[j].x * q[j].x + a[j].y * q[j].y + a[j].z * q[j].z + a[j].w * q[j].w;
        #pragma unroll
        for (int o = 16; o; o >>= 1) s += __shfl_xor_sync(0xFFFFFFFFu, s, o);

        if (s > m) {                         // online rescale (warp-uniform)
            float r = expf(m - s);           // exp(-inf)=0 on first hit
            d *= r;
            #pragma unroll
            for (int j = 0; j < 4; j++) {
                acc[j].x *= r; acc[j].y *= r; acc[j].z *= r; acc[j].w *= r;
            }
            m = s;
        }
        float w = expf(s - m);
        d += w;
        #pragma unroll
        for (int j = 0; j < 4; j++) {
            acc[j].x += w * a[j].x; acc[j].y += w * a[j].y;
            acc[j].z += w * a[j].z; acc[j].w += w * a[j].w;
        }
    }

    float inv = 1.0f / fmaxf(d, 1e-12f);
    float* op = out + (size_t)node * DIM;
    #pragma unroll
    for (int j = 0; j < 4; j++) {
        float4 o = make_float4(acc[j].x * inv, acc[j].y * inv,
                               acc[j].z * inv, acc[j].w * inv);
        *(float4*)(op + lane * 4 + j * 128) = o;
    }
}

// ---------------- launch ---------------------------------------------------
extern "C" void kernel_launch(void* const* d_in, const int* in_sizes, int n_in,
                              void* d_out, int out_size)
{
    const float* enc  = nullptr;
    const void*  c0   = nullptr;
    const void*  c1   = nullptr;
    const float* prev = nullptr;
    const float* Wq   = nullptr;
    const float* bq   = nullptr;
    int n131072 = 0;

    for (int i = 0; i < n_in; i++) {
        switch (in_sizes[i]) {
            case 67108864: enc  = (const float*)d_in[i]; break;
            case 4194304:  prev = (const float*)d_in[i]; break;
            case 262144:   Wq   = (const float*)d_in[i]; break;
            case 512:      bq   = (const float*)d_in[i]; break;
            case 131072:
                if (n131072++ == 0) c0 = d_in[i];
                else                c1 = d_in[i];
                break;
            default: break;
        }
    }

    float* out = (float*)d_out;
    float* q;
    cudaGetSymbolAddress((void**)&q, g_q);

    detect_kernel<<<1, 256>>>((const unsigned*)c0, (const unsigned*)c1);
    zero_kernel<<<N_NODES / 256, 256>>>();
    hist_kernel<<<N_EDGES / 256, 256>>>(c0, c1);
    scan_kernel<<<1, 1024>>>();
    scatter_kernel<<<N_EDGES / 256, 256>>>(c0, c1);

    conv_prev_kernel<<<(N_NODES * DIM / 4) / 1024, 256>>>((const float4*)prev);
    conv_wq_kernel<<<dim3(16, 16), 256>>>(Wq);

    dim3 ggrid(DIM / 128, N_NODES / 128);   // (4, 64)
    gemm_mma_kernel<<<ggrid, 256>>>(bq, q);

    attn_kernel<<<N_NODES / 8, 256>>>(enc, out);
}

// round 7
// speedup vs baseline: 1.5797x; 1.0137x over previous
#include <cuda_runtime.h>
#include <cuda_bf16.h>
#include <cstdint>
#include <cstddef>

#define DIM      512
#define N_NODES  8192
#define N_EDGES  131072   // 2048 paths * 64

// ---------------- scratch (device globals; no runtime allocation) ----------
__device__ float         g_q[N_NODES * DIM];      // projected queries, fp32
__device__ __nv_bfloat16 g_Ahi[N_NODES * DIM];    // prev split hi
__device__ __nv_bfloat16 g_Alo[N_NODES * DIM];    // prev split lo
__device__ __nv_bfloat16 g_BhiT[DIM * DIM];       // Wq^T split hi [n][k]
__device__ __nv_bfloat16 g_BloT[DIM * DIM];       // Wq^T split lo
__device__ int           g_cnt[N_NODES];          // per-node live-edge counts
__device__ int           g_start[N_NODES + 1];    // CSR starts
__device__ int           g_cursor[N_NODES];       // scatter cursors
__device__ int           g_elist[N_EDGES];        // node-sorted live edge ids

struct Cfg { int idx_is_1; int mask_byte; };
__device__ Cfg g_cfg;

// ---------------- helpers ---------------------------------------------------
__device__ __forceinline__ uint32_t smem_u32(const void* p) {
    uint32_t a;
    asm("{ .reg .u64 t; cvta.to.shared.u64 t, %1; cvt.u32.u64 %0, t; }" : "=r"(a) : "l"(p));
    return a;
}
__device__ __forceinline__ void ldm_x4(uint32_t& r0, uint32_t& r1, uint32_t& r2,
                                       uint32_t& r3, uint32_t addr) {
    asm volatile("ldmatrix.sync.aligned.m8n8.x4.shared.b16 {%0,%1,%2,%3}, [%4];"
                 : "=r"(r0), "=r"(r1), "=r"(r2), "=r"(r3) : "r"(addr));
}
__device__ __forceinline__ void mma_16816(float* c, const uint32_t* a, const uint32_t* b) {
    asm volatile(
        "mma.sync.aligned.m16n8k16.row.col.f32.bf16.bf16.f32 "
        "{%0,%1,%2,%3}, {%4,%5,%6,%7}, {%8,%9}, {%0,%1,%2,%3};"
        : "+f"(c[0]), "+f"(c[1]), "+f"(c[2]), "+f"(c[3])
        : "r"(a[0]), "r"(a[1]), "r"(a[2]), "r"(a[3]), "r"(b[0]), "r"(b[1]));
}
__device__ __forceinline__ float4 ldcs4(const float* p) {
    float4 v;
    asm volatile("ld.global.cs.v4.f32 {%0,%1,%2,%3}, [%4];"
                 : "=f"(v.x), "=f"(v.y), "=f"(v.z), "=f"(v.w) : "l"(p));
    return v;
}

// ---------------- K-1: detect idx/mask binding + zero counts ---------------
__global__ __launch_bounds__(256) void detect_kernel(
    const unsigned* __restrict__ c0, const unsigned* __restrict__ c1)
{
    // fused: zero the histogram (8192 ints / 256 threads = 32 each)
    #pragma unroll
    for (int i = 0; i < 32; i++) g_cnt[threadIdx.x + i * 256] = 0;

    __shared__ unsigned sm[2], so[2];
    if (threadIdx.x < 2) { sm[threadIdx.x] = 0u; so[threadIdx.x] = 0u; }
    __syncthreads();
    unsigned m0 = 0, m1 = 0, o0 = 0, o1 = 0;
    for (int i = threadIdx.x; i < 32768; i += 256) {
        unsigned a = c0[i], b = c1[i];
        m0 = max(m0, a); m1 = max(m1, b);
        o0 |= a & 0xFEFEFEFEu; o1 |= b & 0xFEFEFEFEu;
    }
    atomicMax(&sm[0], m0); atomicMax(&sm[1], m1);
    atomicOr (&so[0], o0); atomicOr (&so[1], o1);
    __syncthreads();
    if (threadIdx.x == 0) {
        unsigned M0 = sm[0], M1 = sm[1];
        int idx_is_1;
        if      (M0 <= 1u)                   idx_is_1 = 1;
        else if (M1 <= 1u)                   idx_is_1 = 0;
        else if (M0 < 8192u && M1 >= 8192u)  idx_is_1 = 0;
        else if (M1 < 8192u && M0 >= 8192u)  idx_is_1 = 1;
        else                                 idx_is_1 = 1;
        unsigned Mm = idx_is_1 ? M0 : M1;
        unsigned Om = idx_is_1 ? so[0] : so[1];
        g_cfg.idx_is_1  = idx_is_1;
        g_cfg.mask_byte = (Mm > 1u && Om == 0u) ? 1 : 0;
    }
}
__device__ __forceinline__ bool edge_live(const void* mask, int e, int mask_byte) {
    return mask_byte ? (((const unsigned char*)mask)[e] != 0)
                     : (((const unsigned*)mask)[e] != 0u);
}

// ---------------- S1: histogram of live edges per node ----------------------
__global__ __launch_bounds__(256) void hist_kernel(
    const void* __restrict__ c0, const void* __restrict__ c1)
{
    const Cfg cfg = g_cfg;
    const int*  idx  = cfg.idx_is_1 ? (const int*)c1 : (const int*)c0;
    const void* mask = cfg.idx_is_1 ? c0 : c1;
    int e = blockIdx.x * 256 + threadIdx.x;
    if (edge_live(mask, e, cfg.mask_byte)) atomicAdd(&g_cnt[idx[e]], 1);
}

// ---------------- S2: exclusive scan over 8192 counts (shuffle-based) ------
__global__ __launch_bounds__(1024) void scan_kernel() {
    __shared__ int wsum[32];
    const int t = threadIdx.x, lane = t & 31, wid = t >> 5;
    const int base = t * 8;

    int loc[8], tot = 0;
    #pragma unroll
    for (int i = 0; i < 8; i++) { loc[i] = g_cnt[base + i]; tot += loc[i]; }

    // warp inclusive scan of per-thread totals
    int inc = tot;
    #pragma unroll
    for (int o = 1; o < 32; o <<= 1) {
        int v = __shfl_up_sync(0xFFFFFFFFu, inc, o);
        if (lane >= o) inc += v;
    }
    if (lane == 31) wsum[wid] = inc;
    __syncthreads();

    if (wid == 0) {
        int w = wsum[lane];
        #pragma unroll
        for (int o = 1; o < 32; o <<= 1) {
            int v = __shfl_up_sync(0xFFFFFFFFu, w, o);
            if (lane >= o) w += v;
        }
        wsum[lane] = w;                       // inclusive warp prefix
    }
    __syncthreads();

    int excl = (wid ? wsum[wid - 1] : 0) + (inc - tot);
    #pragma unroll
    for (int i = 0; i < 8; i++) {
        g_start[base + i]  = excl;
        g_cursor[base + i] = excl;
        excl += loc[i];
    }
    if (t == 1023) g_start[N_NODES] = excl;
}

// ---------------- S3: scatter live edges into node-sorted list -------------
__global__ __launch_bounds__(256) void scatter_kernel(
    const void* __restrict__ c0, const void* __restrict__ c1)
{
    const Cfg cfg = g_cfg;
    const int*  idx  = cfg.idx_is_1 ? (const int*)c1 : (const int*)c0;
    const void* mask = cfg.idx_is_1 ? c0 : c1;
    int e = blockIdx.x * 256 + threadIdx.x;
    if (edge_live(mask, e, cfg.mask_byte)) {
        int p = atomicAdd(&g_cursor[idx[e]], 1);
        g_elist[p] = e;
    }
}

// ---------------- C1: split prev into bf16 hi/lo (4 f4/thread) -------------
__global__ __launch_bounds__(256) void conv_prev_kernel(const float4* __restrict__ A) {
    int base = blockIdx.x * 1024 + threadIdx.x;
    #pragma unroll
    for (int k = 0; k < 4; k++) {
        int i = base + k * 256;
        float4 v = A[i];
        __nv_bfloat16 h0 = __float2bfloat16(v.x), h1 = __float2bfloat16(v.y);
        __nv_bfloat16 h2 = __float2bfloat16(v.z), h3 = __float2bfloat16(v.w);
        __nv_bfloat16 l0 = __float2bfloat16(v.x - __bfloat162float(h0));
        __nv_bfloat16 l1 = __float2bfloat16(v.y - __bfloat162float(h1));
        __nv_bfloat16 l2 = __float2bfloat16(v.z - __bfloat162float(h2));
        __nv_bfloat16 l3 = __float2bfloat16(v.w - __bfloat162float(h3));
        ((__nv_bfloat162*)g_Ahi)[i * 2 + 0] = __nv_bfloat162(h0, h1);
        ((__nv_bfloat162*)g_Ahi)[i * 2 + 1] = __nv_bfloat162(h2, h3);
        ((__nv_bfloat162*)g_Alo)[i * 2 + 0] = __nv_bfloat162(l0, l1);
        ((__nv_bfloat162*)g_Alo)[i * 2 + 1] = __nv_bfloat162(l2, l3);
    }
}

// ---------------- C2: transpose+split Wq -> [n][k] bf16 hi/lo --------------
__global__ __launch_bounds__(256) void conv_wq_kernel(const float* __restrict__ Wq) {
    __shared__ float t[32][33];
    int n0 = blockIdx.x * 32, k0 = blockIdx.y * 32;
    #pragma unroll
    for (int i = 0; i < 4; i++) {
        int lin = threadIdx.x + i * 256;
        int r = lin >> 5, c = lin & 31;
        t[r][c] = Wq[(size_t)(k0 + r) * DIM + n0 + c];
    }
    __syncthreads();
    #pragma unroll
    for (int i = 0; i < 4; i++) {
        int lin = threadIdx.x + i * 256;
        int r = lin >> 5, c = lin & 31;
        float v = t[c][r];
        __nv_bfloat16 h = __float2bfloat16(v);
        __nv_bfloat16 l = __float2bfloat16(v - __bfloat162float(h));
        size_t o = (size_t)(n0 + r) * DIM + k0 + c;
        g_BhiT[o] = h; g_BloT[o] = l;
    }
}

// ---------------- K1: q = prev @ Wq + bq via mma.sync bf16-split -----------
#define SSTRIDE 40   // padded bf16 row stride: 80 B -> conflict-free ldmatrix
__global__ __launch_bounds__(256) void gemm_mma_kernel(
    const float* __restrict__ bias, float* __restrict__ C)
{
    __shared__ __nv_bfloat16 sT[4][128][SSTRIDE];   // Ah, Al, Bh, Bl

    const int tid = threadIdx.x, wid = tid >> 5, lane = tid & 31;
    const int wm = wid & 1, wn = wid >> 1;
    const int bm = blockIdx.y, bn = blockIdx.x;

    const __nv_bfloat16* srcs[4];
    srcs[0] = g_Ahi  + (size_t)bm * 128 * DIM;
    srcs[1] = g_Alo  + (size_t)bm * 128 * DIM;
    srcs[2] = g_BhiT + (size_t)bn * 128 * DIM;
    srcs[3] = g_BloT + (size_t)bn * 128 * DIM;

    float acc[4][4][4];
    #pragma unroll
    for (int i = 0; i < 4; i++)
        #pragma unroll
        for (int j = 0; j < 4; j++)
            #pragma unroll
            for (int k = 0; k < 4; k++) acc[i][j][k] = 0.f;

    const uint32_t a_row = lane & 15, a_c8 = (lane >> 4) << 3;
    const uint32_t b_n   = (lane & 7) + ((lane >> 4) << 3);
    const uint32_t b_k8  = ((lane >> 3) & 1) << 3;
    uint32_t sA[2], sB[2];
    sA[0] = smem_u32(&sT[0][wm * 64 + a_row][a_c8]);
    sA[1] = smem_u32(&sT[1][wm * 64 + a_row][a_c8]);
    sB[0] = smem_u32(&sT[2][wn * 32 + b_n][b_k8]);
    sB[1] = smem_u32(&sT[3][wn * 32 + b_n][b_k8]);

    const int u0 = tid, u1 = tid + 256;
    const int r0 = u0 >> 2, c0 = (u0 & 3) * 8;
    const int r1 = u1 >> 2, c1 = (u1 & 3) * 8;

    uint4 pf[8];
    #pragma unroll
    for (int t = 0; t < 4; t++) {
        pf[t * 2 + 0] = *(const uint4*)(srcs[t] + (size_t)r0 * DIM + c0);
        pf[t * 2 + 1] = *(const uint4*)(srcs[t] + (size_t)r1 * DIM + c1);
    }

    for (int ch = 0; ch < 16; ch++) {
        #pragma unroll
        for (int t = 0; t < 4; t++) {
            *(uint4*)&sT[t][r0][c0] = pf[t * 2 + 0];
            *(uint4*)&sT[t][r1][c1] = pf[t * 2 + 1];
        }
        __syncthreads();

        if (ch < 15) {
            const int kb = (ch + 1) * 32;
            #pragma unroll
            for (int t = 0; t < 4; t++) {
                pf[t * 2 + 0] = *(const uint4*)(srcs[t] + (size_t)r0 * DIM + kb + c0);
                pf[t * 2 + 1] = *(const uint4*)(srcs[t] + (size_t)r1 * DIM + kb + c1);
            }
        }

        #pragma unroll
        for (int ks = 0; ks < 2; ks++) {
            const uint32_t ko = ks * 16 * 2;
            uint32_t ah[4][4], al[4][4], bh[4][2], bl[4][2];
            #pragma unroll
            for (int mi = 0; mi < 4; mi++) {
                uint32_t off = mi * 16 * SSTRIDE * 2 + ko;
                ldm_x4(ah[mi][0], ah[mi][1], ah[mi][2], ah[mi][3], sA[0] + off);
                ldm_x4(al[mi][0], al[mi][1], al[mi][2], al[mi][3], sA[1] + off);
            }
            #pragma unroll
            for (int nh = 0; nh < 2; nh++) {
                uint32_t off = nh * 16 * SSTRIDE * 2 + ko;
                ldm_x4(bh[nh*2][0], bh[nh*2][1], bh[nh*2+1][0], bh[nh*2+1][1], sB[0] + off);
                ldm_x4(bl[nh*2][0], bl[nh*2][1], bl[nh*2+1][0], bl[nh*2+1][1], sB[1] + off);
            }
            #pragma unroll
            for (int mi = 0; mi < 4; mi++)
                #pragma unroll
                for (int ni = 0; ni < 4; ni++) {
                    mma_16816(acc[mi][ni], ah[mi], bh[ni]);
                    mma_16816(acc[mi][ni], ah[mi], bl[ni]);
                    mma_16816(acc[mi][ni], al[mi], bh[ni]);
                }
        }
        __syncthreads();
    }

    const int qr = lane >> 2, qc = (lane & 3) * 2;
    #pragma unroll
    for (int ni = 0; ni < 4; ni++) {
        int col = bn * 128 + wn * 32 + ni * 8 + qc;
        float2 b = *(const float2*)(bias + col);
        #pragma unroll
        for (int mi = 0; mi < 4; mi++) {
            int row = bm * 128 + wm * 64 + mi * 16 + qr;
            float2 v0 = make_float2(acc[mi][ni][0] + b.x, acc[mi][ni][1] + b.y);
            float2 v1 = make_float2(acc[mi][ni][2] + b.x, acc[mi][ni][3] + b.y);
            *(float2*)(C + (size_t)row * DIM + col)       = v0;
            *(float2*)(C + (size_t)(row + 8) * DIM + col) = v1;
        }
    }
}

// ---------------- K2: fused node-major online-softmax attention ------------
// one warp per node, software-pipelined: edge p+1's loads issued before
// edge p's reduction so DRAM latency overlaps the shuffle/exp chain.
__global__ __launch_bounds__(256) void attn_kernel(
    const float* __restrict__ vals, float* __restrict__ out)
{
    int node = (blockIdx.x * 256 + threadIdx.x) >> 5;
    int lane = threadIdx.x & 31;

    int s0 = g_start[node], s1 = g_start[node + 1];

    const float* qp = g_q + (size_t)node * DIM;
    float4 q[4];
    #pragma unroll
    for (int j = 0; j < 4; j++) q[j] = *(const float4*)(qp + lane * 4 + j * 128);

    float m = -1e30f, d = 0.f;
    float4 acc[4];
    #pragma unroll
    for (int j = 0; j < 4; j++) acc[j] = make_float4(0.f, 0.f, 0.f, 0.f);

    float4 cur[4];
    if (s0 < s1) {
        const float* v = vals + (size_t)__ldg(&g_elist[s0]) * DIM;
        #pragma unroll
        for (int j = 0; j < 4; j++) cur[j] = ldcs4(v + lane * 4 + j * 128);
    }

    for (int p = s0; p < s1; p++) {
        float4 nxt[4];
        if (p + 1 < s1) {                                // prefetch next edge
            const float* v = vals + (size_t)__ldg(&g_elist[p + 1]) * DIM;
            #pragma unroll
            for (int j = 0; j < 4; j++) nxt[j] = ldcs4(v + lane * 4 + j * 128);
        }

        float s = 0.f;
        #pragma unroll
        for (int j = 0; j < 4; j++)
            s += cur[j].x * q[j].x + cur[j].y * q[j].y
               + cur[j].z * q[j].z + cur[j].w * q[j].w;
        #pragma unroll
        for (int o = 16; o; o >>= 1) s += __shfl_xor_sync(0xFFFFFFFFu, s, o);

        if (s > m) {                                     // warp-uniform rescale
            float r = expf(m - s);                       // exp(-inf)=0 first hit
            d *= r;
            #pragma unroll
            for (int j = 0; j < 4; j++) {
                acc[j].x *= r; acc[j].y *= r; acc[j].z *= r; acc[j].w *= r;
            }
            m = s;
        }
        float w = expf(s - m);
        d += w;
        #pragma unroll
        for (int j = 0; j < 4; j++) {
            acc[j].x += w * cur[j].x; acc[j].y += w * cur[j].y;
            acc[j].z += w * cur[j].z; acc[j].w += w * cur[j].w;
        }

        #pragma unroll
        for (int j = 0; j < 4; j++) cur[j] = nxt[j];
    }

    float inv = 1.0f / fmaxf(d, 1e-12f);
    float* op = out + (size_t)node * DIM;
    #pragma unroll
    for (int j = 0; j < 4; j++) {
        float4 o = make_float4(acc[j].x * inv, acc[j].y * inv,
                               acc[j].z * inv, acc[j].w * inv);
        *(float4*)(op + lane * 4 + j * 128) = o;
    }
}

// ---------------- launch ---------------------------------------------------
extern "C" void kernel_launch(void* const* d_in, const int* in_sizes, int n_in,
                              void* d_out, int out_size)
{
    const float* enc  = nullptr;
    const void*  c0   = nullptr;
    const void*  c1   = nullptr;
    const float* prev = nullptr;
    const float* Wq   = nullptr;
    const float* bq   = nullptr;
    int n131072 = 0;

    for (int i = 0; i < n_in; i++) {
        switch (in_sizes[i]) {
            case 67108864: enc  = (const float*)d_in[i]; break;
            case 4194304:  prev = (const float*)d_in[i]; break;
            case 262144:   Wq   = (const float*)d_in[i]; break;
            case 512:      bq   = (const float*)d_in[i]; break;
            case 131072:
                if (n131072++ == 0) c0 = d_in[i];
                else                c1 = d_in[i];
                break;
            default: break;
        }
    }

    float* out = (float*)d_out;
    float* q;
    cudaGetSymbolAddress((void**)&q, g_q);

    detect_kernel<<<1, 256>>>((const unsigned*)c0, (const unsigned*)c1);
    hist_kernel<<<N_EDGES / 256, 256>>>(c0, c1);
    scan_kernel<<<1, 1024>>>();
    scatter_kernel<<<N_EDGES / 256, 256>>>(c0, c1);

    conv_prev_kernel<<<(N_NODES * DIM / 4) / 1024, 256>>>((const float4*)prev);
    conv_wq_kernel<<<dim3(16, 16), 256>>>(Wq);

    dim3 ggrid(DIM / 128, N_NODES / 128);   // (4, 64)
    gemm_mma_kernel<<<ggrid, 256>>>(bq, q);

    attn_kernel<<<N_NODES / 8, 256>>>(enc, out);
}

// round 8
// speedup vs baseline: 1.7553x; 1.1112x over previous
#include <cuda_runtime.h>
#include <cuda_bf16.h>
#include <cstdint>
#include <cstddef>

#define DIM      512
#define N_NODES  8192
#define N_EDGES  131072   // 2048 paths * 64

// ---------------- scratch (device globals; no runtime allocation) ----------
__device__ float         g_q[N_NODES * DIM];      // projected queries, fp32
__device__ __nv_bfloat16 g_BhiT[DIM * DIM];       // Wq^T split hi [n][k]
__device__ __nv_bfloat16 g_BloT[DIM * DIM];       // Wq^T split lo
__device__ int           g_cnt[N_NODES];          // per-node live-edge counts
__device__ int           g_start[N_NODES + 1];    // CSR starts
__device__ int           g_cursor[N_NODES];       // scatter cursors
__device__ int           g_elist[N_EDGES];        // node-sorted live edge ids

struct Cfg { int idx_is_1; int mask_byte; };
__device__ Cfg g_cfg;

// ---------------- helpers ---------------------------------------------------
__device__ __forceinline__ uint32_t smem_u32(const void* p) {
    uint32_t a;
    asm("{ .reg .u64 t; cvta.to.shared.u64 t, %1; cvt.u32.u64 %0, t; }" : "=r"(a) : "l"(p));
    return a;
}
__device__ __forceinline__ void ldm_x4(uint32_t& r0, uint32_t& r1, uint32_t& r2,
                                       uint32_t& r3, uint32_t addr) {
    asm volatile("ldmatrix.sync.aligned.m8n8.x4.shared.b16 {%0,%1,%2,%3}, [%4];"
                 : "=r"(r0), "=r"(r1), "=r"(r2), "=r"(r3) : "r"(addr));
}
__device__ __forceinline__ void mma_16816(float* c, const uint32_t* a, const uint32_t* b) {
    asm volatile(
        "mma.sync.aligned.m16n8k16.row.col.f32.bf16.bf16.f32 "
        "{%0,%1,%2,%3}, {%4,%5,%6,%7}, {%8,%9}, {%0,%1,%2,%3};"
        : "+f"(c[0]), "+f"(c[1]), "+f"(c[2]), "+f"(c[3])
        : "r"(a[0]), "r"(a[1]), "r"(a[2]), "r"(a[3]), "r"(b[0]), "r"(b[1]));
}
__device__ __forceinline__ float4 ldcs4(const float* p) {
    float4 v;
    asm volatile("ld.global.cs.v4.f32 {%0,%1,%2,%3}, [%4];"
                 : "=f"(v.x), "=f"(v.y), "=f"(v.z), "=f"(v.w) : "l"(p));
    return v;
}

// ---------------- K-1: detect idx/mask binding + zero counts ---------------
__global__ __launch_bounds__(256) void detect_kernel(
    const unsigned* __restrict__ c0, const unsigned* __restrict__ c1)
{
    #pragma unroll
    for (int i = 0; i < 32; i++) g_cnt[threadIdx.x + i * 256] = 0;

    __shared__ unsigned sm[2], so[2];
    if (threadIdx.x < 2) { sm[threadIdx.x] = 0u; so[threadIdx.x] = 0u; }
    __syncthreads();
    unsigned m0 = 0, m1 = 0, o0 = 0, o1 = 0;
    for (int i = threadIdx.x; i < 32768; i += 256) {
        unsigned a = c0[i], b = c1[i];
        m0 = max(m0, a); m1 = max(m1, b);
        o0 |= a & 0xFEFEFEFEu; o1 |= b & 0xFEFEFEFEu;
    }
    atomicMax(&sm[0], m0); atomicMax(&sm[1], m1);
    atomicOr (&so[0], o0); atomicOr (&so[1], o1);
    __syncthreads();
    if (threadIdx.x == 0) {
        unsigned M0 = sm[0], M1 = sm[1];
        int idx_is_1;
        if      (M0 <= 1u)                   idx_is_1 = 1;
        else if (M1 <= 1u)                   idx_is_1 = 0;
        else if (M0 < 8192u && M1 >= 8192u)  idx_is_1 = 0;
        else if (M1 < 8192u && M0 >= 8192u)  idx_is_1 = 1;
        else                                 idx_is_1 = 1;
        unsigned Mm = idx_is_1 ? M0 : M1;
        unsigned Om = idx_is_1 ? so[0] : so[1];
        g_cfg.idx_is_1  = idx_is_1;
        g_cfg.mask_byte = (Mm > 1u && Om == 0u) ? 1 : 0;
    }
}
__device__ __forceinline__ bool edge_live(const void* mask, int e, int mask_byte) {
    return mask_byte ? (((const unsigned char*)mask)[e] != 0)
                     : (((const unsigned*)mask)[e] != 0u);
}

// ---------------- S1: histogram of live edges per node ----------------------
__global__ __launch_bounds__(256) void hist_kernel(
    const void* __restrict__ c0, const void* __restrict__ c1)
{
    const Cfg cfg = g_cfg;
    const int*  idx  = cfg.idx_is_1 ? (const int*)c1 : (const int*)c0;
    const void* mask = cfg.idx_is_1 ? c0 : c1;
    int e = blockIdx.x * 256 + threadIdx.x;
    if (edge_live(mask, e, cfg.mask_byte)) atomicAdd(&g_cnt[idx[e]], 1);
}

// ---------------- S2: exclusive scan over 8192 counts (shuffle-based) ------
__global__ __launch_bounds__(1024) void scan_kernel() {
    __shared__ int wsum[32];
    const int t = threadIdx.x, lane = t & 31, wid = t >> 5;
    const int base = t * 8;

    int loc[8], tot = 0;
    #pragma unroll
    for (int i = 0; i < 8; i++) { loc[i] = g_cnt[base + i]; tot += loc[i]; }

    int inc = tot;
    #pragma unroll
    for (int o = 1; o < 32; o <<= 1) {
        int v = __shfl_up_sync(0xFFFFFFFFu, inc, o);
        if (lane >= o) inc += v;
    }
    if (lane == 31) wsum[wid] = inc;
    __syncthreads();

    if (wid == 0) {
        int w = wsum[lane];
        #pragma unroll
        for (int o = 1; o < 32; o <<= 1) {
            int v = __shfl_up_sync(0xFFFFFFFFu, w, o);
            if (lane >= o) w += v;
        }
        wsum[lane] = w;
    }
    __syncthreads();

    int excl = (wid ? wsum[wid - 1] : 0) + (inc - tot);
    #pragma unroll
    for (int i = 0; i < 8; i++) {
        g_start[base + i]  = excl;
        g_cursor[base + i] = excl;
        excl += loc[i];
    }
    if (t == 1023) g_start[N_NODES] = excl;
}

// ---------------- S3: scatter live edges into node-sorted list -------------
__global__ __launch_bounds__(256) void scatter_kernel(
    const void* __restrict__ c0, const void* __restrict__ c1)
{
    const Cfg cfg = g_cfg;
    const int*  idx  = cfg.idx_is_1 ? (const int*)c1 : (const int*)c0;
    const void* mask = cfg.idx_is_1 ? c0 : c1;
    int e = blockIdx.x * 256 + threadIdx.x;
    if (edge_live(mask, e, cfg.mask_byte)) {
        int p = atomicAdd(&g_cursor[idx[e]], 1);
        g_elist[p] = e;
    }
}

// ---------------- C2: transpose+split Wq -> [n][k] bf16 hi/lo --------------
__global__ __launch_bounds__(256) void conv_wq_kernel(const float* __restrict__ Wq) {
    __shared__ float t[32][33];
    int n0 = blockIdx.x * 32, k0 = blockIdx.y * 32;
    #pragma unroll
    for (int i = 0; i < 4; i++) {
        int lin = threadIdx.x + i * 256;
        int r = lin >> 5, c = lin & 31;
        t[r][c] = Wq[(size_t)(k0 + r) * DIM + n0 + c];
    }
    __syncthreads();
    #pragma unroll
    for (int i = 0; i < 4; i++) {
        int lin = threadIdx.x + i * 256;
        int r = lin >> 5, c = lin & 31;
        float v = t[c][r];
        __nv_bfloat16 h = __float2bfloat16(v);
        __nv_bfloat16 l = __float2bfloat16(v - __bfloat162float(h));
        size_t o = (size_t)(n0 + r) * DIM + k0 + c;
        g_BhiT[o] = h; g_BloT[o] = l;
    }
}

// ---------------- K1: q = prev @ Wq + bq via mma.sync bf16-split -----------
// A is split hi/lo ON THE FLY from fp32 prev (no conv_prev pass, same bytes).
#define SSTRIDE 40   // padded bf16 row stride: 80 B -> conflict-free ldmatrix
__global__ __launch_bounds__(256) void gemm_mma_kernel(
    const float* __restrict__ Aprev,   // [8192, 512] fp32
    const float* __restrict__ bias, float* __restrict__ C)
{
    __shared__ __nv_bfloat16 sT[4][128][SSTRIDE];   // Ah, Al, Bh, Bl

    const int tid = threadIdx.x, wid = tid >> 5, lane = tid & 31;
    const int wm = wid & 1, wn = wid >> 1;
    const int bm = blockIdx.y, bn = blockIdx.x;

    const float* Asrc = Aprev + (size_t)bm * 128 * DIM;
    const __nv_bfloat16* Bh = g_BhiT + (size_t)bn * 128 * DIM;
    const __nv_bfloat16* Bl = g_BloT + (size_t)bn * 128 * DIM;

    float acc[4][4][4];
    #pragma unroll
    for (int i = 0; i < 4; i++)
        #pragma unroll
        for (int j = 0; j < 4; j++)
            #pragma unroll
            for (int k = 0; k < 4; k++) acc[i][j][k] = 0.f;

    const uint32_t a_row = lane & 15, a_c8 = (lane >> 4) << 3;
    const uint32_t b_n   = (lane & 7) + ((lane >> 4) << 3);
    const uint32_t b_k8  = ((lane >> 3) & 1) << 3;
    uint32_t sA[2], sB[2];
    sA[0] = smem_u32(&sT[0][wm * 64 + a_row][a_c8]);
    sA[1] = smem_u32(&sT[1][wm * 64 + a_row][a_c8]);
    sB[0] = smem_u32(&sT[2][wn * 32 + b_n][b_k8]);
    sB[1] = smem_u32(&sT[3][wn * 32 + b_n][b_k8]);

    // A fp32 tile: 128 rows x 32 cols = 1024 float4 -> 4 per thread
    int ar[4], ac[4];
    #pragma unroll
    for (int i = 0; i < 4; i++) {
        int l = tid + i * 256;
        ar[i] = l >> 3; ac[i] = (l & 7) * 4;
    }
    // B bf16 tiles: 128 rows x 32 cols = 512 uint4 per tile -> 2 per thread
    const int u0 = tid, u1 = tid + 256;
    const int br0 = u0 >> 2, bc0 = (u0 & 3) * 8;
    const int br1 = u1 >> 2, bc1 = (u1 & 3) * 8;

    float4 pa[4];
    uint4  pb[4];
    #pragma unroll
    for (int i = 0; i < 4; i++)
        pa[i] = *(const float4*)(Asrc + (size_t)ar[i] * DIM + ac[i]);
    pb[0] = *(const uint4*)(Bh + (size_t)br0 * DIM + bc0);
    pb[1] = *(const uint4*)(Bh + (size_t)br1 * DIM + bc1);
    pb[2] = *(const uint4*)(Bl + (size_t)br0 * DIM + bc0);
    pb[3] = *(const uint4*)(Bl + (size_t)br1 * DIM + bc1);

    for (int ch = 0; ch < 16; ch++) {
        // stage A with on-the-fly hi/lo split
        #pragma unroll
        for (int i = 0; i < 4; i++) {
            float4 v = pa[i];
            __nv_bfloat16 h0 = __float2bfloat16(v.x), h1 = __float2bfloat16(v.y);
            __nv_bfloat16 h2 = __float2bfloat16(v.z), h3 = __float2bfloat16(v.w);
            __nv_bfloat16 l0 = __float2bfloat16(v.x - __bfloat162float(h0));
            __nv_bfloat16 l1 = __float2bfloat16(v.y - __bfloat162float(h1));
            __nv_bfloat16 l2 = __float2bfloat16(v.z - __bfloat162float(h2));
            __nv_bfloat16 l3 = __float2bfloat16(v.w - __bfloat162float(h3));
            *(__nv_bfloat162*)&sT[0][ar[i]][ac[i]]     = __nv_bfloat162(h0, h1);
            *(__nv_bfloat162*)&sT[0][ar[i]][ac[i] + 2] = __nv_bfloat162(h2, h3);
            *(__nv_bfloat162*)&sT[1][ar[i]][ac[i]]     = __nv_bfloat162(l0, l1);
            *(__nv_bfloat162*)&sT[1][ar[i]][ac[i] + 2] = __nv_bfloat162(l2, l3);
        }
        *(uint4*)&sT[2][br0][bc0] = pb[0];
        *(uint4*)&sT[2][br1][bc1] = pb[1];
        *(uint4*)&sT[3][br0][bc0] = pb[2];
        *(uint4*)&sT[3][br1][bc1] = pb[3];
        __syncthreads();

        if (ch < 15) {
            const int kb = (ch + 1) * 32;
            #pragma unroll
            for (int i = 0; i < 4; i++)
                pa[i] = *(const float4*)(Asrc + (size_t)ar[i] * DIM + kb + ac[i]);
            pb[0] = *(const uint4*)(Bh + (size_t)br0 * DIM + kb + bc0);
            pb[1] = *(const uint4*)(Bh + (size_t)br1 * DIM + kb + bc1);
            pb[2] = *(const uint4*)(Bl + (size_t)br0 * DIM + kb + bc0);
            pb[3] = *(const uint4*)(Bl + (size_t)br1 * DIM + kb + bc1);
        }

        #pragma unroll
        for (int ks = 0; ks < 2; ks++) {
            const uint32_t ko = ks * 16 * 2;
            uint32_t ah[4][4], al[4][4], bh[4][2], bl[4][2];
            #pragma unroll
            for (int mi = 0; mi < 4; mi++) {
                uint32_t off = mi * 16 * SSTRIDE * 2 + ko;
                ldm_x4(ah[mi][0], ah[mi][1], ah[mi][2], ah[mi][3], sA[0] + off);
                ldm_x4(al[mi][0], al[mi][1], al[mi][2], al[mi][3], sA[1] + off);
            }
            #pragma unroll
            for (int nh = 0; nh < 2; nh++) {
                uint32_t off = nh * 16 * SSTRIDE * 2 + ko;
                ldm_x4(bh[nh*2][0], bh[nh*2][1], bh[nh*2+1][0], bh[nh*2+1][1], sB[0] + off);
                ldm_x4(bl[nh*2][0], bl[nh*2][1], bl[nh*2+1][0], bl[nh*2+1][1], sB[1] + off);
            }
            #pragma unroll
            for (int mi = 0; mi < 4; mi++)
                #pragma unroll
                for (int ni = 0; ni < 4; ni++) {
                    mma_16816(acc[mi][ni], ah[mi], bh[ni]);
                    mma_16816(acc[mi][ni], ah[mi], bl[ni]);
                    mma_16816(acc[mi][ni], al[mi], bh[ni]);
                }
        }
        __syncthreads();
    }

    const int qr = lane >> 2, qc = (lane & 3) * 2;
    #pragma unroll
    for (int ni = 0; ni < 4; ni++) {
        int col = bn * 128 + wn * 32 + ni * 8 + qc;
        float2 b = *(const float2*)(bias + col);
        #pragma unroll
        for (int mi = 0; mi < 4; mi++) {
            int row = bm * 128 + wm * 64 + mi * 16 + qr;
            float2 v0 = make_float2(acc[mi][ni][0] + b.x, acc[mi][ni][1] + b.y);
            float2 v1 = make_float2(acc[mi][ni][2] + b.x, acc[mi][ni][3] + b.y);
            *(float2*)(C + (size_t)row * DIM + col)       = v0;
            *(float2*)(C + (size_t)(row + 8) * DIM + col) = v1;
        }
    }
}

// ---------------- K2: fused node-major online-softmax attention ------------
// one warp per node; edges processed in PAIRS: two independent load+dot
// chains per iteration, one max/rescale per pair.
__global__ __launch_bounds__(256) void attn_kernel(
    const float* __restrict__ vals, float* __restrict__ out)
{
    int node = (blockIdx.x * 256 + threadIdx.x) >> 5;
    int lane = threadIdx.x & 31;

    int s0 = g_start[node], s1 = g_start[node + 1];

    const float* qp = g_q + (size_t)node * DIM;
    float4 q[4];
    #pragma unroll
    for (int j = 0; j < 4; j++) q[j] = *(const float4*)(qp + lane * 4 + j * 128);

    float m = -1e30f, d = 0.f;
    float4 acc[4];
    #pragma unroll
    for (int j = 0; j < 4; j++) acc[j] = make_float4(0.f, 0.f, 0.f, 0.f);

    for (int p = s0; p < s1; p += 2) {
        const bool has2 = (p + 1 < s1);
        const float* va = vals + (size_t)g_elist[p] * DIM;
        const float* vb = vals + (size_t)g_elist[has2 ? p + 1 : p] * DIM;

        float4 a[4], b[4];
        #pragma unroll
        for (int j = 0; j < 4; j++) {         // both edges' loads issued together
            a[j] = ldcs4(va + lane * 4 + j * 128);
            b[j] = ldcs4(vb + lane * 4 + j * 128);
        }

        float sa = 0.f, sb = 0.f;
        #pragma unroll
        for (int j = 0; j < 4; j++) {
            sa += a[j].x * q[j].x + a[j].y * q[j].y + a[j].z * q[j].z + a[j].w * q[j].w;
            sb += b[j].x * q[j].x + b[j].y * q[j].y + b[j].z * q[j].z + b[j].w * q[j].w;
        }
        #pragma unroll
        for (int o = 16; o; o >>= 1) {        // two interleaved reduce chains
            sa += __shfl_xor_sync(0xFFFFFFFFu, sa, o);
            sb += __shfl_xor_sync(0xFFFFFFFFu, sb, o);
        }
        if (!has2) sb = -1e30f;               // exp -> 0, mathematically absent

        float mx = fmaxf(m, fmaxf(sa, sb));   // warp-uniform
        float r  = expf(m - mx);              // first pair: exp(-inf)=0
        d *= r;
        float wa = expf(sa - mx), wb = expf(sb - mx);
        d += wa + wb;
        #pragma unroll
        for (int j = 0; j < 4; j++) {
            acc[j].x = acc[j].x * r + wa * a[j].x + wb * b[j].x;
            acc[j].y = acc[j].y * r + wa * a[j].y + wb * b[j].y;
            acc[j].z = acc[j].z * r + wa * a[j].z + wb * b[j].z;
            acc[j].w = acc[j].w * r + wa * a[j].w + wb * b[j].w;
        }
        m = mx;
    }

    float inv = 1.0f / fmaxf(d, 1e-12f);
    float* op = out + (size_t)node * DIM;
    #pragma unroll
    for (int j = 0; j < 4; j++) {
        float4 o = make_float4(acc[j].x * inv, acc[j].y * inv,
                               acc[j].z * inv, acc[j].w * inv);
        *(float4*)(op + lane * 4 + j * 128) = o;
    }
}

// ---------------- launch ---------------------------------------------------
extern "C" void kernel_launch(void* const* d_in, const int* in_sizes, int n_in,
                              void* d_out, int out_size)
{
    const float* enc  = nullptr;
    const void*  c0   = nullptr;
    const void*  c1   = nullptr;
    const float* prev = nullptr;
    const float* Wq   = nullptr;
    const float* bq   = nullptr;
    int n131072 = 0;

    for (int i = 0; i < n_in; i++) {
        switch (in_sizes[i]) {
            case 67108864: enc  = (const float*)d_in[i]; break;
            case 4194304:  prev = (const float*)d_in[i]; break;
            case 262144:   Wq   = (const float*)d_in[i]; break;
            case 512:      bq   = (const float*)d_in[i]; break;
            case 131072:
                if (n131072++ == 0) c0 = d_in[i];
                else                c1 = d_in[i];
                break;
            default: break;
        }
    }

    float* out = (float*)d_out;
    float* q;
    cudaGetSymbolAddress((void**)&q, g_q);

    detect_kernel<<<1, 256>>>((const unsigned*)c0, (const unsigned*)c1);
    hist_kernel<<<N_EDGES / 256, 256>>>(c0, c1);
    scan_kernel<<<1, 1024>>>();
    scatter_kernel<<<N_EDGES / 256, 256>>>(c0, c1);

    conv_wq_kernel<<<dim3(16, 16), 256>>>(Wq);

    dim3 ggrid(DIM / 128, N_NODES / 128);   // (4, 64)
    gemm_mma_kernel<<<ggrid, 256>>>(prev, bq, q);

    attn_kernel<<<N_NODES / 8, 256>>>(enc, out);
}

// round 9
// speedup vs baseline: 1.9164x; 1.0918x over previous
#include <cuda_runtime.h>
#include <cuda_bf16.h>
#include <cstdint>
#include <cstddef>

#define DIM      512
#define N_NODES  8192
#define N_EDGES  131072   // 2048 paths * 64
#define CAP      128      // per-node edge-bucket capacity (λ≈8, 16x headroom)

// ---------------- scratch (device globals; no runtime allocation) ----------
__device__ float         g_q[N_NODES * DIM];      // projected queries, fp32
__device__ __nv_bfloat16 g_BhiT[DIM * DIM];       // Wq^T split hi [n][k]
__device__ __nv_bfloat16 g_BloT[DIM * DIM];       // Wq^T split lo
__device__ int           g_cnt[N_NODES];          // per-node live-edge counts
__device__ int           g_elist[N_NODES * CAP];  // per-node edge buckets

struct Cfg { int idx_is_1; int mask_byte; };
__device__ Cfg g_cfg;

// ---------------- helpers ---------------------------------------------------
__device__ __forceinline__ uint32_t smem_u32(const void* p) {
    uint32_t a;
    asm("{ .reg .u64 t; cvta.to.shared.u64 t, %1; cvt.u32.u64 %0, t; }" : "=r"(a) : "l"(p));
    return a;
}
__device__ __forceinline__ void ldm_x4(uint32_t& r0, uint32_t& r1, uint32_t& r2,
                                       uint32_t& r3, uint32_t addr) {
    asm volatile("ldmatrix.sync.aligned.m8n8.x4.shared.b16 {%0,%1,%2,%3}, [%4];"
                 : "=r"(r0), "=r"(r1), "=r"(r2), "=r"(r3) : "r"(addr));
}
__device__ __forceinline__ void mma_16816(float* c, const uint32_t* a, const uint32_t* b) {
    asm volatile(
        "mma.sync.aligned.m16n8k16.row.col.f32.bf16.bf16.f32 "
        "{%0,%1,%2,%3}, {%4,%5,%6,%7}, {%8,%9}, {%0,%1,%2,%3};"
        : "+f"(c[0]), "+f"(c[1]), "+f"(c[2]), "+f"(c[3])
        : "r"(a[0]), "r"(a[1]), "r"(a[2]), "r"(a[3]), "r"(b[0]), "r"(b[1]));
}
__device__ __forceinline__ float4 ldcs4(const float* p) {
    float4 v;
    asm volatile("ld.global.cs.v4.f32 {%0,%1,%2,%3}, [%4];"
                 : "=f"(v.x), "=f"(v.y), "=f"(v.z), "=f"(v.w) : "l"(p));
    return v;
}

// ---------------- K0: detect idx/mask binding + zero counts ----------------
__global__ __launch_bounds__(256) void detect_kernel(
    const unsigned* __restrict__ c0, const unsigned* __restrict__ c1)
{
    #pragma unroll
    for (int i = 0; i < 32; i++) g_cnt[threadIdx.x + i * 256] = 0;

    __shared__ unsigned sm[2], so[2];
    if (threadIdx.x < 2) { sm[threadIdx.x] = 0u; so[threadIdx.x] = 0u; }
    __syncthreads();
    unsigned m0 = 0, m1 = 0, o0 = 0, o1 = 0;
    for (int i = threadIdx.x; i < 32768; i += 256) {
        unsigned a = c0[i], b = c1[i];
        m0 = max(m0, a); m1 = max(m1, b);
        o0 |= a & 0xFEFEFEFEu; o1 |= b & 0xFEFEFEFEu;
    }
    atomicMax(&sm[0], m0); atomicMax(&sm[1], m1);
    atomicOr (&so[0], o0); atomicOr (&so[1], o1);
    __syncthreads();
    if (threadIdx.x == 0) {
        unsigned M0 = sm[0], M1 = sm[1];
        int idx_is_1;
        if      (M0 <= 1u)                   idx_is_1 = 1;
        else if (M1 <= 1u)                   idx_is_1 = 0;
        else if (M0 < 8192u && M1 >= 8192u)  idx_is_1 = 0;
        else if (M1 < 8192u && M0 >= 8192u)  idx_is_1 = 1;
        else                                 idx_is_1 = 1;
        unsigned Mm = idx_is_1 ? M0 : M1;
        unsigned Om = idx_is_1 ? so[0] : so[1];
        g_cfg.idx_is_1  = idx_is_1;
        g_cfg.mask_byte = (Mm > 1u && Om == 0u) ? 1 : 0;
    }
}
__device__ __forceinline__ bool edge_live(const void* mask, int e, int mask_byte) {
    return mask_byte ? (((const unsigned char*)mask)[e] != 0)
                     : (((const unsigned*)mask)[e] != 0u);
}

// ---------------- K1: build per-node edge buckets (single pass) ------------
__global__ __launch_bounds__(256) void build_kernel(
    const void* __restrict__ c0, const void* __restrict__ c1)
{
    const Cfg cfg = g_cfg;
    const int*  idx  = cfg.idx_is_1 ? (const int*)c1 : (const int*)c0;
    const void* mask = cfg.idx_is_1 ? c0 : c1;
    int e = blockIdx.x * 256 + threadIdx.x;
    if (edge_live(mask, e, cfg.mask_byte)) {
        int node = idx[e];
        int pos  = atomicAdd(&g_cnt[node], 1);
        if (pos < CAP) g_elist[node * CAP + pos] = e;
    }
}

// ---------------- K2: transpose+split Wq -> [n][k] bf16 hi/lo --------------
__global__ __launch_bounds__(256) void conv_wq_kernel(const float* __restrict__ Wq) {
    __shared__ float t[32][33];
    int n0 = blockIdx.x * 32, k0 = blockIdx.y * 32;
    #pragma unroll
    for (int i = 0; i < 4; i++) {
        int lin = threadIdx.x + i * 256;
        int r = lin >> 5, c = lin & 31;
        t[r][c] = Wq[(size_t)(k0 + r) * DIM + n0 + c];
    }
    __syncthreads();
    #pragma unroll
    for (int i = 0; i < 4; i++) {
        int lin = threadIdx.x + i * 256;
        int r = lin >> 5, c = lin & 31;
        float v = t[c][r];
        __nv_bfloat16 h = __float2bfloat16(v);
        __nv_bfloat16 l = __float2bfloat16(v - __bfloat162float(h));
        size_t o = (size_t)(n0 + r) * DIM + k0 + c;
        g_BhiT[o] = h; g_BloT[o] = l;
    }
}

// ---------------- K3: q = prev @ Wq + bq via mma.sync bf16-split -----------
// A is split hi/lo ON THE FLY from fp32 prev.
#define SSTRIDE 40   // padded bf16 row stride: 80 B -> conflict-free ldmatrix
__global__ __launch_bounds__(256) void gemm_mma_kernel(
    const float* __restrict__ Aprev,   // [8192, 512] fp32
    const float* __restrict__ bias, float* __restrict__ C)
{
    __shared__ __nv_bfloat16 sT[4][128][SSTRIDE];   // Ah, Al, Bh, Bl

    const int tid = threadIdx.x, wid = tid >> 5, lane = tid & 31;
    const int wm = wid & 1, wn = wid >> 1;
    const int bm = blockIdx.y, bn = blockIdx.x;

    const float* Asrc = Aprev + (size_t)bm * 128 * DIM;
    const __nv_bfloat16* Bh = g_BhiT + (size_t)bn * 128 * DIM;
    const __nv_bfloat16* Bl = g_BloT + (size_t)bn * 128 * DIM;

    float acc[4][4][4];
    #pragma unroll
    for (int i = 0; i < 4; i++)
        #pragma unroll
        for (int j = 0; j < 4; j++)
            #pragma unroll
            for (int k = 0; k < 4; k++) acc[i][j][k] = 0.f;

    const uint32_t a_row = lane & 15, a_c8 = (lane >> 4) << 3;
    const uint32_t b_n   = (lane & 7) + ((lane >> 4) << 3);
    const uint32_t b_k8  = ((lane >> 3) & 1) << 3;
    uint32_t sA[2], sB[2];
    sA[0] = smem_u32(&sT[0][wm * 64 + a_row][a_c8]);
    sA[1] = smem_u32(&sT[1][wm * 64 + a_row][a_c8]);
    sB[0] = smem_u32(&sT[2][wn * 32 + b_n][b_k8]);
    sB[1] = smem_u32(&sT[3][wn * 32 + b_n][b_k8]);

    int ar[4], ac[4];
    #pragma unroll
    for (int i = 0; i < 4; i++) {
        int l = tid + i * 256;
        ar[i] = l >> 3; ac[i] = (l & 7) * 4;
    }
    const int u0 = tid, u1 = tid + 256;
    const int br0 = u0 >> 2, bc0 = (u0 & 3) * 8;
    const int br1 = u1 >> 2, bc1 = (u1 & 3) * 8;

    float4 pa[4];
    uint4  pb[4];
    #pragma unroll
    for (int i = 0; i < 4; i++)
        pa[i] = *(const float4*)(Asrc + (size_t)ar[i] * DIM + ac[i]);
    pb[0] = *(const uint4*)(Bh + (size_t)br0 * DIM + bc0);
    pb[1] = *(const uint4*)(Bh + (size_t)br1 * DIM + bc1);
    pb[2] = *(const uint4*)(Bl + (size_t)br0 * DIM + bc0);
    pb[3] = *(const uint4*)(Bl + (size_t)br1 * DIM + bc1);

    for (int ch = 0; ch < 16; ch++) {
        #pragma unroll
        for (int i = 0; i < 4; i++) {
            float4 v = pa[i];
            __nv_bfloat16 h0 = __float2bfloat16(v.x), h1 = __float2bfloat16(v.y);
            __nv_bfloat16 h2 = __float2bfloat16(v.z), h3 = __float2bfloat16(v.w);
            __nv_bfloat16 l0 = __float2bfloat16(v.x - __bfloat162float(h0));
            __nv_bfloat16 l1 = __float2bfloat16(v.y - __bfloat162float(h1));
            __nv_bfloat16 l2 = __float2bfloat16(v.z - __bfloat162float(h2));
            __nv_bfloat16 l3 = __float2bfloat16(v.w - __bfloat162float(h3));
            *(__nv_bfloat162*)&sT[0][ar[i]][ac[i]]     = __nv_bfloat162(h0, h1);
            *(__nv_bfloat162*)&sT[0][ar[i]][ac[i] + 2] = __nv_bfloat162(h2, h3);
            *(__nv_bfloat162*)&sT[1][ar[i]][ac[i]]     = __nv_bfloat162(l0, l1);
            *(__nv_bfloat162*)&sT[1][ar[i]][ac[i] + 2] = __nv_bfloat162(l2, l3);
        }
        *(uint4*)&sT[2][br0][bc0] = pb[0];
        *(uint4*)&sT[2][br1][bc1] = pb[1];
        *(uint4*)&sT[3][br0][bc0] = pb[2];
        *(uint4*)&sT[3][br1][bc1] = pb[3];
        __syncthreads();

        if (ch < 15) {
            const int kb = (ch + 1) * 32;
            #pragma unroll
            for (int i = 0; i < 4; i++)
                pa[i] = *(const float4*)(Asrc + (size_t)ar[i] * DIM + kb + ac[i]);
            pb[0] = *(const uint4*)(Bh + (size_t)br0 * DIM + kb + bc0);
            pb[1] = *(const uint4*)(Bh + (size_t)br1 * DIM + kb + bc1);
            pb[2] = *(const uint4*)(Bl + (size_t)br0 * DIM + kb + bc0);
            pb[3] = *(const uint4*)(Bl + (size_t)br1 * DIM + kb + bc1);
        }

        #pragma unroll
        for (int ks = 0; ks < 2; ks++) {
            const uint32_t ko = ks * 16 * 2;
            uint32_t ah[4][4], al[4][4], bh[4][2], bl[4][2];
            #pragma unroll
            for (int mi = 0; mi < 4; mi++) {
                uint32_t off = mi * 16 * SSTRIDE * 2 + ko;
                ldm_x4(ah[mi][0], ah[mi][1], ah[mi][2], ah[mi][3], sA[0] + off);
                ldm_x4(al[mi][0], al[mi][1], al[mi][2], al[mi][3], sA[1] + off);
            }
            #pragma unroll
            for (int nh = 0; nh < 2; nh++) {
                uint32_t off = nh * 16 * SSTRIDE * 2 + ko;
                ldm_x4(bh[nh*2][0], bh[nh*2][1], bh[nh*2+1][0], bh[nh*2+1][1], sB[0] + off);
                ldm_x4(bl[nh*2][0], bl[nh*2][1], bl[nh*2+1][0], bl[nh*2+1][1], sB[1] + off);
            }
            #pragma unroll
            for (int mi = 0; mi < 4; mi++)
                #pragma unroll
                for (int ni = 0; ni < 4; ni++) {
                    mma_16816(acc[mi][ni], ah[mi], bh[ni]);
                    mma_16816(acc[mi][ni], ah[mi], bl[ni]);
                    mma_16816(acc[mi][ni], al[mi], bh[ni]);
                }
        }
        __syncthreads();
    }

    const int qr = lane >> 2, qc = (lane & 3) * 2;
    #pragma unroll
    for (int ni = 0; ni < 4; ni++) {
        int col = bn * 128 + wn * 32 + ni * 8 + qc;
        float2 b = *(const float2*)(bias + col);
        #pragma unroll
        for (int mi = 0; mi < 4; mi++) {
            int row = bm * 128 + wm * 64 + mi * 16 + qr;
            float2 v0 = make_float2(acc[mi][ni][0] + b.x, acc[mi][ni][1] + b.y);
            float2 v1 = make_float2(acc[mi][ni][2] + b.x, acc[mi][ni][3] + b.y);
            *(float2*)(C + (size_t)row * DIM + col)       = v0;
            *(float2*)(C + (size_t)(row + 8) * DIM + col) = v1;
        }
    }
}

// ---------------- K4: fused node-major online-softmax attention ------------
// one warp per node; edges in pairs (two independent load+dot chains).
__global__ __launch_bounds__(256) void attn_kernel(
    const float* __restrict__ vals, float* __restrict__ out)
{
    int node = (blockIdx.x * 256 + threadIdx.x) >> 5;
    int lane = threadIdx.x & 31;

    int cnt = min(g_cnt[node], CAP);
    const int* el = g_elist + node * CAP;

    const float* qp = g_q + (size_t)node * DIM;
    float4 q[4];
    #pragma unroll
    for (int j = 0; j < 4; j++) q[j] = *(const float4*)(qp + lane * 4 + j * 128);

    float m = -1e30f, d = 0.f;
    float4 acc[4];
    #pragma unroll
    for (int j = 0; j < 4; j++) acc[j] = make_float4(0.f, 0.f, 0.f, 0.f);

    for (int p = 0; p < cnt; p += 2) {
        const bool has2 = (p + 1 < cnt);
        const float* va = vals + (size_t)el[p] * DIM;
        const float* vb = vals + (size_t)el[has2 ? p + 1 : p] * DIM;

        float4 a[4], b[4];
        #pragma unroll
        for (int j = 0; j < 4; j++) {
            a[j] = ldcs4(va + lane * 4 + j * 128);
            b[j] = ldcs4(vb + lane * 4 + j * 128);
        }

        float sa = 0.f, sb = 0.f;
        #pragma unroll
        for (int j = 0; j < 4; j++) {
            sa += a[j].x * q[j].x + a[j].y * q[j].y + a[j].z * q[j].z + a[j].w * q[j].w;
            sb += b[j].x * q[j].x + b[j].y * q[j].y + b[j].z * q[j].z + b[j].w * q[j].w;
        }
        #pragma unroll
        for (int o = 16; o; o >>= 1) {
            sa += __shfl_xor_sync(0xFFFFFFFFu, sa, o);
            sb += __shfl_xor_sync(0xFFFFFFFFu, sb, o);
        }
        if (!has2) sb = -1e30f;

        float mx = fmaxf(m, fmaxf(sa, sb));
        float r  = expf(m - mx);
        d *= r;
        float wa = expf(sa - mx), wb = expf(sb - mx);
        d += wa + wb;
        #pragma unroll
        for (int j = 0; j < 4; j++) {
            acc[j].x = acc[j].x * r + wa * a[j].x + wb * b[j].x;
            acc[j].y = acc[j].y * r + wa * a[j].y + wb * b[j].y;
            acc[j].z = acc[j].z * r + wa * a[j].z + wb * b[j].z;
            acc[j].w = acc[j].w * r + wa * a[j].w + wb * b[j].w;
        }
        m = mx;
    }

    float inv = 1.0f / fmaxf(d, 1e-12f);
    float* op = out + (size_t)node * DIM;
    #pragma unroll
    for (int j = 0; j < 4; j++) {
        float4 o = make_float4(acc[j].x * inv, acc[j].y * inv,
                               acc[j].z * inv, acc[j].w * inv);
        *(float4*)(op + lane * 4 + j * 128) = o;
    }
}

// ---------------- launch ---------------------------------------------------
extern "C" void kernel_launch(void* const* d_in, const int* in_sizes, int n_in,
                              void* d_out, int out_size)
{
    const float* enc  = nullptr;
    const void*  c0   = nullptr;
    const void*  c1   = nullptr;
    const float* prev = nullptr;
    const float* Wq   = nullptr;
    const float* bq   = nullptr;
    int n131072 = 0;

    for (int i = 0; i < n_in; i++) {
        switch (in_sizes[i]) {
            case 67108864: enc  = (const float*)d_in[i]; break;
            case 4194304:  prev = (const float*)d_in[i]; break;
            case 262144:   Wq   = (const float*)d_in[i]; break;
            case 512:      bq   = (const float*)d_in[i]; break;
            case 131072:
                if (n131072++ == 0) c0 = d_in[i];
                else                c1 = d_in[i];
                break;
            default: break;
        }
    }

    float* out = (float*)d_out;
    float* q;
    cudaGetSymbolAddress((void**)&q, g_q);

    detect_kernel<<<1, 256>>>((const unsigned*)c0, (const unsigned*)c1);   // 0
    build_kernel<<<N_EDGES / 256, 256>>>(c0, c1);                           // 1
    conv_wq_kernel<<<dim3(16, 16), 256>>>(Wq);                              // 2

    dim3 ggrid(DIM / 128, N_NODES / 128);   // (4, 64)
    gemm_mma_kernel<<<ggrid, 256>>>(prev, bq, q);                           // 3 (profiled)

    attn_kernel<<<N_NODES / 8, 256>>>(enc, out);                            // 4
}

// round 10
// speedup vs baseline: 1.9251x; 1.0046x over previous
#include <cuda_runtime.h>
#include <cuda_bf16.h>
#include <cstdint>
#include <cstddef>

#define DIM      512
#define N_NODES  8192
#define N_EDGES  131072   // 2048 paths * 64
#define CAP      128      // per-node edge-bucket capacity (λ≈8, 16x headroom)

// GEMM smem geometry
#define SSTRIDE  40                    // padded bf16 row stride (80 B)
#define TILE_B   (128 * SSTRIDE * 2)   // 10240 B per tile
#define BUF_B    (4 * TILE_B)          // Ah, Al, Bh, Bl = 40960 B
#define GSMEM    (2 * BUF_B)           // double buffered = 81920 B

// ---------------- scratch (device globals; no runtime allocation) ----------
__device__ float         g_q[N_NODES * DIM];      // projected queries, fp32
__device__ __nv_bfloat16 g_BhiT[DIM * DIM];       // Wq^T split hi [n][k]
__device__ __nv_bfloat16 g_BloT[DIM * DIM];       // Wq^T split lo
__device__ int           g_cnt[N_NODES];          // per-node live-edge counts
__device__ int           g_elist[N_NODES * CAP];  // per-node edge buckets

struct Cfg { int idx_is_1; int mask_byte; };
__device__ Cfg g_cfg;

// ---------------- helpers ---------------------------------------------------
__device__ __forceinline__ uint32_t smem_u32(const void* p) {
    uint32_t a;
    asm("{ .reg .u64 t; cvta.to.shared.u64 t, %1; cvt.u32.u64 %0, t; }" : "=r"(a) : "l"(p));
    return a;
}
__device__ __forceinline__ void ldm_x4(uint32_t& r0, uint32_t& r1, uint32_t& r2,
                                       uint32_t& r3, uint32_t addr) {
    asm volatile("ldmatrix.sync.aligned.m8n8.x4.shared.b16 {%0,%1,%2,%3}, [%4];"
                 : "=r"(r0), "=r"(r1), "=r"(r2), "=r"(r3) : "r"(addr));
}
__device__ __forceinline__ void mma_16816(float* c, const uint32_t* a, const uint32_t* b) {
    asm volatile(
        "mma.sync.aligned.m16n8k16.row.col.f32.bf16.bf16.f32 "
        "{%0,%1,%2,%3}, {%4,%5,%6,%7}, {%8,%9}, {%0,%1,%2,%3};"
        : "+f"(c[0]), "+f"(c[1]), "+f"(c[2]), "+f"(c[3])
        : "r"(a[0]), "r"(a[1]), "r"(a[2]), "r"(a[3]), "r"(b[0]), "r"(b[1]));
}
__device__ __forceinline__ float4 ldcs4(const float* p) {
    float4 v;
    asm volatile("ld.global.cs.v4.f32 {%0,%1,%2,%3}, [%4];"
                 : "=f"(v.x), "=f"(v.y), "=f"(v.z), "=f"(v.w) : "l"(p));
    return v;
}

// ---------------- K0: detect idx/mask binding + zero counts ----------------
__global__ __launch_bounds__(256) void detect_kernel(
    const unsigned* __restrict__ c0, const unsigned* __restrict__ c1)
{
    #pragma unroll
    for (int i = 0; i < 32; i++) g_cnt[threadIdx.x + i * 256] = 0;

    __shared__ unsigned sm[2], so[2];
    if (threadIdx.x < 2) { sm[threadIdx.x] = 0u; so[threadIdx.x] = 0u; }
    __syncthreads();
    unsigned m0 = 0, m1 = 0, o0 = 0, o1 = 0;
    for (int i = threadIdx.x; i < 32768; i += 256) {
        unsigned a = c0[i], b = c1[i];
        m0 = max(m0, a); m1 = max(m1, b);
        o0 |= a & 0xFEFEFEFEu; o1 |= b & 0xFEFEFEFEu;
    }
    atomicMax(&sm[0], m0); atomicMax(&sm[1], m1);
    atomicOr (&so[0], o0); atomicOr (&so[1], o1);
    __syncthreads();
    if (threadIdx.x == 0) {
        unsigned M0 = sm[0], M1 = sm[1];
        int idx_is_1;
        if      (M0 <= 1u)                   idx_is_1 = 1;
        else if (M1 <= 1u)                   idx_is_1 = 0;
        else if (M0 < 8192u && M1 >= 8192u)  idx_is_1 = 0;
        else if (M1 < 8192u && M0 >= 8192u)  idx_is_1 = 1;
        else                                 idx_is_1 = 1;
        unsigned Mm = idx_is_1 ? M0 : M1;
        unsigned Om = idx_is_1 ? so[0] : so[1];
        g_cfg.idx_is_1  = idx_is_1;
        g_cfg.mask_byte = (Mm > 1u && Om == 0u) ? 1 : 0;
    }
}
__device__ __forceinline__ bool edge_live(const void* mask, int e, int mask_byte) {
    return mask_byte ? (((const unsigned char*)mask)[e] != 0)
                     : (((const unsigned*)mask)[e] != 0u);
}

// ---------------- K1: build per-node edge buckets (single pass) ------------
__global__ __launch_bounds__(256) void build_kernel(
    const void* __restrict__ c0, const void* __restrict__ c1)
{
    const Cfg cfg = g_cfg;
    const int*  idx  = cfg.idx_is_1 ? (const int*)c1 : (const int*)c0;
    const void* mask = cfg.idx_is_1 ? c0 : c1;
    int e = blockIdx.x * 256 + threadIdx.x;
    if (edge_live(mask, e, cfg.mask_byte)) {
        int node = idx[e];
        int pos  = atomicAdd(&g_cnt[node], 1);
        if (pos < CAP) g_elist[node * CAP + pos] = e;
    }
}

// ---------------- K2: transpose+split Wq -> [n][k] bf16 hi/lo --------------
__global__ __launch_bounds__(256) void conv_wq_kernel(const float* __restrict__ Wq) {
    __shared__ float t[32][33];
    int n0 = blockIdx.x * 32, k0 = blockIdx.y * 32;
    #pragma unroll
    for (int i = 0; i < 4; i++) {
        int lin = threadIdx.x + i * 256;
        int r = lin >> 5, c = lin & 31;
        t[r][c] = Wq[(size_t)(k0 + r) * DIM + n0 + c];
    }
    __syncthreads();
    #pragma unroll
    for (int i = 0; i < 4; i++) {
        int lin = threadIdx.x + i * 256;
        int r = lin >> 5, c = lin & 31;
        float v = t[c][r];
        __nv_bfloat16 h = __float2bfloat16(v);
        __nv_bfloat16 l = __float2bfloat16(v - __bfloat162float(h));
        size_t o = (size_t)(n0 + r) * DIM + k0 + c;
        g_BhiT[o] = h; g_BloT[o] = l;
    }
}

// ---------------- K3: q = prev @ Wq + bq (mma.sync, double-buffered) -------
// A split hi/lo on the fly from fp32 prev. One __syncthreads per K-chunk:
//   store regs -> buf[ch&1]; sync; issue loads(ch+1); MMA from buf[ch&1].
// Stores at ch+2 are separated from ch's ldmatrix by the ch+1 barrier.
__global__ __launch_bounds__(256) void gemm_mma_kernel(
    const float* __restrict__ Aprev,   // [8192, 512] fp32
    const float* __restrict__ bias, float* __restrict__ C)
{
    extern __shared__ char dsm[];

    const int tid = threadIdx.x, wid = tid >> 5, lane = tid & 31;
    const int wm = wid & 1, wn = wid >> 1;
    const int bm = blockIdx.y, bn = blockIdx.x;

    const float* Asrc = Aprev + (size_t)bm * 128 * DIM;
    const __nv_bfloat16* Bh = g_BhiT + (size_t)bn * 128 * DIM;
    const __nv_bfloat16* Bl = g_BloT + (size_t)bn * 128 * DIM;

    float acc[4][4][4];
    #pragma unroll
    for (int i = 0; i < 4; i++)
        #pragma unroll
        for (int j = 0; j < 4; j++)
            #pragma unroll
            for (int k = 0; k < 4; k++) acc[i][j][k] = 0.f;

    // per-lane ldmatrix byte offsets WITHIN one buffer
    const uint32_t a_row = lane & 15, a_c8 = (lane >> 4) << 3;
    const uint32_t b_n   = (lane & 7) + ((lane >> 4) << 3);
    const uint32_t b_k8  = ((lane >> 3) & 1) << 3;
    const uint32_t sbase = smem_u32(dsm);
    const uint32_t offA0 = 0 * TILE_B + (wm * 64 + a_row) * (SSTRIDE * 2) + a_c8 * 2;
    const uint32_t offA1 = 1 * TILE_B + (wm * 64 + a_row) * (SSTRIDE * 2) + a_c8 * 2;
    const uint32_t offB0 = 2 * TILE_B + (wn * 32 + b_n) * (SSTRIDE * 2) + b_k8 * 2;
    const uint32_t offB1 = 3 * TILE_B + (wn * 32 + b_n) * (SSTRIDE * 2) + b_k8 * 2;

    // staging maps
    int ar[4], ac[4];
    #pragma unroll
    for (int i = 0; i < 4; i++) {
        int l = tid + i * 256;
        ar[i] = l >> 3; ac[i] = (l & 7) * 4;
    }
    const int u0 = tid, u1 = tid + 256;
    const int br0 = u0 >> 2, bc0 = (u0 & 3) * 8;
    const int br1 = u1 >> 2, bc1 = (u1 & 3) * 8;

    float4 pa[4];
    uint4  pb[4];
    #pragma unroll
    for (int i = 0; i < 4; i++)
        pa[i] = *(const float4*)(Asrc + (size_t)ar[i] * DIM + ac[i]);
    pb[0] = *(const uint4*)(Bh + (size_t)br0 * DIM + bc0);
    pb[1] = *(const uint4*)(Bh + (size_t)br1 * DIM + bc1);
    pb[2] = *(const uint4*)(Bl + (size_t)br0 * DIM + bc0);
    pb[3] = *(const uint4*)(Bl + (size_t)br1 * DIM + bc1);

    for (int ch = 0; ch < 16; ch++) {
        char* buf = dsm + (ch & 1) * BUF_B;
        // stage A (split) and B tiles into this chunk's buffer
        #pragma unroll
        for (int i = 0; i < 4; i++) {
            float4 v = pa[i];
            __nv_bfloat16 h0 = __float2bfloat16(v.x), h1 = __float2bfloat16(v.y);
            __nv_bfloat16 h2 = __float2bfloat16(v.z), h3 = __float2bfloat16(v.w);
            __nv_bfloat16 l0 = __float2bfloat16(v.x - __bfloat162float(h0));
            __nv_bfloat16 l1 = __float2bfloat16(v.y - __bfloat162float(h1));
            __nv_bfloat16 l2 = __float2bfloat16(v.z - __bfloat162float(h2));
            __nv_bfloat16 l3 = __float2bfloat16(v.w - __bfloat162float(h3));
            uint32_t byo = ar[i] * (SSTRIDE * 2) + ac[i] * 2;
            *(__nv_bfloat162*)(buf + 0 * TILE_B + byo)     = __nv_bfloat162(h0, h1);
            *(__nv_bfloat162*)(buf + 0 * TILE_B + byo + 4) = __nv_bfloat162(h2, h3);
            *(__nv_bfloat162*)(buf + 1 * TILE_B + byo)     = __nv_bfloat162(l0, l1);
            *(__nv_bfloat162*)(buf + 1 * TILE_B + byo + 4) = __nv_bfloat162(l2, l3);
        }
        *(uint4*)(buf + 2 * TILE_B + br0 * (SSTRIDE * 2) + bc0 * 2) = pb[0];
        *(uint4*)(buf + 2 * TILE_B + br1 * (SSTRIDE * 2) + bc1 * 2) = pb[1];
        *(uint4*)(buf + 3 * TILE_B + br0 * (SSTRIDE * 2) + bc0 * 2) = pb[2];
        *(uint4*)(buf + 3 * TILE_B + br1 * (SSTRIDE * 2) + bc1 * 2) = pb[3];
        __syncthreads();

        if (ch < 15) {          // issue next chunk's global loads; they overlap MMAs
            const int kb = (ch + 1) * 32;
            #pragma unroll
            for (int i = 0; i < 4; i++)
                pa[i] = *(const float4*)(Asrc + (size_t)ar[i] * DIM + kb + ac[i]);
            pb[0] = *(const uint4*)(Bh + (size_t)br0 * DIM + kb + bc0);
            pb[1] = *(const uint4*)(Bh + (size_t)br1 * DIM + kb + bc1);
            pb[2] = *(const uint4*)(Bl + (size_t)br0 * DIM + kb + bc0);
            pb[3] = *(const uint4*)(Bl + (size_t)br1 * DIM + kb + bc1);
        }

        const uint32_t bb = sbase + (ch & 1) * BUF_B;
        #pragma unroll
        for (int ks = 0; ks < 2; ks++) {
            const uint32_t ko = ks * 16 * 2;
            uint32_t ah[4][4], al[4][4], bh[4][2], bl[4][2];
            #pragma unroll
            for (int mi = 0; mi < 4; mi++) {
                uint32_t off = mi * 16 * SSTRIDE * 2 + ko;
                ldm_x4(ah[mi][0], ah[mi][1], ah[mi][2], ah[mi][3], bb + offA0 + off);
                ldm_x4(al[mi][0], al[mi][1], al[mi][2], al[mi][3], bb + offA1 + off);
            }
            #pragma unroll
            for (int nh = 0; nh < 2; nh++) {
                uint32_t off = nh * 16 * SSTRIDE * 2 + ko;
                ldm_x4(bh[nh*2][0], bh[nh*2][1], bh[nh*2+1][0], bh[nh*2+1][1], bb + offB0 + off);
                ldm_x4(bl[nh*2][0], bl[nh*2][1], bl[nh*2+1][0], bl[nh*2+1][1], bb + offB1 + off);
            }
            #pragma unroll
            for (int mi = 0; mi < 4; mi++)
                #pragma unroll
                for (int ni = 0; ni < 4; ni++) {
                    mma_16816(acc[mi][ni], ah[mi], bh[ni]);
                    mma_16816(acc[mi][ni], ah[mi], bl[ni]);
                    mma_16816(acc[mi][ni], al[mi], bh[ni]);
                }
        }
        // no second sync: buffer reuse is fenced by the NEXT iteration's barrier
    }

    const int qr = lane >> 2, qc = (lane & 3) * 2;
    #pragma unroll
    for (int ni = 0; ni < 4; ni++) {
        int col = bn * 128 + wn * 32 + ni * 8 + qc;
        float2 b = *(const float2*)(bias + col);
        #pragma unroll
        for (int mi = 0; mi < 4; mi++) {
            int row = bm * 128 + wm * 64 + mi * 16 + qr;
            float2 v0 = make_float2(acc[mi][ni][0] + b.x, acc[mi][ni][1] + b.y);
            float2 v1 = make_float2(acc[mi][ni][2] + b.x, acc[mi][ni][3] + b.y);
            *(float2*)(C + (size_t)row * DIM + col)       = v0;
            *(float2*)(C + (size_t)(row + 8) * DIM + col) = v1;
        }
    }
}

// ---------------- K4: fused node-major online-softmax attention ------------
__global__ __launch_bounds__(256) void attn_kernel(
    const float* __restrict__ vals, float* __restrict__ out)
{
    int node = (blockIdx.x * 256 + threadIdx.x) >> 5;
    int lane = threadIdx.x & 31;

    int cnt = min(g_cnt[node], CAP);
    const int* el = g_elist + node * CAP;

    const float* qp = g_q + (size_t)node * DIM;
    float4 q[4];
    #pragma unroll
    for (int j = 0; j < 4; j++) q[j] = *(const float4*)(qp + lane * 4 + j * 128);

    float m = -1e30f, d = 0.f;
    float4 acc[4];
    #pragma unroll
    for (int j = 0; j < 4; j++) acc[j] = make_float4(0.f, 0.f, 0.f, 0.f);

    for (int p = 0; p < cnt; p += 2) {
        const bool has2 = (p + 1 < cnt);
        const float* va = vals + (size_t)el[p] * DIM;
        const float* vb = vals + (size_t)el[has2 ? p + 1 : p] * DIM;

        float4 a[4], b[4];
        #pragma unroll
        for (int j = 0; j < 4; j++) {
            a[j] = ldcs4(va + lane * 4 + j * 128);
            b[j] = ldcs4(vb + lane * 4 + j * 128);
        }

        float sa = 0.f, sb = 0.f;
        #pragma unroll
        for (int j = 0; j < 4; j++) {
            sa += a[j].x * q[j].x + a[j].y * q[j].y + a[j].z * q[j].z + a[j].w * q[j].w;
            sb += b[j].x * q[j].x + b[j].y * q[j].y + b[j].z * q[j].z + b[j].w * q[j].w;
        }
        #pragma unroll
        for (int o = 16; o; o >>= 1) {
            sa += __shfl_xor_sync(0xFFFFFFFFu, sa, o);
            sb += __shfl_xor_sync(0xFFFFFFFFu, sb, o);
        }
        if (!has2) sb = -1e30f;

        float mx = fmaxf(m, fmaxf(sa, sb));
        float r  = expf(m - mx);
        d *= r;
        float wa = expf(sa - mx), wb = expf(sb - mx);
        d += wa + wb;
        #pragma unroll
        for (int j = 0; j < 4; j++) {
            acc[j].x = acc[j].x * r + wa * a[j].x + wb * b[j].x;
            acc[j].y = acc[j].y * r + wa * a[j].y + wb * b[j].y;
            acc[j].z = acc[j].z * r + wa * a[j].z + wb * b[j].z;
            acc[j].w = acc[j].w * r + wa * a[j].w + wb * b[j].w;
        }
        m = mx;
    }

    float inv = 1.0f / fmaxf(d, 1e-12f);
    float* op = out + (size_t)node * DIM;
    #pragma unroll
    for (int j = 0; j < 4; j++) {
        float4 o = make_float4(acc[j].x * inv, acc[j].y * inv,
                               acc[j].z * inv, acc[j].w * inv);
        *(float4*)(op + lane * 4 + j * 128) = o;
    }
}

// ---------------- launch ---------------------------------------------------
extern "C" void kernel_launch(void* const* d_in, const int* in_sizes, int n_in,
                              void* d_out, int out_size)
{
    const float* enc  = nullptr;
    const void*  c0   = nullptr;
    const void*  c1   = nullptr;
    const float* prev = nullptr;
    const float* Wq   = nullptr;
    const float* bq   = nullptr;
    int n131072 = 0;

    for (int i = 0; i < n_in; i++) {
        switch (in_sizes[i]) {
            case 67108864: enc  = (const float*)d_in[i]; break;
            case 4194304:  prev = (const float*)d_in[i]; break;
            case 262144:   Wq   = (const float*)d_in[i]; break;
            case 512:      bq   = (const float*)d_in[i]; break;
            case 131072:
                if (n131072++ == 0) c0 = d_in[i];
                else                c1 = d_in[i];
                break;
            default: break;
        }
    }

    float* out = (float*)d_out;
    float* q;
    cudaGetSymbolAddress((void**)&q, g_q);

    static int smem_set = 0;
    if (!smem_set) {
        cudaFuncSetAttribute(gemm_mma_kernel,
                             cudaFuncAttributeMaxDynamicSharedMemorySize, GSMEM);
        smem_set = 1;
    }

    detect_kernel<<<1, 256>>>((const unsigned*)c0, (const unsigned*)c1);   // 0
    build_kernel<<<N_EDGES / 256, 256>>>(c0, c1);                           // 1
    conv_wq_kernel<<<dim3(16, 16), 256>>>(Wq);                              // 2

    dim3 ggrid(DIM / 128, N_NODES / 128);   // (4, 64)
    gemm_mma_kernel<<<ggrid, 256, GSMEM>>>(prev, bq, q);                    // 3 (profiled)

    attn_kernel<<<N_NODES / 8, 256>>>(enc, out);                            // 4
}

// round 11
// speedup vs baseline: 1.9436x; 1.0096x over previous
#include <cuda_runtime.h>
#include <cuda_bf16.h>
#include <cstdint>
#include <cstddef>

#define DIM      512
#define N_NODES  8192
#define N_EDGES  131072   // 2048 paths * 64
#define CAP      128      // per-node edge-bucket capacity (λ≈8, 16x headroom)

// GEMM smem geometry
#define SSTRIDE  40                    // padded bf16 row stride (80 B)
#define TILE_B   (128 * SSTRIDE * 2)   // 10240 B per tile
#define BUF_B    (4 * TILE_B)          // Ah, Al, Bh, Bl = 40960 B
#define GSMEM    (2 * BUF_B)           // double buffered = 81920 B

// ---------------- scratch (device globals; no runtime allocation) ----------
__device__ float         g_q[N_NODES * DIM];      // projected queries, fp32
__device__ __nv_bfloat16 g_BhiT[DIM * DIM];       // Wq^T split hi [n][k]
__device__ __nv_bfloat16 g_BloT[DIM * DIM];       // Wq^T split lo
__device__ int           g_cnt[N_NODES];          // per-node live-edge counts
__device__ int           g_elist[N_NODES * CAP];  // per-node edge buckets

struct Cfg { int idx_is_1; int mask_byte; };
__device__ Cfg g_cfg;

// ---------------- helpers ---------------------------------------------------
__device__ __forceinline__ uint32_t smem_u32(const void* p) {
    uint32_t a;
    asm("{ .reg .u64 t; cvta.to.shared.u64 t, %1; cvt.u32.u64 %0, t; }" : "=r"(a) : "l"(p));
    return a;
}
__device__ __forceinline__ void ldm_x4(uint32_t& r0, uint32_t& r1, uint32_t& r2,
                                       uint32_t& r3, uint32_t addr) {
    asm volatile("ldmatrix.sync.aligned.m8n8.x4.shared.b16 {%0,%1,%2,%3}, [%4];"
                 : "=r"(r0), "=r"(r1), "=r"(r2), "=r"(r3) : "r"(addr));
}
__device__ __forceinline__ void mma_16816(float* c, const uint32_t* a, const uint32_t* b) {
    asm volatile(
        "mma.sync.aligned.m16n8k16.row.col.f32.bf16.bf16.f32 "
        "{%0,%1,%2,%3}, {%4,%5,%6,%7}, {%8,%9}, {%0,%1,%2,%3};"
        : "+f"(c[0]), "+f"(c[1]), "+f"(c[2]), "+f"(c[3])
        : "r"(a[0]), "r"(a[1]), "r"(a[2]), "r"(a[3]), "r"(b[0]), "r"(b[1]));
}
__device__ __forceinline__ float4 ldcs4(const float* p) {
    float4 v;
    asm volatile("ld.global.cs.v4.f32 {%0,%1,%2,%3}, [%4];"
                 : "=f"(v.x), "=f"(v.y), "=f"(v.z), "=f"(v.w) : "l"(p));
    return v;
}

// ---------------- K0: detect idx/mask binding + zero counts ----------------
__global__ __launch_bounds__(256) void detect_kernel(
    const unsigned* __restrict__ c0, const unsigned* __restrict__ c1)
{
    #pragma unroll
    for (int i = 0; i < 32; i++) g_cnt[threadIdx.x + i * 256] = 0;

    __shared__ unsigned sm[2], so[2];
    if (threadIdx.x < 2) { sm[threadIdx.x] = 0u; so[threadIdx.x] = 0u; }
    __syncthreads();
    unsigned m0 = 0, m1 = 0, o0 = 0, o1 = 0;
    for (int i = threadIdx.x; i < 32768; i += 256) {
        unsigned a = c0[i], b = c1[i];
        m0 = max(m0, a); m1 = max(m1, b);
        o0 |= a & 0xFEFEFEFEu; o1 |= b & 0xFEFEFEFEu;
    }
    atomicMax(&sm[0], m0); atomicMax(&sm[1], m1);
    atomicOr (&so[0], o0); atomicOr (&so[1], o1);
    __syncthreads();
    if (threadIdx.x == 0) {
        unsigned M0 = sm[0], M1 = sm[1];
        int idx_is_1;
        if      (M0 <= 1u)                   idx_is_1 = 1;
        else if (M1 <= 1u)                   idx_is_1 = 0;
        else if (M0 < 8192u && M1 >= 8192u)  idx_is_1 = 0;
        else if (M1 < 8192u && M0 >= 8192u)  idx_is_1 = 1;
        else                                 idx_is_1 = 1;
        unsigned Mm = idx_is_1 ? M0 : M1;
        unsigned Om = idx_is_1 ? so[0] : so[1];
        g_cfg.idx_is_1  = idx_is_1;
        g_cfg.mask_byte = (Mm > 1u && Om == 0u) ? 1 : 0;
    }
}
__device__ __forceinline__ bool edge_live(const void* mask, int e, int mask_byte) {
    return mask_byte ? (((const unsigned char*)mask)[e] != 0)
                     : (((const unsigned*)mask)[e] != 0u);
}

// ---------------- K1: build per-node edge buckets (single pass) ------------
__global__ __launch_bounds__(256) void build_kernel(
    const void* __restrict__ c0, const void* __restrict__ c1)
{
    const Cfg cfg = g_cfg;
    const int*  idx  = cfg.idx_is_1 ? (const int*)c1 : (const int*)c0;
    const void* mask = cfg.idx_is_1 ? c0 : c1;
    int e = blockIdx.x * 256 + threadIdx.x;
    if (edge_live(mask, e, cfg.mask_byte)) {
        int node = idx[e];
        int pos  = atomicAdd(&g_cnt[node], 1);
        if (pos < CAP) g_elist[node * CAP + pos] = e;
    }
}

// ---------------- K2: transpose+split Wq -> [n][k] bf16 hi/lo --------------
__global__ __launch_bounds__(256) void conv_wq_kernel(const float* __restrict__ Wq) {
    __shared__ float t[32][33];
    int n0 = blockIdx.x * 32, k0 = blockIdx.y * 32;
    #pragma unroll
    for (int i = 0; i < 4; i++) {
        int lin = threadIdx.x + i * 256;
        int r = lin >> 5, c = lin & 31;
        t[r][c] = Wq[(size_t)(k0 + r) * DIM + n0 + c];
    }
    __syncthreads();
    #pragma unroll
    for (int i = 0; i < 4; i++) {
        int lin = threadIdx.x + i * 256;
        int r = lin >> 5, c = lin & 31;
        float v = t[c][r];
        __nv_bfloat16 h = __float2bfloat16(v);
        __nv_bfloat16 l = __float2bfloat16(v - __bfloat162float(h));
        size_t o = (size_t)(n0 + r) * DIM + k0 + c;
        g_BhiT[o] = h; g_BloT[o] = l;
    }
}

// ---------------- K3: q = prev @ Wq + bq (mma.sync, double-buffered) -------
// Term-major MMA order: 16 independent accumulators between RAW reuse.
__global__ __launch_bounds__(256) void gemm_mma_kernel(
    const float* __restrict__ Aprev,   // [8192, 512] fp32
    const float* __restrict__ bias, float* __restrict__ C)
{
    extern __shared__ char dsm[];

    const int tid = threadIdx.x, wid = tid >> 5, lane = tid & 31;
    const int wm = wid & 1, wn = wid >> 1;
    const int bm = blockIdx.y, bn = blockIdx.x;

    const float* Asrc = Aprev + (size_t)bm * 128 * DIM;
    const __nv_bfloat16* Bh = g_BhiT + (size_t)bn * 128 * DIM;
    const __nv_bfloat16* Bl = g_BloT + (size_t)bn * 128 * DIM;

    float acc[4][4][4];
    #pragma unroll
    for (int i = 0; i < 4; i++)
        #pragma unroll
        for (int j = 0; j < 4; j++)
            #pragma unroll
            for (int k = 0; k < 4; k++) acc[i][j][k] = 0.f;

    const uint32_t a_row = lane & 15, a_c8 = (lane >> 4) << 3;
    const uint32_t b_n   = (lane & 7) + ((lane >> 4) << 3);
    const uint32_t b_k8  = ((lane >> 3) & 1) << 3;
    const uint32_t sbase = smem_u32(dsm);
    const uint32_t offA0 = 0 * TILE_B + (wm * 64 + a_row) * (SSTRIDE * 2) + a_c8 * 2;
    const uint32_t offA1 = 1 * TILE_B + (wm * 64 + a_row) * (SSTRIDE * 2) + a_c8 * 2;
    const uint32_t offB0 = 2 * TILE_B + (wn * 32 + b_n) * (SSTRIDE * 2) + b_k8 * 2;
    const uint32_t offB1 = 3 * TILE_B + (wn * 32 + b_n) * (SSTRIDE * 2) + b_k8 * 2;

    int ar[4], ac[4];
    #pragma unroll
    for (int i = 0; i < 4; i++) {
        int l = tid + i * 256;
        ar[i] = l >> 3; ac[i] = (l & 7) * 4;
    }
    const int u0 = tid, u1 = tid + 256;
    const int br0 = u0 >> 2, bc0 = (u0 & 3) * 8;
    const int br1 = u1 >> 2, bc1 = (u1 & 3) * 8;

    float4 pa[4];
    uint4  pb[4];
    #pragma unroll
    for (int i = 0; i < 4; i++)
        pa[i] = *(const float4*)(Asrc + (size_t)ar[i] * DIM + ac[i]);
    pb[0] = *(const uint4*)(Bh + (size_t)br0 * DIM + bc0);
    pb[1] = *(const uint4*)(Bh + (size_t)br1 * DIM + bc1);
    pb[2] = *(const uint4*)(Bl + (size_t)br0 * DIM + bc0);
    pb[3] = *(const uint4*)(Bl + (size_t)br1 * DIM + bc1);

    for (int ch = 0; ch < 16; ch++) {
        char* buf = dsm + (ch & 1) * BUF_B;
        #pragma unroll
        for (int i = 0; i < 4; i++) {
            float4 v = pa[i];
            __nv_bfloat16 h0 = __float2bfloat16(v.x), h1 = __float2bfloat16(v.y);
            __nv_bfloat16 h2 = __float2bfloat16(v.z), h3 = __float2bfloat16(v.w);
            __nv_bfloat16 l0 = __float2bfloat16(v.x - __bfloat162float(h0));
            __nv_bfloat16 l1 = __float2bfloat16(v.y - __bfloat162float(h1));
            __nv_bfloat16 l2 = __float2bfloat16(v.z - __bfloat162float(h2));
            __nv_bfloat16 l3 = __float2bfloat16(v.w - __bfloat162float(h3));
            uint32_t byo = ar[i] * (SSTRIDE * 2) + ac[i] * 2;
            *(__nv_bfloat162*)(buf + 0 * TILE_B + byo)     = __nv_bfloat162(h0, h1);
            *(__nv_bfloat162*)(buf + 0 * TILE_B + byo + 4) = __nv_bfloat162(h2, h3);
            *(__nv_bfloat162*)(buf + 1 * TILE_B + byo)     = __nv_bfloat162(l0, l1);
            *(__nv_bfloat162*)(buf + 1 * TILE_B + byo + 4) = __nv_bfloat162(l2, l3);
        }
        *(uint4*)(buf + 2 * TILE_B + br0 * (SSTRIDE * 2) + bc0 * 2) = pb[0];
        *(uint4*)(buf + 2 * TILE_B + br1 * (SSTRIDE * 2) + bc1 * 2) = pb[1];
        *(uint4*)(buf + 3 * TILE_B + br0 * (SSTRIDE * 2) + bc0 * 2) = pb[2];
        *(uint4*)(buf + 3 * TILE_B + br1 * (SSTRIDE * 2) + bc1 * 2) = pb[3];
        __syncthreads();

        if (ch < 15) {
            const int kb = (ch + 1) * 32;
            #pragma unroll
            for (int i = 0; i < 4; i++)
                pa[i] = *(const float4*)(Asrc + (size_t)ar[i] * DIM + kb + ac[i]);
            pb[0] = *(const uint4*)(Bh + (size_t)br0 * DIM + kb + bc0);
            pb[1] = *(const uint4*)(Bh + (size_t)br1 * DIM + kb + bc1);
            pb[2] = *(const uint4*)(Bl + (size_t)br0 * DIM + kb + bc0);
            pb[3] = *(const uint4*)(Bl + (size_t)br1 * DIM + kb + bc1);
        }

        const uint32_t bb = sbase + (ch & 1) * BUF_B;
        #pragma unroll
        for (int ks = 0; ks < 2; ks++) {
            const uint32_t ko = ks * 16 * 2;
            uint32_t ah[4][4], al[4][4], bh[4][2], bl[4][2];
            #pragma unroll
            for (int mi = 0; mi < 4; mi++) {
                uint32_t off = mi * 16 * SSTRIDE * 2 + ko;
                ldm_x4(ah[mi][0], ah[mi][1], ah[mi][2], ah[mi][3], bb + offA0 + off);
                ldm_x4(al[mi][0], al[mi][1], al[mi][2], al[mi][3], bb + offA1 + off);
            }
            #pragma unroll
            for (int nh = 0; nh < 2; nh++) {
                uint32_t off = nh * 16 * SSTRIDE * 2 + ko;
                ldm_x4(bh[nh*2][0], bh[nh*2][1], bh[nh*2+1][0], bh[nh*2+1][1], bb + offB0 + off);
                ldm_x4(bl[nh*2][0], bl[nh*2][1], bl[nh*2+1][0], bl[nh*2+1][1], bb + offB1 + off);
            }
            // term-major: 16 independent accumulators between any RAW reuse
            #pragma unroll
            for (int mi = 0; mi < 4; mi++)
                #pragma unroll
                for (int ni = 0; ni < 4; ni++)
                    mma_16816(acc[mi][ni], ah[mi], bh[ni]);
            #pragma unroll
            for (int mi = 0; mi < 4; mi++)
                #pragma unroll
                for (int ni = 0; ni < 4; ni++)
                    mma_16816(acc[mi][ni], ah[mi], bl[ni]);
            #pragma unroll
            for (int mi = 0; mi < 4; mi++)
                #pragma unroll
                for (int ni = 0; ni < 4; ni++)
                    mma_16816(acc[mi][ni], al[mi], bh[ni]);
        }
    }

    const int qr = lane >> 2, qc = (lane & 3) * 2;
    #pragma unroll
    for (int ni = 0; ni < 4; ni++) {
        int col = bn * 128 + wn * 32 + ni * 8 + qc;
        float2 b = *(const float2*)(bias + col);
        #pragma unroll
        for (int mi = 0; mi < 4; mi++) {
            int row = bm * 128 + wm * 64 + mi * 16 + qr;
            float2 v0 = make_float2(acc[mi][ni][0] + b.x, acc[mi][ni][1] + b.y);
            float2 v1 = make_float2(acc[mi][ni][2] + b.x, acc[mi][ni][3] + b.y);
            *(float2*)(C + (size_t)row * DIM + col)       = v0;
            *(float2*)(C + (size_t)(row + 8) * DIM + col) = v1;
        }
    }
}

// ---------------- K4: fused node-major online-softmax attention ------------
__global__ __launch_bounds__(256) void attn_kernel(
    const float* __restrict__ vals, float* __restrict__ out)
{
    int node = (blockIdx.x * 256 + threadIdx.x) >> 5;
    int lane = threadIdx.x & 31;

    int cnt = min(g_cnt[node], CAP);
    const int* el = g_elist + node * CAP;

    const float* qp = g_q + (size_t)node * DIM;
    float4 q[4];
    #pragma unroll
    for (int j = 0; j < 4; j++) q[j] = *(const float4*)(qp + lane * 4 + j * 128);

    float m = -1e30f, d = 0.f;
    float4 acc[4];
    #pragma unroll
    for (int j = 0; j < 4; j++) acc[j] = make_float4(0.f, 0.f, 0.f, 0.f);

    for (int p = 0; p < cnt; p += 2) {
        const bool has2 = (p + 1 < cnt);
        const float* va = vals + (size_t)el[p] * DIM;
        const float* vb = vals + (size_t)el[has2 ? p + 1 : p] * DIM;

        float4 a[4], b[4];
        #pragma unroll
        for (int j = 0; j < 4; j++) {
            a[j] = ldcs4(va + lane * 4 + j * 128);
            b[j] = ldcs4(vb + lane * 4 + j * 128);
        }

        float sa = 0.f, sb = 0.f;
        #pragma unroll
        for (int j = 0; j < 4; j++) {
            sa += a[j].x * q[j].x + a[j].y * q[j].y + a[j].z * q[j].z + a[j].w * q[j].w;
            sb += b[j].x * q[j].x + b[j].y * q[j].y + b[j].z * q[j].z + b[j].w * q[j].w;
        }
        #pragma unroll
        for (int o = 16; o; o >>= 1) {
            sa += __shfl_xor_sync(0xFFFFFFFFu, sa, o);
            sb += __shfl_xor_sync(0xFFFFFFFFu, sb, o);
        }
        if (!has2) sb = -1e30f;

        float mx = fmaxf(m, fmaxf(sa, sb));
        float r  = expf(m - mx);
        d *= r;
        float wa = expf(sa - mx), wb = expf(sb - mx);
        d += wa + wb;
        #pragma unroll
        for (int j = 0; j < 4; j++) {
            acc[j].x = acc[j].x * r + wa * a[j].x + wb * b[j].x;
            acc[j].y = acc[j].y * r + wa * a[j].y + wb * b[j].y;
            acc[j].z = acc[j].z * r + wa * a[j].z + wb * b[j].z;
            acc[j].w = acc[j].w * r + wa * a[j].w + wb * b[j].w;
        }
        m = mx;
    }

    float inv = 1.0f / fmaxf(d, 1e-12f);
    float* op = out + (size_t)node * DIM;
    #pragma unroll
    for (int j = 0; j < 4; j++) {
        float4 o = make_float4(acc[j].x * inv, acc[j].y * inv,
                               acc[j].z * inv, acc[j].w * inv);
        *(float4*)(op + lane * 4 + j * 128) = o;
    }
}

// ---------------- launch ---------------------------------------------------
extern "C" void kernel_launch(void* const* d_in, const int* in_sizes, int n_in,
                              void* d_out, int out_size)
{
    const float* enc  = nullptr;
    const void*  c0   = nullptr;
    const void*  c1   = nullptr;
    const float* prev = nullptr;
    const float* Wq   = nullptr;
    const float* bq   = nullptr;
    int n131072 = 0;

    for (int i = 0; i < n_in; i++) {
        switch (in_sizes[i]) {
            case 67108864: enc  = (const float*)d_in[i]; break;
            case 4194304:  prev = (const float*)d_in[i]; break;
            case 262144:   Wq   = (const float*)d_in[i]; break;
            case 512:      bq   = (const float*)d_in[i]; break;
            case 131072:
                if (n131072++ == 0) c0 = d_in[i];
                else                c1 = d_in[i];
                break;
            default: break;
        }
    }

    float* out = (float*)d_out;
    float* q;
    cudaGetSymbolAddress((void**)&q, g_q);

    static int smem_set = 0;
    if (!smem_set) {
        cudaFuncSetAttribute(gemm_mma_kernel,
                             cudaFuncAttributeMaxDynamicSharedMemorySize, GSMEM);
        smem_set = 1;
    }

    detect_kernel<<<1, 256>>>((const unsigned*)c0, (const unsigned*)c1);   // 0
    build_kernel<<<N_EDGES / 256, 256>>>(c0, c1);                           // 1
    conv_wq_kernel<<<dim3(16, 16), 256>>>(Wq);                              // 2

    dim3 ggrid(DIM / 128, N_NODES / 128);   // (4, 64)
    gemm_mma_kernel<<<ggrid, 256, GSMEM>>>(prev, bq, q);                    // 3 (profiled)

    attn_kernel<<<N_NODES / 8, 256>>>(enc, out);                            // 4
}

// round 12
// speedup vs baseline: 1.9848x; 1.0212x over previous
#include <cuda_runtime.h>
#include <cuda_bf16.h>
#include <cstdint>
#include <cstddef>

#define DIM      512
#define N_NODES  8192
#define N_EDGES  131072   // 2048 paths * 64
#define CAP      128      // per-node edge-bucket capacity (λ≈8, 16x headroom)

// GEMM smem geometry
#define SSTRIDE  40                    // padded bf16 row stride (80 B)
#define TILE_B   (128 * SSTRIDE * 2)   // 10240 B per tile
#define BUF_B    (4 * TILE_B)          // Ah, Al, Bh, Bl = 40960 B
#define GSMEM    (2 * BUF_B)           // double buffered = 81920 B

// ---------------- scratch (device globals; no runtime allocation) ----------
__device__ float         g_q[N_NODES * DIM];      // projected queries, fp32
__device__ __nv_bfloat16 g_BhiT[DIM * DIM];       // Wq^T split hi [n][k]
__device__ __nv_bfloat16 g_BloT[DIM * DIM];       // Wq^T split lo
__device__ int           g_cnt[N_NODES];          // per-node live-edge counts
__device__ int           g_elist[N_NODES * CAP];  // per-node edge buckets

struct Cfg { int idx_is_1; int mask_byte; };
__device__ Cfg g_cfg;

// ---------------- helpers ---------------------------------------------------
__device__ __forceinline__ uint32_t smem_u32(const void* p) {
    uint32_t a;
    asm("{ .reg .u64 t; cvta.to.shared.u64 t, %1; cvt.u32.u64 %0, t; }" : "=r"(a) : "l"(p));
    return a;
}
__device__ __forceinline__ void ldm_x4(uint32_t& r0, uint32_t& r1, uint32_t& r2,
                                       uint32_t& r3, uint32_t addr) {
    asm volatile("ldmatrix.sync.aligned.m8n8.x4.shared.b16 {%0,%1,%2,%3}, [%4];"
                 : "=r"(r0), "=r"(r1), "=r"(r2), "=r"(r3) : "r"(addr));
}
__device__ __forceinline__ void mma_16816(float* c, const uint32_t* a, const uint32_t* b) {
    asm volatile(
        "mma.sync.aligned.m16n8k16.row.col.f32.bf16.bf16.f32 "
        "{%0,%1,%2,%3}, {%4,%5,%6,%7}, {%8,%9}, {%0,%1,%2,%3};"
        : "+f"(c[0]), "+f"(c[1]), "+f"(c[2]), "+f"(c[3])
        : "r"(a[0]), "r"(a[1]), "r"(a[2]), "r"(a[3]), "r"(b[0]), "r"(b[1]));
}
__device__ __forceinline__ float4 ldcs4(const float* p) {
    float4 v;
    asm volatile("ld.global.cs.v4.f32 {%0,%1,%2,%3}, [%4];"
                 : "=f"(v.x), "=f"(v.y), "=f"(v.z), "=f"(v.w) : "l"(p));
    return v;
}

// ---------------- K0: detect idx/mask binding + zero counts ----------------
__global__ __launch_bounds__(256) void detect_kernel(
    const unsigned* __restrict__ c0, const unsigned* __restrict__ c1)
{
    #pragma unroll
    for (int i = 0; i < 32; i++) g_cnt[threadIdx.x + i * 256] = 0;

    __shared__ unsigned sm[2], so[2];
    if (threadIdx.x < 2) { sm[threadIdx.x] = 0u; so[threadIdx.x] = 0u; }
    __syncthreads();
    unsigned m0 = 0, m1 = 0, o0 = 0, o1 = 0;
    for (int i = threadIdx.x; i < 32768; i += 256) {
        unsigned a = c0[i], b = c1[i];
        m0 = max(m0, a); m1 = max(m1, b);
        o0 |= a & 0xFEFEFEFEu; o1 |= b & 0xFEFEFEFEu;
    }
    atomicMax(&sm[0], m0); atomicMax(&sm[1], m1);
    atomicOr (&so[0], o0); atomicOr (&so[1], o1);
    __syncthreads();
    if (threadIdx.x == 0) {
        unsigned M0 = sm[0], M1 = sm[1];
        int idx_is_1;
        if      (M0 <= 1u)                   idx_is_1 = 1;
        else if (M1 <= 1u)                   idx_is_1 = 0;
        else if (M0 < 8192u && M1 >= 8192u)  idx_is_1 = 0;
        else if (M1 < 8192u && M0 >= 8192u)  idx_is_1 = 1;
        else                                 idx_is_1 = 1;
        unsigned Mm = idx_is_1 ? M0 : M1;
        unsigned Om = idx_is_1 ? so[0] : so[1];
        g_cfg.idx_is_1  = idx_is_1;
        g_cfg.mask_byte = (Mm > 1u && Om == 0u) ? 1 : 0;
    }
}
__device__ __forceinline__ bool edge_live(const void* mask, int e, int mask_byte) {
    return mask_byte ? (((const unsigned char*)mask)[e] != 0)
                     : (((const unsigned*)mask)[e] != 0u);
}

// ---------------- K1: build per-node edge buckets (single pass) ------------
__global__ __launch_bounds__(256) void build_kernel(
    const void* __restrict__ c0, const void* __restrict__ c1)
{
    const Cfg cfg = g_cfg;
    const int*  idx  = cfg.idx_is_1 ? (const int*)c1 : (const int*)c0;
    const void* mask = cfg.idx_is_1 ? c0 : c1;
    int e = blockIdx.x * 256 + threadIdx.x;
    if (edge_live(mask, e, cfg.mask_byte)) {
        int node = idx[e];
        int pos  = atomicAdd(&g_cnt[node], 1);
        if (pos < CAP) g_elist[node * CAP + pos] = e;
    }
}

// ---------------- K2: transpose+split Wq -> [n][k] bf16 hi/lo --------------
__global__ __launch_bounds__(256) void conv_wq_kernel(const float* __restrict__ Wq) {
    __shared__ float t[32][33];
    int n0 = blockIdx.x * 32, k0 = blockIdx.y * 32;
    #pragma unroll
    for (int i = 0; i < 4; i++) {
        int lin = threadIdx.x + i * 256;
        int r = lin >> 5, c = lin & 31;
        t[r][c] = Wq[(size_t)(k0 + r) * DIM + n0 + c];
    }
    __syncthreads();
    #pragma unroll
    for (int i = 0; i < 4; i++) {
        int lin = threadIdx.x + i * 256;
        int r = lin >> 5, c = lin & 31;
        float v = t[c][r];
        __nv_bfloat16 h = __float2bfloat16(v);
        __nv_bfloat16 l = __float2bfloat16(v - __bfloat162float(h));
        size_t o = (size_t)(n0 + r) * DIM + k0 + c;
        g_BhiT[o] = h; g_BloT[o] = l;
    }
}

// ---------------- K3: q = prev @ Wq + bq (mma.sync, 16 warps/CTA) ----------
// 512 threads, warp grid 4(M)x4(N), 32x32 warp tiles. Double-buffered smem,
// one __syncthreads per K-chunk. 4 warps/SMSP for latency hiding.
__global__ __launch_bounds__(512, 1) void gemm_mma_kernel(
    const float* __restrict__ Aprev,   // [8192, 512] fp32
    const float* __restrict__ bias, float* __restrict__ C)
{
    extern __shared__ char dsm[];

    const int tid = threadIdx.x, wid = tid >> 5, lane = tid & 31;
    const int wm = wid & 3, wn = wid >> 2;          // 4(M) x 4(N)
    const int bm = blockIdx.y, bn = blockIdx.x;

    const float* Asrc = Aprev + (size_t)bm * 128 * DIM;
    const __nv_bfloat16* Bh = g_BhiT + (size_t)bn * 128 * DIM;
    const __nv_bfloat16* Bl = g_BloT + (size_t)bn * 128 * DIM;

    float acc[2][4][4];                              // 32 regs
    #pragma unroll
    for (int i = 0; i < 2; i++)
        #pragma unroll
        for (int j = 0; j < 4; j++)
            #pragma unroll
            for (int k = 0; k < 4; k++) acc[i][j][k] = 0.f;

    // per-lane ldmatrix byte offsets within one buffer
    const uint32_t a_row = lane & 15, a_c8 = (lane >> 4) << 3;
    const uint32_t b_n   = (lane & 7) + ((lane >> 4) << 3);
    const uint32_t b_k8  = ((lane >> 3) & 1) << 3;
    const uint32_t sbase = smem_u32(dsm);
    const uint32_t offA0 = 0 * TILE_B + (wm * 32 + a_row) * (SSTRIDE * 2) + a_c8 * 2;
    const uint32_t offA1 = 1 * TILE_B + (wm * 32 + a_row) * (SSTRIDE * 2) + a_c8 * 2;
    const uint32_t offB0 = 2 * TILE_B + (wn * 32 + b_n) * (SSTRIDE * 2) + b_k8 * 2;
    const uint32_t offB1 = 3 * TILE_B + (wn * 32 + b_n) * (SSTRIDE * 2) + b_k8 * 2;

    // staging maps: A 128x32 fp32 = 1024 float4 -> 2/thread; B 512 uint4 -> 1/thread/tile
    int ar[2], ac[2];
    #pragma unroll
    for (int i = 0; i < 2; i++) {
        int l = tid + i * 512;
        ar[i] = l >> 3; ac[i] = (l & 7) * 4;
    }
    const int br = tid >> 2, bc = (tid & 3) * 8;

    float4 pa[2];
    uint4  pb[2];
    #pragma unroll
    for (int i = 0; i < 2; i++)
        pa[i] = *(const float4*)(Asrc + (size_t)ar[i] * DIM + ac[i]);
    pb[0] = *(const uint4*)(Bh + (size_t)br * DIM + bc);
    pb[1] = *(const uint4*)(Bl + (size_t)br * DIM + bc);

    for (int ch = 0; ch < 16; ch++) {
        char* buf = dsm + (ch & 1) * BUF_B;
        #pragma unroll
        for (int i = 0; i < 2; i++) {
            float4 v = pa[i];
            __nv_bfloat16 h0 = __float2bfloat16(v.x), h1 = __float2bfloat16(v.y);
            __nv_bfloat16 h2 = __float2bfloat16(v.z), h3 = __float2bfloat16(v.w);
            __nv_bfloat16 l0 = __float2bfloat16(v.x - __bfloat162float(h0));
            __nv_bfloat16 l1 = __float2bfloat16(v.y - __bfloat162float(h1));
            __nv_bfloat16 l2 = __float2bfloat16(v.z - __bfloat162float(h2));
            __nv_bfloat16 l3 = __float2bfloat16(v.w - __bfloat162float(h3));
            uint32_t byo = ar[i] * (SSTRIDE * 2) + ac[i] * 2;
            *(__nv_bfloat162*)(buf + 0 * TILE_B + byo)     = __nv_bfloat162(h0, h1);
            *(__nv_bfloat162*)(buf + 0 * TILE_B + byo + 4) = __nv_bfloat162(h2, h3);
            *(__nv_bfloat162*)(buf + 1 * TILE_B + byo)     = __nv_bfloat162(l0, l1);
            *(__nv_bfloat162*)(buf + 1 * TILE_B + byo + 4) = __nv_bfloat162(l2, l3);
        }
        *(uint4*)(buf + 2 * TILE_B + br * (SSTRIDE * 2) + bc * 2) = pb[0];
        *(uint4*)(buf + 3 * TILE_B + br * (SSTRIDE * 2) + bc * 2) = pb[1];
        __syncthreads();

        if (ch < 15) {                  // next chunk's global loads overlap MMAs
            const int kb = (ch + 1) * 32;
            #pragma unroll
            for (int i = 0; i < 2; i++)
                pa[i] = *(const float4*)(Asrc + (size_t)ar[i] * DIM + kb + ac[i]);
            pb[0] = *(const uint4*)(Bh + (size_t)br * DIM + kb + bc);
            pb[1] = *(const uint4*)(Bl + (size_t)br * DIM + kb + bc);
        }

        const uint32_t bb = sbase + (ch & 1) * BUF_B;
        #pragma unroll
        for (int ks = 0; ks < 2; ks++) {
            const uint32_t ko = ks * 16 * 2;
            uint32_t ah[2][4], al[2][4], bh[4][2], bl[4][2];
            #pragma unroll
            for (int mi = 0; mi < 2; mi++) {
                uint32_t off = mi * 16 * SSTRIDE * 2 + ko;
                ldm_x4(ah[mi][0], ah[mi][1], ah[mi][2], ah[mi][3], bb + offA0 + off);
                ldm_x4(al[mi][0], al[mi][1], al[mi][2], al[mi][3], bb + offA1 + off);
            }
            #pragma unroll
            for (int nh = 0; nh < 2; nh++) {
                uint32_t off = nh * 16 * SSTRIDE * 2 + ko;
                ldm_x4(bh[nh*2][0], bh[nh*2][1], bh[nh*2+1][0], bh[nh*2+1][1], bb + offB0 + off);
                ldm_x4(bl[nh*2][0], bl[nh*2][1], bl[nh*2+1][0], bl[nh*2+1][1], bb + offB1 + off);
            }
            #pragma unroll
            for (int mi = 0; mi < 2; mi++)
                #pragma unroll
                for (int ni = 0; ni < 4; ni++)
                    mma_16816(acc[mi][ni], ah[mi], bh[ni]);
            #pragma unroll
            for (int mi = 0; mi < 2; mi++)
                #pragma unroll
                for (int ni = 0; ni < 4; ni++)
                    mma_16816(acc[mi][ni], ah[mi], bl[ni]);
            #pragma unroll
            for (int mi = 0; mi < 2; mi++)
                #pragma unroll
                for (int ni = 0; ni < 4; ni++)
                    mma_16816(acc[mi][ni], al[mi], bh[ni]);
        }
    }

    const int qr = lane >> 2, qc = (lane & 3) * 2;
    #pragma unroll
    for (int ni = 0; ni < 4; ni++) {
        int col = bn * 128 + wn * 32 + ni * 8 + qc;
        float2 b = *(const float2*)(bias + col);
        #pragma unroll
        for (int mi = 0; mi < 2; mi++) {
            int row = bm * 128 + wm * 32 + mi * 16 + qr;
            float2 v0 = make_float2(acc[mi][ni][0] + b.x, acc[mi][ni][1] + b.y);
            float2 v1 = make_float2(acc[mi][ni][2] + b.x, acc[mi][ni][3] + b.y);
            *(float2*)(C + (size_t)row * DIM + col)       = v0;
            *(float2*)(C + (size_t)(row + 8) * DIM + col) = v1;
        }
    }
}

// ---------------- K4: fused node-major online-softmax attention ------------
__global__ __launch_bounds__(256) void attn_kernel(
    const float* __restrict__ vals, float* __restrict__ out)
{
    int node = (blockIdx.x * 256 + threadIdx.x) >> 5;
    int lane = threadIdx.x & 31;

    int cnt = min(g_cnt[node], CAP);
    const int* el = g_elist + node * CAP;

    const float* qp = g_q + (size_t)node * DIM;
    float4 q[4];
    #pragma unroll
    for (int j = 0; j < 4; j++) q[j] = *(const float4*)(qp + lane * 4 + j * 128);

    float m = -1e30f, d = 0.f;
    float4 acc[4];
    #pragma unroll
    for (int j = 0; j < 4; j++) acc[j] = make_float4(0.f, 0.f, 0.f, 0.f);

    for (int p = 0; p < cnt; p += 2) {
        const bool has2 = (p + 1 < cnt);
        const float* va = vals + (size_t)el[p] * DIM;
        const float* vb = vals + (size_t)el[has2 ? p + 1 : p] * DIM;

        float4 a[4], b[4];
        #pragma unroll
        for (int j = 0; j < 4; j++) {
            a[j] = ldcs4(va + lane * 4 + j * 128);
            b[j] = ldcs4(vb + lane * 4 + j * 128);
        }

        float sa = 0.f, sb = 0.f;
        #pragma unroll
        for (int j = 0; j < 4; j++) {
            sa += a[j].x * q[j].x + a[j].y * q[j].y + a[j].z * q[j].z + a[j].w * q[j].w;
            sb += b[j].x * q[j].x + b[j].y * q[j].y + b[j].z * q[j].z + b[j].w * q[j].w;
        }
        #pragma unroll
        for (int o = 16; o; o >>= 1) {
            sa += __shfl_xor_sync(0xFFFFFFFFu, sa, o);
            sb += __shfl_xor_sync(0xFFFFFFFFu, sb, o);
        }
        if (!has2) sb = -1e30f;

        float mx = fmaxf(m, fmaxf(sa, sb));
        float r  = expf(m - mx);
        d *= r;
        float wa = expf(sa - mx), wb = expf(sb - mx);
        d += wa + wb;
        #pragma unroll
        for (int j = 0; j < 4; j++) {
            acc[j].x = acc[j].x * r + wa * a[j].x + wb * b[j].x;
            acc[j].y = acc[j].y * r + wa * a[j].y + wb * b[j].y;
            acc[j].z = acc[j].z * r + wa * a[j].z + wb * b[j].z;
            acc[j].w = acc[j].w * r + wa * a[j].w + wb * b[j].w;
        }
        m = mx;
    }

    float inv = 1.0f / fmaxf(d, 1e-12f);
    float* op = out + (size_t)node * DIM;
    #pragma unroll
    for (int j = 0; j < 4; j++) {
        float4 o = make_float4(acc[j].x * inv, acc[j].y * inv,
                               acc[j].z * inv, acc[j].w * inv);
        *(float4*)(op + lane * 4 + j * 128) = o;
    }
}

// ---------------- launch ---------------------------------------------------
extern "C" void kernel_launch(void* const* d_in, const int* in_sizes, int n_in,
                              void* d_out, int out_size)
{
    const float* enc  = nullptr;
    const void*  c0   = nullptr;
    const void*  c1   = nullptr;
    const float* prev = nullptr;
    const float* Wq   = nullptr;
    const float* bq   = nullptr;
    int n131072 = 0;

    for (int i = 0; i < n_in; i++) {
        switch (in_sizes[i]) {
            case 67108864: enc  = (const float*)d_in[i]; break;
            case 4194304:  prev = (const float*)d_in[i]; break;
            case 262144:   Wq   = (const float*)d_in[i]; break;
            case 512:      bq   = (const float*)d_in[i]; break;
            case 131072:
                if (n131072++ == 0) c0 = d_in[i];
                else                c1 = d_in[i];
                break;
            default: break;
        }
    }

    float* out = (float*)d_out;
    float* q;
    cudaGetSymbolAddress((void**)&q, g_q);

    static int smem_set = 0;
    if (!smem_set) {
        cudaFuncSetAttribute(gemm_mma_kernel,
                             cudaFuncAttributeMaxDynamicSharedMemorySize, GSMEM);
        smem_set = 1;
    }

    detect_kernel<<<1, 256>>>((const unsigned*)c0, (const unsigned*)c1);   // 0
    build_kernel<<<N_EDGES / 256, 256>>>(c0, c1);                           // 1
    conv_wq_kernel<<<dim3(16, 16), 256>>>(Wq);                              // 2

    dim3 ggrid(DIM / 128, N_NODES / 128);   // (4, 64)
    gemm_mma_kernel<<<ggrid, 512, GSMEM>>>(prev, bq, q);                    // 3 (profiled)

    attn_kernel<<<N_NODES / 8, 256>>>(enc, out);                            // 4
}

// round 13
// speedup vs baseline: 2.1391x; 1.0777x over previous
#include <cuda_runtime.h>
#include <cuda_bf16.h>
#include <cstdint>
#include <cstddef>

#define DIM      512
#define N_NODES  8192
#define N_EDGES  131072   // 2048 paths * 64
#define CAP      128      // per-node edge-bucket capacity (λ≈8, 16x headroom)

// GEMM smem geometry
#define SSTRIDE  40                    // padded bf16 row stride (80 B)
#define TILE_B   (128 * SSTRIDE * 2)   // 10240 B per tile
#define BUF_B    (4 * TILE_B)          // Ah, Al, Bh, Bl = 40960 B
#define GSMEM    (2 * BUF_B)           // double buffered = 81920 B

// ---------------- scratch (device globals; no runtime allocation) ----------
__device__ float         g_q[N_NODES * DIM];      // projected queries, fp32
__device__ __nv_bfloat16 g_BhiT[DIM * DIM];       // Wq^T split hi [n][k]
__device__ __nv_bfloat16 g_BloT[DIM * DIM];       // Wq^T split lo
__device__ int           g_cnt[N_NODES];          // per-node live-edge counts
__device__ int           g_elist[N_NODES * CAP];  // per-node edge buckets

struct Cfg { int idx_is_1; int mask_byte; };
__device__ Cfg g_cfg;

// ---------------- helpers ---------------------------------------------------
__device__ __forceinline__ uint32_t smem_u32(const void* p) {
    uint32_t a;
    asm("{ .reg .u64 t; cvta.to.shared.u64 t, %1; cvt.u32.u64 %0, t; }" : "=r"(a) : "l"(p));
    return a;
}
__device__ __forceinline__ void ldm_x4(uint32_t& r0, uint32_t& r1, uint32_t& r2,
                                       uint32_t& r3, uint32_t addr) {
    asm volatile("ldmatrix.sync.aligned.m8n8.x4.shared.b16 {%0,%1,%2,%3}, [%4];"
                 : "=r"(r0), "=r"(r1), "=r"(r2), "=r"(r3) : "r"(addr));
}
__device__ __forceinline__ void mma_16816(float* c, const uint32_t* a, const uint32_t* b) {
    asm volatile(
        "mma.sync.aligned.m16n8k16.row.col.f32.bf16.bf16.f32 "
        "{%0,%1,%2,%3}, {%4,%5,%6,%7}, {%8,%9}, {%0,%1,%2,%3};"
        : "+f"(c[0]), "+f"(c[1]), "+f"(c[2]), "+f"(c[3])
        : "r"(a[0]), "r"(a[1]), "r"(a[2]), "r"(a[3]), "r"(b[0]), "r"(b[1]));
}
__device__ __forceinline__ float4 ldcs4(const float* p) {
    float4 v;
    asm volatile("ld.global.cs.v4.f32 {%0,%1,%2,%3}, [%4];"
                 : "=f"(v.x), "=f"(v.y), "=f"(v.z), "=f"(v.w) : "l"(p));
    return v;
}

// ---------------- K0: detect idx/mask binding + zero counts ----------------
__global__ __launch_bounds__(256) void detect_kernel(
    const unsigned* __restrict__ c0, const unsigned* __restrict__ c1)
{
    #pragma unroll
    for (int i = 0; i < 32; i++) g_cnt[threadIdx.x + i * 256] = 0;

    __shared__ unsigned sm[2], so[2];
    if (threadIdx.x < 2) { sm[threadIdx.x] = 0u; so[threadIdx.x] = 0u; }
    __syncthreads();
    unsigned m0 = 0, m1 = 0, o0 = 0, o1 = 0;
    for (int i = threadIdx.x; i < 32768; i += 256) {
        unsigned a = c0[i], b = c1[i];
        m0 = max(m0, a); m1 = max(m1, b);
        o0 |= a & 0xFEFEFEFEu; o1 |= b & 0xFEFEFEFEu;
    }
    atomicMax(&sm[0], m0); atomicMax(&sm[1], m1);
    atomicOr (&so[0], o0); atomicOr (&so[1], o1);
    __syncthreads();
    if (threadIdx.x == 0) {
        unsigned M0 = sm[0], M1 = sm[1];
        int idx_is_1;
        if      (M0 <= 1u)                   idx_is_1 = 1;
        else if (M1 <= 1u)                   idx_is_1 = 0;
        else if (M0 < 8192u && M1 >= 8192u)  idx_is_1 = 0;
        else if (M1 < 8192u && M0 >= 8192u)  idx_is_1 = 1;
        else                                 idx_is_1 = 1;
        unsigned Mm = idx_is_1 ? M0 : M1;
        unsigned Om = idx_is_1 ? so[0] : so[1];
        g_cfg.idx_is_1  = idx_is_1;
        g_cfg.mask_byte = (Mm > 1u && Om == 0u) ? 1 : 0;
    }
}
__device__ __forceinline__ bool edge_live(const void* mask, int e, int mask_byte) {
    return mask_byte ? (((const unsigned char*)mask)[e] != 0)
                     : (((const unsigned*)mask)[e] != 0u);
}

// ---------------- K1: build per-node edge buckets (single pass) ------------
__global__ __launch_bounds__(256) void build_kernel(
    const void* __restrict__ c0, const void* __restrict__ c1)
{
    const Cfg cfg = g_cfg;
    const int*  idx  = cfg.idx_is_1 ? (const int*)c1 : (const int*)c0;
    const void* mask = cfg.idx_is_1 ? c0 : c1;
    int e = blockIdx.x * 256 + threadIdx.x;
    if (edge_live(mask, e, cfg.mask_byte)) {
        int node = idx[e];
        int pos  = atomicAdd(&g_cnt[node], 1);
        if (pos < CAP) g_elist[node * CAP + pos] = e;
    }
}

// ---------------- K2: transpose+split Wq -> [n][k] bf16 hi/lo --------------
__global__ __launch_bounds__(256) void conv_wq_kernel(const float* __restrict__ Wq) {
    __shared__ float t[32][33];
    int n0 = blockIdx.x * 32, k0 = blockIdx.y * 32;
    #pragma unroll
    for (int i = 0; i < 4; i++) {
        int lin = threadIdx.x + i * 256;
        int r = lin >> 5, c = lin & 31;
        t[r][c] = Wq[(size_t)(k0 + r) * DIM + n0 + c];
    }
    __syncthreads();
    #pragma unroll
    for (int i = 0; i < 4; i++) {
        int lin = threadIdx.x + i * 256;
        int r = lin >> 5, c = lin & 31;
        float v = t[c][r];
        __nv_bfloat16 h = __float2bfloat16(v);
        __nv_bfloat16 l = __float2bfloat16(v - __bfloat162float(h));
        size_t o = (size_t)(n0 + r) * DIM + k0 + c;
        g_BhiT[o] = h; g_BloT[o] = l;
    }
}

// ---------------- K3: q = prev @ Wq + bq (mma.sync, 16 warps/CTA) ----------
// bm_base selects the M half (each launch covers 4096 rows = 32 bm tiles).
__global__ __launch_bounds__(512, 1) void gemm_mma_kernel(
    const float* __restrict__ Aprev,   // [8192, 512] fp32
    const float* __restrict__ bias, float* __restrict__ C, int bm_base)
{
    extern __shared__ char dsm[];

    const int tid = threadIdx.x, wid = tid >> 5, lane = tid & 31;
    const int wm = wid & 3, wn = wid >> 2;          // 4(M) x 4(N)
    const int bm = blockIdx.y + bm_base, bn = blockIdx.x;

    const float* Asrc = Aprev + (size_t)bm * 128 * DIM;
    const __nv_bfloat16* Bh = g_BhiT + (size_t)bn * 128 * DIM;
    const __nv_bfloat16* Bl = g_BloT + (size_t)bn * 128 * DIM;

    float acc[2][4][4];
    #pragma unroll
    for (int i = 0; i < 2; i++)
        #pragma unroll
        for (int j = 0; j < 4; j++)
            #pragma unroll
            for (int k = 0; k < 4; k++) acc[i][j][k] = 0.f;

    const uint32_t a_row = lane & 15, a_c8 = (lane >> 4) << 3;
    const uint32_t b_n   = (lane & 7) + ((lane >> 4) << 3);
    const uint32_t b_k8  = ((lane >> 3) & 1) << 3;
    const uint32_t sbase = smem_u32(dsm);
    const uint32_t offA0 = 0 * TILE_B + (wm * 32 + a_row) * (SSTRIDE * 2) + a_c8 * 2;
    const uint32_t offA1 = 1 * TILE_B + (wm * 32 + a_row) * (SSTRIDE * 2) + a_c8 * 2;
    const uint32_t offB0 = 2 * TILE_B + (wn * 32 + b_n) * (SSTRIDE * 2) + b_k8 * 2;
    const uint32_t offB1 = 3 * TILE_B + (wn * 32 + b_n) * (SSTRIDE * 2) + b_k8 * 2;

    int ar[2], ac[2];
    #pragma unroll
    for (int i = 0; i < 2; i++) {
        int l = tid + i * 512;
        ar[i] = l >> 3; ac[i] = (l & 7) * 4;
    }
    const int br = tid >> 2, bc = (tid & 3) * 8;

    float4 pa[2];
    uint4  pb[2];
    #pragma unroll
    for (int i = 0; i < 2; i++)
        pa[i] = *(const float4*)(Asrc + (size_t)ar[i] * DIM + ac[i]);
    pb[0] = *(const uint4*)(Bh + (size_t)br * DIM + bc);
    pb[1] = *(const uint4*)(Bl + (size_t)br * DIM + bc);

    for (int ch = 0; ch < 16; ch++) {
        char* buf = dsm + (ch & 1) * BUF_B;
        #pragma unroll
        for (int i = 0; i < 2; i++) {
            float4 v = pa[i];
            __nv_bfloat16 h0 = __float2bfloat16(v.x), h1 = __float2bfloat16(v.y);
            __nv_bfloat16 h2 = __float2bfloat16(v.z), h3 = __float2bfloat16(v.w);
            __nv_bfloat16 l0 = __float2bfloat16(v.x - __bfloat162float(h0));
            __nv_bfloat16 l1 = __float2bfloat16(v.y - __bfloat162float(h1));
            __nv_bfloat16 l2 = __float2bfloat16(v.z - __bfloat162float(h2));
            __nv_bfloat16 l3 = __float2bfloat16(v.w - __bfloat162float(h3));
            uint32_t byo = ar[i] * (SSTRIDE * 2) + ac[i] * 2;
            *(__nv_bfloat162*)(buf + 0 * TILE_B + byo)     = __nv_bfloat162(h0, h1);
            *(__nv_bfloat162*)(buf + 0 * TILE_B + byo + 4) = __nv_bfloat162(h2, h3);
            *(__nv_bfloat162*)(buf + 1 * TILE_B + byo)     = __nv_bfloat162(l0, l1);
            *(__nv_bfloat162*)(buf + 1 * TILE_B + byo + 4) = __nv_bfloat162(l2, l3);
        }
        *(uint4*)(buf + 2 * TILE_B + br * (SSTRIDE * 2) + bc * 2) = pb[0];
        *(uint4*)(buf + 3 * TILE_B + br * (SSTRIDE * 2) + bc * 2) = pb[1];
        __syncthreads();

        if (ch < 15) {
            const int kb = (ch + 1) * 32;
            #pragma unroll
            for (int i = 0; i < 2; i++)
                pa[i] = *(const float4*)(Asrc + (size_t)ar[i] * DIM + kb + ac[i]);
            pb[0] = *(const uint4*)(Bh + (size_t)br * DIM + kb + bc);
            pb[1] = *(const uint4*)(Bl + (size_t)br * DIM + kb + bc);
        }

        const uint32_t bb = sbase + (ch & 1) * BUF_B;
        #pragma unroll
        for (int ks = 0; ks < 2; ks++) {
            const uint32_t ko = ks * 16 * 2;
            uint32_t ah[2][4], al[2][4], bh[4][2], bl[4][2];
            #pragma unroll
            for (int mi = 0; mi < 2; mi++) {
                uint32_t off = mi * 16 * SSTRIDE * 2 + ko;
                ldm_x4(ah[mi][0], ah[mi][1], ah[mi][2], ah[mi][3], bb + offA0 + off);
                ldm_x4(al[mi][0], al[mi][1], al[mi][2], al[mi][3], bb + offA1 + off);
            }
            #pragma unroll
            for (int nh = 0; nh < 2; nh++) {
                uint32_t off = nh * 16 * SSTRIDE * 2 + ko;
                ldm_x4(bh[nh*2][0], bh[nh*2][1], bh[nh*2+1][0], bh[nh*2+1][1], bb + offB0 + off);
                ldm_x4(bl[nh*2][0], bl[nh*2][1], bl[nh*2+1][0], bl[nh*2+1][1], bb + offB1 + off);
            }
            #pragma unroll
            for (int mi = 0; mi < 2; mi++)
                #pragma unroll
                for (int ni = 0; ni < 4; ni++)
                    mma_16816(acc[mi][ni], ah[mi], bh[ni]);
            #pragma unroll
            for (int mi = 0; mi < 2; mi++)
                #pragma unroll
                for (int ni = 0; ni < 4; ni++)
                    mma_16816(acc[mi][ni], ah[mi], bl[ni]);
            #pragma unroll
            for (int mi = 0; mi < 2; mi++)
                #pragma unroll
                for (int ni = 0; ni < 4; ni++)
                    mma_16816(acc[mi][ni], al[mi], bh[ni]);
        }
    }

    const int qr = lane >> 2, qc = (lane & 3) * 2;
    #pragma unroll
    for (int ni = 0; ni < 4; ni++) {
        int col = bn * 128 + wn * 32 + ni * 8 + qc;
        float2 b = *(const float2*)(bias + col);
        #pragma unroll
        for (int mi = 0; mi < 2; mi++) {
            int row = bm * 128 + wm * 32 + mi * 16 + qr;
            float2 v0 = make_float2(acc[mi][ni][0] + b.x, acc[mi][ni][1] + b.y);
            float2 v1 = make_float2(acc[mi][ni][2] + b.x, acc[mi][ni][3] + b.y);
            *(float2*)(C + (size_t)row * DIM + col)       = v0;
            *(float2*)(C + (size_t)(row + 8) * DIM + col) = v1;
        }
    }
}

// ---------------- K4: fused node-major online-softmax attention ------------
__global__ __launch_bounds__(256) void attn_kernel(
    const float* __restrict__ vals, float* __restrict__ out, int node_base)
{
    int node = node_base + ((blockIdx.x * 256 + threadIdx.x) >> 5);
    int lane = threadIdx.x & 31;

    int cnt = min(g_cnt[node], CAP);
    const int* el = g_elist + node * CAP;

    const float* qp = g_q + (size_t)node * DIM;
    float4 q[4];
    #pragma unroll
    for (int j = 0; j < 4; j++) q[j] = *(const float4*)(qp + lane * 4 + j * 128);

    float m = -1e30f, d = 0.f;
    float4 acc[4];
    #pragma unroll
    for (int j = 0; j < 4; j++) acc[j] = make_float4(0.f, 0.f, 0.f, 0.f);

    for (int p = 0; p < cnt; p += 2) {
        const bool has2 = (p + 1 < cnt);
        const float* va = vals + (size_t)el[p] * DIM;
        const float* vb = vals + (size_t)el[has2 ? p + 1 : p] * DIM;

        float4 a[4], b[4];
        #pragma unroll
        for (int j = 0; j < 4; j++) {
            a[j] = ldcs4(va + lane * 4 + j * 128);
            b[j] = ldcs4(vb + lane * 4 + j * 128);
        }

        float sa = 0.f, sb = 0.f;
        #pragma unroll
        for (int j = 0; j < 4; j++) {
            sa += a[j].x * q[j].x + a[j].y * q[j].y + a[j].z * q[j].z + a[j].w * q[j].w;
            sb += b[j].x * q[j].x + b[j].y * q[j].y + b[j].z * q[j].z + b[j].w * q[j].w;
        }
        #pragma unroll
        for (int o = 16; o; o >>= 1) {
            sa += __shfl_xor_sync(0xFFFFFFFFu, sa, o);
            sb += __shfl_xor_sync(0xFFFFFFFFu, sb, o);
        }
        if (!has2) sb = -1e30f;

        float mx = fmaxf(m, fmaxf(sa, sb));
        float r  = expf(m - mx);
        d *= r;
        float wa = expf(sa - mx), wb = expf(sb - mx);
        d += wa + wb;
        #pragma unroll
        for (int j = 0; j < 4; j++) {
            acc[j].x = acc[j].x * r + wa * a[j].x + wb * b[j].x;
            acc[j].y = acc[j].y * r + wa * a[j].y + wb * b[j].y;
            acc[j].z = acc[j].z * r + wa * a[j].z + wb * b[j].z;
            acc[j].w = acc[j].w * r + wa * a[j].w + wb * b[j].w;
        }
        m = mx;
    }

    float inv = 1.0f / fmaxf(d, 1e-12f);
    float* op = out + (size_t)node * DIM;
    #pragma unroll
    for (int j = 0; j < 4; j++) {
        float4 o = make_float4(acc[j].x * inv, acc[j].y * inv,
                               acc[j].z * inv, acc[j].w * inv);
        *(float4*)(op + lane * 4 + j * 128) = o;
    }
}

// ---------------- launch (fork-join: side stream for build + attn) ---------
extern "C" void kernel_launch(void* const* d_in, const int* in_sizes, int n_in,
                              void* d_out, int out_size)
{
    const float* enc  = nullptr;
    const void*  c0   = nullptr;
    const void*  c1   = nullptr;
    const float* prev = nullptr;
    const float* Wq   = nullptr;
    const float* bq   = nullptr;
    int n131072 = 0;

    for (int i = 0; i < n_in; i++) {
        switch (in_sizes[i]) {
            case 67108864: enc  = (const float*)d_in[i]; break;
            case 4194304:  prev = (const float*)d_in[i]; break;
            case 262144:   Wq   = (const float*)d_in[i]; break;
            case 512:      bq   = (const float*)d_in[i]; break;
            case 131072:
                if (n131072++ == 0) c0 = d_in[i];
                else                c1 = d_in[i];
                break;
            default: break;
        }
    }

    float* out = (float*)d_out;
    float* q;
    cudaGetSymbolAddress((void**)&q, g_q);

    static cudaStream_t s2 = nullptr;
    static cudaEvent_t  evFork, evG0, evG1, evJoin;
    if (!s2) {
        cudaFuncSetAttribute(gemm_mma_kernel,
                             cudaFuncAttributeMaxDynamicSharedMemorySize, GSMEM);
        cudaStreamCreateWithFlags(&s2, cudaStreamNonBlocking);
        cudaEventCreateWithFlags(&evFork, cudaEventDisableTiming);
        cudaEventCreateWithFlags(&evG0,   cudaEventDisableTiming);
        cudaEventCreateWithFlags(&evG1,   cudaEventDisableTiming);
        cudaEventCreateWithFlags(&evJoin, cudaEventDisableTiming);
    }

    // fork: side stream handles edge bucketing (independent of gemm path)
    cudaEventRecord(evFork, 0);
    cudaStreamWaitEvent(s2, evFork, 0);
    detect_kernel<<<1, 256, 0, s2>>>((const unsigned*)c0, (const unsigned*)c1);
    build_kernel<<<N_EDGES / 256, 256, 0, s2>>>(c0, c1);

    // main stream: weight conversion, then the two gemm halves
    conv_wq_kernel<<<dim3(16, 16), 256>>>(Wq);
    dim3 hgrid(DIM / 128, 32);                       // 128 CTAs = ~1 wave
    gemm_mma_kernel<<<hgrid, 512, GSMEM>>>(prev, bq, q, 0);
    cudaEventRecord(evG0, 0);
    gemm_mma_kernel<<<hgrid, 512, GSMEM>>>(prev, bq, q, 32);
    cudaEventRecord(evG1, 0);

    // side stream: attn half 0 overlaps gemm half 1
    cudaStreamWaitEvent(s2, evG0, 0);
    attn_kernel<<<512, 256, 0, s2>>>(enc, out, 0);
    cudaStreamWaitEvent(s2, evG1, 0);
    attn_kernel<<<512, 256, 0, s2>>>(enc, out, 4096);

    // join back into the captured origin stream
    cudaEventRecord(evJoin, s2);
    cudaStreamWaitEvent(0, evJoin, 0);
}

// round 14
// speedup vs baseline: 2.1407x; 1.0007x over previous
#include <cuda_runtime.h>
#include <cuda_bf16.h>
#include <cstdint>
#include <cstddef>

#define DIM      512
#define N_NODES  8192
#define N_EDGES  131072   // 2048 paths * 64
#define CAP      128      // per-node edge-bucket capacity (λ≈8, 16x headroom)

// GEMM smem geometry
#define SSTRIDE  40                    // padded bf16 row stride (80 B)
#define TILE_B   (128 * SSTRIDE * 2)   // 10240 B per tile
#define BUF_B    (4 * TILE_B)          // Ah, Al, Bh, Bl = 40960 B
#define GSMEM    (2 * BUF_B)           // double buffered = 81920 B

// ---------------- scratch (device globals; no runtime allocation) ----------
__device__ float         g_q[N_NODES * DIM];      // projected queries, fp32
__device__ __nv_bfloat16 g_BhiT[DIM * DIM];       // Wq^T split hi [n][k]
__device__ __nv_bfloat16 g_BloT[DIM * DIM];       // Wq^T split lo
__device__ int           g_cnt[N_NODES];          // per-node live-edge counts
__device__ int           g_elist[N_NODES * CAP];  // per-node edge buckets

struct Cfg { int idx_is_1; int mask_byte; };
__device__ Cfg g_cfg;

// ---------------- helpers ---------------------------------------------------
__device__ __forceinline__ uint32_t smem_u32(const void* p) {
    uint32_t a;
    asm("{ .reg .u64 t; cvta.to.shared.u64 t, %1; cvt.u32.u64 %0, t; }" : "=r"(a) : "l"(p));
    return a;
}
__device__ __forceinline__ void ldm_x4(uint32_t& r0, uint32_t& r1, uint32_t& r2,
                                       uint32_t& r3, uint32_t addr) {
    asm volatile("ldmatrix.sync.aligned.m8n8.x4.shared.b16 {%0,%1,%2,%3}, [%4];"
                 : "=r"(r0), "=r"(r1), "=r"(r2), "=r"(r3) : "r"(addr));
}
__device__ __forceinline__ void mma_16816(float* c, const uint32_t* a, const uint32_t* b) {
    asm volatile(
        "mma.sync.aligned.m16n8k16.row.col.f32.bf16.bf16.f32 "
        "{%0,%1,%2,%3}, {%4,%5,%6,%7}, {%8,%9}, {%0,%1,%2,%3};"
        : "+f"(c[0]), "+f"(c[1]), "+f"(c[2]), "+f"(c[3])
        : "r"(a[0]), "r"(a[1]), "r"(a[2]), "r"(a[3]), "r"(b[0]), "r"(b[1]));
}
__device__ __forceinline__ float4 ldcs4(const float* p) {
    float4 v;
    asm volatile("ld.global.cs.v4.f32 {%0,%1,%2,%3}, [%4];"
                 : "=f"(v.x), "=f"(v.y), "=f"(v.z), "=f"(v.w) : "l"(p));
    return v;
}

// ---------------- K0: detect idx/mask binding + zero counts ----------------
__global__ __launch_bounds__(256) void detect_kernel(
    const unsigned* __restrict__ c0, const unsigned* __restrict__ c1)
{
    #pragma unroll
    for (int i = 0; i < 32; i++) g_cnt[threadIdx.x + i * 256] = 0;

    __shared__ unsigned sm[2], so[2];
    if (threadIdx.x < 2) { sm[threadIdx.x] = 0u; so[threadIdx.x] = 0u; }
    __syncthreads();
    unsigned m0 = 0, m1 = 0, o0 = 0, o1 = 0;
    for (int i = threadIdx.x; i < 32768; i += 256) {
        unsigned a = c0[i], b = c1[i];
        m0 = max(m0, a); m1 = max(m1, b);
        o0 |= a & 0xFEFEFEFEu; o1 |= b & 0xFEFEFEFEu;
    }
    atomicMax(&sm[0], m0); atomicMax(&sm[1], m1);
    atomicOr (&so[0], o0); atomicOr (&so[1], o1);
    __syncthreads();
    if (threadIdx.x == 0) {
        unsigned M0 = sm[0], M1 = sm[1];
        int idx_is_1;
        if      (M0 <= 1u)                   idx_is_1 = 1;
        else if (M1 <= 1u)                   idx_is_1 = 0;
        else if (M0 < 8192u && M1 >= 8192u)  idx_is_1 = 0;
        else if (M1 < 8192u && M0 >= 8192u)  idx_is_1 = 1;
        else                                 idx_is_1 = 1;
        unsigned Mm = idx_is_1 ? M0 : M1;
        unsigned Om = idx_is_1 ? so[0] : so[1];
        g_cfg.idx_is_1  = idx_is_1;
        g_cfg.mask_byte = (Mm > 1u && Om == 0u) ? 1 : 0;
    }
}
__device__ __forceinline__ bool edge_live(const void* mask, int e, int mask_byte) {
    return mask_byte ? (((const unsigned char*)mask)[e] != 0)
                     : (((const unsigned*)mask)[e] != 0u);
}

// ---------------- K1: build per-node edge buckets (single pass) ------------
__global__ __launch_bounds__(256) void build_kernel(
    const void* __restrict__ c0, const void* __restrict__ c1)
{
    const Cfg cfg = g_cfg;
    const int*  idx  = cfg.idx_is_1 ? (const int*)c1 : (const int*)c0;
    const void* mask = cfg.idx_is_1 ? c0 : c1;
    int e = blockIdx.x * 256 + threadIdx.x;
    if (edge_live(mask, e, cfg.mask_byte)) {
        int node = idx[e];
        int pos  = atomicAdd(&g_cnt[node], 1);
        if (pos < CAP) g_elist[node * CAP + pos] = e;
    }
}

// ---------------- K2: transpose+split Wq -> [n][k] bf16 hi/lo --------------
__global__ __launch_bounds__(256) void conv_wq_kernel(const float* __restrict__ Wq) {
    __shared__ float t[32][33];
    int n0 = blockIdx.x * 32, k0 = blockIdx.y * 32;
    #pragma unroll
    for (int i = 0; i < 4; i++) {
        int lin = threadIdx.x + i * 256;
        int r = lin >> 5, c = lin & 31;
        t[r][c] = Wq[(size_t)(k0 + r) * DIM + n0 + c];
    }
    __syncthreads();
    #pragma unroll
    for (int i = 0; i < 4; i++) {
        int lin = threadIdx.x + i * 256;
        int r = lin >> 5, c = lin & 31;
        float v = t[c][r];
        __nv_bfloat16 h = __float2bfloat16(v);
        __nv_bfloat16 l = __float2bfloat16(v - __bfloat162float(h));
        size_t o = (size_t)(n0 + r) * DIM + k0 + c;
        g_BhiT[o] = h; g_BloT[o] = l;
    }
}

// ---------------- K3: q = prev @ Wq + bq (mma.sync, 16 warps/CTA) ----------
__global__ __launch_bounds__(512, 1) void gemm_mma_kernel(
    const float* __restrict__ Aprev,   // [8192, 512] fp32
    const float* __restrict__ bias, float* __restrict__ C, int bm_base)
{
    extern __shared__ char dsm[];

    const int tid = threadIdx.x, wid = tid >> 5, lane = tid & 31;
    const int wm = wid & 3, wn = wid >> 2;          // 4(M) x 4(N)
    const int bm = blockIdx.y + bm_base, bn = blockIdx.x;

    const float* Asrc = Aprev + (size_t)bm * 128 * DIM;
    const __nv_bfloat16* Bh = g_BhiT + (size_t)bn * 128 * DIM;
    const __nv_bfloat16* Bl = g_BloT + (size_t)bn * 128 * DIM;

    float acc[2][4][4];
    #pragma unroll
    for (int i = 0; i < 2; i++)
        #pragma unroll
        for (int j = 0; j < 4; j++)
            #pragma unroll
            for (int k = 0; k < 4; k++) acc[i][j][k] = 0.f;

    const uint32_t a_row = lane & 15, a_c8 = (lane >> 4) << 3;
    const uint32_t b_n   = (lane & 7) + ((lane >> 4) << 3);
    const uint32_t b_k8  = ((lane >> 3) & 1) << 3;
    const uint32_t sbase = smem_u32(dsm);
    const uint32_t offA0 = 0 * TILE_B + (wm * 32 + a_row) * (SSTRIDE * 2) + a_c8 * 2;
    const uint32_t offA1 = 1 * TILE_B + (wm * 32 + a_row) * (SSTRIDE * 2) + a_c8 * 2;
    const uint32_t offB0 = 2 * TILE_B + (wn * 32 + b_n) * (SSTRIDE * 2) + b_k8 * 2;
    const uint32_t offB1 = 3 * TILE_B + (wn * 32 + b_n) * (SSTRIDE * 2) + b_k8 * 2;

    int ar[2], ac[2];
    #pragma unroll
    for (int i = 0; i < 2; i++) {
        int l = tid + i * 512;
        ar[i] = l >> 3; ac[i] = (l & 7) * 4;
    }
    const int br = tid >> 2, bc = (tid & 3) * 8;

    float4 pa[2];
    uint4  pb[2];
    #pragma unroll
    for (int i = 0; i < 2; i++)
        pa[i] = *(const float4*)(Asrc + (size_t)ar[i] * DIM + ac[i]);
    pb[0] = *(const uint4*)(Bh + (size_t)br * DIM + bc);
    pb[1] = *(const uint4*)(Bl + (size_t)br * DIM + bc);

    for (int ch = 0; ch < 16; ch++) {
        char* buf = dsm + (ch & 1) * BUF_B;
        #pragma unroll
        for (int i = 0; i < 2; i++) {
            float4 v = pa[i];
            __nv_bfloat16 h0 = __float2bfloat16(v.x), h1 = __float2bfloat16(v.y);
            __nv_bfloat16 h2 = __float2bfloat16(v.z), h3 = __float2bfloat16(v.w);
            __nv_bfloat16 l0 = __float2bfloat16(v.x - __bfloat162float(h0));
            __nv_bfloat16 l1 = __float2bfloat16(v.y - __bfloat162float(h1));
            __nv_bfloat16 l2 = __float2bfloat16(v.z - __bfloat162float(h2));
            __nv_bfloat16 l3 = __float2bfloat16(v.w - __bfloat162float(h3));
            uint32_t byo = ar[i] * (SSTRIDE * 2) + ac[i] * 2;
            *(__nv_bfloat162*)(buf + 0 * TILE_B + byo)     = __nv_bfloat162(h0, h1);
            *(__nv_bfloat162*)(buf + 0 * TILE_B + byo + 4) = __nv_bfloat162(h2, h3);
            *(__nv_bfloat162*)(buf + 1 * TILE_B + byo)     = __nv_bfloat162(l0, l1);
            *(__nv_bfloat162*)(buf + 1 * TILE_B + byo + 4) = __nv_bfloat162(l2, l3);
        }
        *(uint4*)(buf + 2 * TILE_B + br * (SSTRIDE * 2) + bc * 2) = pb[0];
        *(uint4*)(buf + 3 * TILE_B + br * (SSTRIDE * 2) + bc * 2) = pb[1];
        __syncthreads();

        if (ch < 15) {
            const int kb = (ch + 1) * 32;
            #pragma unroll
            for (int i = 0; i < 2; i++)
                pa[i] = *(const float4*)(Asrc + (size_t)ar[i] * DIM + kb + ac[i]);
            pb[0] = *(const uint4*)(Bh + (size_t)br * DIM + kb + bc);
            pb[1] = *(const uint4*)(Bl + (size_t)br * DIM + kb + bc);
        }

        const uint32_t bb = sbase + (ch & 1) * BUF_B;
        #pragma unroll
        for (int ks = 0; ks < 2; ks++) {
            const uint32_t ko = ks * 16 * 2;
            uint32_t ah[2][4], al[2][4], bh[4][2], bl[4][2];
            #pragma unroll
            for (int mi = 0; mi < 2; mi++) {
                uint32_t off = mi * 16 * SSTRIDE * 2 + ko;
                ldm_x4(ah[mi][0], ah[mi][1], ah[mi][2], ah[mi][3], bb + offA0 + off);
                ldm_x4(al[mi][0], al[mi][1], al[mi][2], al[mi][3], bb + offA1 + off);
            }
            #pragma unroll
            for (int nh = 0; nh < 2; nh++) {
                uint32_t off = nh * 16 * SSTRIDE * 2 + ko;
                ldm_x4(bh[nh*2][0], bh[nh*2][1], bh[nh*2+1][0], bh[nh*2+1][1], bb + offB0 + off);
                ldm_x4(bl[nh*2][0], bl[nh*2][1], bl[nh*2+1][0], bl[nh*2+1][1], bb + offB1 + off);
            }
            #pragma unroll
            for (int mi = 0; mi < 2; mi++)
                #pragma unroll
                for (int ni = 0; ni < 4; ni++)
                    mma_16816(acc[mi][ni], ah[mi], bh[ni]);
            #pragma unroll
            for (int mi = 0; mi < 2; mi++)
                #pragma unroll
                for (int ni = 0; ni < 4; ni++)
                    mma_16816(acc[mi][ni], ah[mi], bl[ni]);
            #pragma unroll
            for (int mi = 0; mi < 2; mi++)
                #pragma unroll
                for (int ni = 0; ni < 4; ni++)
                    mma_16816(acc[mi][ni], al[mi], bh[ni]);
        }
    }

    const int qr = lane >> 2, qc = (lane & 3) * 2;
    #pragma unroll
    for (int ni = 0; ni < 4; ni++) {
        int col = bn * 128 + wn * 32 + ni * 8 + qc;
        float2 b = *(const float2*)(bias + col);
        #pragma unroll
        for (int mi = 0; mi < 2; mi++) {
            int row = bm * 128 + wm * 32 + mi * 16 + qr;
            float2 v0 = make_float2(acc[mi][ni][0] + b.x, acc[mi][ni][1] + b.y);
            float2 v1 = make_float2(acc[mi][ni][2] + b.x, acc[mi][ni][3] + b.y);
            *(float2*)(C + (size_t)row * DIM + col)       = v0;
            *(float2*)(C + (size_t)(row + 8) * DIM + col) = v1;
        }
    }
}

// ---------------- K4a: attn-lite (co-resident with gemm: 128thr, <=64 regs)
// single-edge loop; runs hidden inside gemm's register hole.
__global__ __launch_bounds__(128, 8) void attn_lite_kernel(
    const float* __restrict__ vals, float* __restrict__ out, int node_base)
{
    int node = node_base + ((blockIdx.x * 128 + threadIdx.x) >> 5);
    int lane = threadIdx.x & 31;

    int cnt = min(g_cnt[node], CAP);
    const int* el = g_elist + node * CAP;

    const float* qp = g_q + (size_t)node * DIM;
    float4 q[4];
    #pragma unroll
    for (int j = 0; j < 4; j++) q[j] = *(const float4*)(qp + lane * 4 + j * 128);

    float m = -1e30f, d = 0.f;
    float4 acc[4];
    #pragma unroll
    for (int j = 0; j < 4; j++) acc[j] = make_float4(0.f, 0.f, 0.f, 0.f);

    for (int p = 0; p < cnt; p++) {
        const float* v = vals + (size_t)el[p] * DIM;
        float4 a[4];
        #pragma unroll
        for (int j = 0; j < 4; j++) a[j] = ldcs4(v + lane * 4 + j * 128);

        float s = 0.f;
        #pragma unroll
        for (int j = 0; j < 4; j++)
            s += a[j].x * q[j].x + a[j].y * q[j].y + a[j].z * q[j].z + a[j].w * q[j].w;
        #pragma unroll
        for (int o = 16; o; o >>= 1) s += __shfl_xor_sync(0xFFFFFFFFu, s, o);

        float mx = fmaxf(m, s);
        float r  = expf(m - mx);
        float w  = expf(s - mx);
        d = d * r + w;
        #pragma unroll
        for (int j = 0; j < 4; j++) {
            acc[j].x = acc[j].x * r + w * a[j].x;
            acc[j].y = acc[j].y * r + w * a[j].y;
            acc[j].z = acc[j].z * r + w * a[j].z;
            acc[j].w = acc[j].w * r + w * a[j].w;
        }
        m = mx;
    }

    float inv = 1.0f / fmaxf(d, 1e-12f);
    float* op = out + (size_t)node * DIM;
    #pragma unroll
    for (int j = 0; j < 4; j++) {
        float4 o = make_float4(acc[j].x * inv, acc[j].y * inv,
                               acc[j].z * inv, acc[j].w * inv);
        *(float4*)(op + lane * 4 + j * 128) = o;
    }
}

// ---------------- K4b: attn paired (full-speed, runs alone) ----------------
__global__ __launch_bounds__(256) void attn_kernel(
    const float* __restrict__ vals, float* __restrict__ out, int node_base)
{
    int node = node_base + ((blockIdx.x * 256 + threadIdx.x) >> 5);
    int lane = threadIdx.x & 31;

    int cnt = min(g_cnt[node], CAP);
    const int* el = g_elist + node * CAP;

    const float* qp = g_q + (size_t)node * DIM;
    float4 q[4];
    #pragma unroll
    for (int j = 0; j < 4; j++) q[j] = *(const float4*)(qp + lane * 4 + j * 128);

    float m = -1e30f, d = 0.f;
    float4 acc[4];
    #pragma unroll
    for (int j = 0; j < 4; j++) acc[j] = make_float4(0.f, 0.f, 0.f, 0.f);

    for (int p = 0; p < cnt; p += 2) {
        const bool has2 = (p + 1 < cnt);
        const float* va = vals + (size_t)el[p] * DIM;
        const float* vb = vals + (size_t)el[has2 ? p + 1 : p] * DIM;

        float4 a[4], b[4];
        #pragma unroll
        for (int j = 0; j < 4; j++) {
            a[j] = ldcs4(va + lane * 4 + j * 128);
            b[j] = ldcs4(vb + lane * 4 + j * 128);
        }

        float sa = 0.f, sb = 0.f;
        #pragma unroll
        for (int j = 0; j < 4; j++) {
            sa += a[j].x * q[j].x + a[j].y * q[j].y + a[j].z * q[j].z + a[j].w * q[j].w;
            sb += b[j].x * q[j].x + b[j].y * q[j].y + b[j].z * q[j].z + b[j].w * q[j].w;
        }
        #pragma unroll
        for (int o = 16; o; o >>= 1) {
            sa += __shfl_xor_sync(0xFFFFFFFFu, sa, o);
            sb += __shfl_xor_sync(0xFFFFFFFFu, sb, o);
        }
        if (!has2) sb = -1e30f;

        float mx = fmaxf(m, fmaxf(sa, sb));
        float r  = expf(m - mx);
        d *= r;
        float wa = expf(sa - mx), wb = expf(sb - mx);
        d += wa + wb;
        #pragma unroll
        for (int j = 0; j < 4; j++) {
            acc[j].x = acc[j].x * r + wa * a[j].x + wb * b[j].x;
            acc[j].y = acc[j].y * r + wa * a[j].y + wb * b[j].y;
            acc[j].z = acc[j].z * r + wa * a[j].z + wb * b[j].z;
            acc[j].w = acc[j].w * r + wa * a[j].w + wb * b[j].w;
        }
        m = mx;
    }

    float inv = 1.0f / fmaxf(d, 1e-12f);
    float* op = out + (size_t)node * DIM;
    #pragma unroll
    for (int j = 0; j < 4; j++) {
        float4 o = make_float4(acc[j].x * inv, acc[j].y * inv,
                               acc[j].z * inv, acc[j].w * inv);
        *(float4*)(op + lane * 4 + j * 128) = o;
    }
}

// ---------------- launch (fork-join with co-resident attn-lite) ------------
extern "C" void kernel_launch(void* const* d_in, const int* in_sizes, int n_in,
                              void* d_out, int out_size)
{
    const float* enc  = nullptr;
    const void*  c0   = nullptr;
    const void*  c1   = nullptr;
    const float* prev = nullptr;
    const float* Wq   = nullptr;
    const float* bq   = nullptr;
    int n131072 = 0;

    for (int i = 0; i < n_in; i++) {
        switch (in_sizes[i]) {
            case 67108864: enc  = (const float*)d_in[i]; break;
            case 4194304:  prev = (const float*)d_in[i]; break;
            case 262144:   Wq   = (const float*)d_in[i]; break;
            case 512:      bq   = (const float*)d_in[i]; break;
            case 131072:
                if (n131072++ == 0) c0 = d_in[i];
                else                c1 = d_in[i];
                break;
            default: break;
        }
    }

    float* out = (float*)d_out;
    float* q;
    cudaGetSymbolAddress((void**)&q, g_q);

    static cudaStream_t s2 = nullptr;
    static cudaEvent_t  evFork, evG0, evG1, evJoin;
    if (!s2) {
        cudaFuncSetAttribute(gemm_mma_kernel,
                             cudaFuncAttributeMaxDynamicSharedMemorySize, GSMEM);
        cudaStreamCreateWithFlags(&s2, cudaStreamNonBlocking);
        cudaEventCreateWithFlags(&evFork, cudaEventDisableTiming);
        cudaEventCreateWithFlags(&evG0,   cudaEventDisableTiming);
        cudaEventCreateWithFlags(&evG1,   cudaEventDisableTiming);
        cudaEventCreateWithFlags(&evJoin, cudaEventDisableTiming);
    }

    // fork: side stream handles edge bucketing (independent of gemm path)
    cudaEventRecord(evFork, 0);
    cudaStreamWaitEvent(s2, evFork, 0);
    detect_kernel<<<1, 256, 0, s2>>>((const unsigned*)c0, (const unsigned*)c1);
    build_kernel<<<N_EDGES / 256, 256, 0, s2>>>(c0, c1);

    // main stream: weight conversion, then the two gemm halves
    conv_wq_kernel<<<dim3(16, 16), 256>>>(Wq);
    dim3 hgrid(DIM / 128, 32);                       // 128 CTAs = ~1 wave
    gemm_mma_kernel<<<hgrid, 512, GSMEM>>>(prev, bq, q, 0);
    cudaEventRecord(evG0, 0);
    gemm_mma_kernel<<<hgrid, 512, GSMEM>>>(prev, bq, q, 32);
    cudaEventRecord(evG1, 0);

    // side stream: lite attn half 0 co-resides with gemm half 1 (fits the
    // 9K-register hole gemm leaves per SM); paired attn half 1 runs alone.
    cudaStreamWaitEvent(s2, evG0, 0);
    attn_lite_kernel<<<1024, 128, 0, s2>>>(enc, out, 0);
    cudaStreamWaitEvent(s2, evG1, 0);
    attn_kernel<<<512, 256, 0, s2>>>(enc, out, 4096);

    // join back into the captured origin stream
    cudaEventRecord(evJoin, s2);
    cudaStreamWaitEvent(0, evJoin, 0);
}